// round 2
// baseline (speedup 1.0000x reference)
#include <cuda_runtime.h>
#include <math.h>

#define B_  2
#define N_  2048
#define QN_ 512
#define D_  1024
#define H_  16
#define HD_ 64
#define LN_ 256
#define LD_ 64

// ---------------- scratch (static device, no allocation) ----------------
__device__ float g_qkv  [B_*N_*3*D_];   // [B*N, 3*1024] = q|k|v, per-head cols h*64
__device__ float g_kv   [B_*N_*2*D_];   // [B*N, 2*1024] = k2|v2
__device__ float g_qqkv [B_*QN_*3*D_];  // [B*QN, 3*1024] = qq|qk|qv
__device__ float g_xattn[B_*N_*D_];     // [B*N, H*HD]
__device__ float g_qattn[B_*QN_*D_];    // [B*QN, QH*QHD]

// ---------------- generic tiled GEMM: C = A[MxK] @ B[KxN] (+bias) ----------------
__global__ __launch_bounds__(256) void gemm_kernel(
    const float* __restrict__ A, const float* __restrict__ Bm,
    const float* __restrict__ bias, float* __restrict__ C,
    int M, int N, int K)
{
    __shared__ float As[16][68];  // [k][m], padded pitch (272B, 16B-divisible)
    __shared__ float Bs[16][68];  // [k][n]

    const int t  = threadIdx.x;
    const int tx = t & 15;
    const int ty = t >> 4;
    const int bm = blockIdx.y * 64;
    const int bn = blockIdx.x * 64;

    const int arow = t >> 2;          // 0..63
    const int acol = (t & 3) << 2;    // 0,4,8,12  (16-deep tile: full coverage)
    const int brow = t >> 4;          // 0..15
    const int bcol = (t & 15) << 2;   // 0..60

    float acc[4][4];
#pragma unroll
    for (int i = 0; i < 4; i++)
#pragma unroll
        for (int j = 0; j < 4; j++) acc[i][j] = 0.f;

    for (int k0 = 0; k0 < K; k0 += 16) {
        float4 av = *(const float4*)&A[(size_t)(bm + arow) * K + k0 + acol];
        float4 bv = *(const float4*)&Bm[(size_t)(k0 + brow) * N + bn + bcol];
        As[acol + 0][arow] = av.x;
        As[acol + 1][arow] = av.y;
        As[acol + 2][arow] = av.z;
        As[acol + 3][arow] = av.w;
        *(float4*)&Bs[brow][bcol] = bv;
        __syncthreads();
#pragma unroll
        for (int kk = 0; kk < 16; kk++) {
            float4 a = *(const float4*)&As[kk][ty * 4];
            float4 b = *(const float4*)&Bs[kk][tx * 4];
            float aa[4] = {a.x, a.y, a.z, a.w};
            float bb[4] = {b.x, b.y, b.z, b.w};
#pragma unroll
            for (int i = 0; i < 4; i++)
#pragma unroll
                for (int j = 0; j < 4; j++)
                    acc[i][j] = fmaf(aa[i], bb[j], acc[i][j]);
        }
        __syncthreads();
    }

#pragma unroll
    for (int i = 0; i < 4; i++) {
        int r = bm + ty * 4 + i;
#pragma unroll
        for (int j = 0; j < 4; j++) {
            int c = bn + tx * 4 + j;
            float v = acc[i][j];
            if (bias) v += bias[c];
            C[(size_t)r * N + c] = v;
        }
    }
}

// ---------------- flash-attention segment (64-query tile x nkeys) ----------------
// Qs: [e][row] (transposed). KPs: K as [e][key] during S, reused as P [row][key].
// Vs: [key][d] natural.
// Tile loads: 256 threads, each loads row (t>>2), 16-col strip at (t&3)*16.
__device__ __forceinline__ void flash_segment(
    const float* __restrict__ Kg, const float* __restrict__ Vg,
    int kstride, int nkeys,
    float (*Qs)[64], float (*KPs)[64], float (*Vs)[64],
    float acc[4][4], float* m_i, float* l_i,
    int tx, int ty, int lrow, int lcol, float scale)
{
    for (int k0 = 0; k0 < nkeys; k0 += 64) {
        __syncthreads();  // prior P/V reads done; Qs (first iter) visible
        {
            const float* krow = &Kg[(size_t)(k0 + lrow) * kstride + lcol];
            const float* vrow = &Vg[(size_t)(k0 + lrow) * kstride + lcol];
#pragma unroll
            for (int c = 0; c < 16; c += 4) {
                float4 kv4 = *(const float4*)&krow[c];
                KPs[lcol + c + 0][lrow] = kv4.x;
                KPs[lcol + c + 1][lrow] = kv4.y;
                KPs[lcol + c + 2][lrow] = kv4.z;
                KPs[lcol + c + 3][lrow] = kv4.w;
                float4 vv = *(const float4*)&vrow[c];
                *(float4*)&Vs[lrow][lcol + c] = vv;
            }
        }
        __syncthreads();

        float s[4][4];
#pragma unroll
        for (int i = 0; i < 4; i++)
#pragma unroll
            for (int j = 0; j < 4; j++) s[i][j] = 0.f;

#pragma unroll 8
        for (int e = 0; e < 64; e++) {
            float4 a = *(const float4*)&Qs[e][ty * 4];
            float4 b = *(const float4*)&KPs[e][tx * 4];
            float aa[4] = {a.x, a.y, a.z, a.w};
            float bb[4] = {b.x, b.y, b.z, b.w};
#pragma unroll
            for (int i = 0; i < 4; i++)
#pragma unroll
                for (int j = 0; j < 4; j++)
                    s[i][j] = fmaf(aa[i], bb[j], s[i][j]);
        }
        __syncthreads();  // done reading KPs as K; safe to overwrite as P

        // online softmax (row stats reduced across the 16 tx lanes of each row)
#pragma unroll
        for (int i = 0; i < 4; i++) {
            float rm = -1e30f;
#pragma unroll
            for (int j = 0; j < 4; j++) {
                s[i][j] *= scale;
                rm = fmaxf(rm, s[i][j]);
            }
#pragma unroll
            for (int o = 8; o >= 1; o >>= 1)
                rm = fmaxf(rm, __shfl_xor_sync(0xffffffffu, rm, o));
            float mnew = fmaxf(m_i[i], rm);
            float alpha = __expf(m_i[i] - mnew);
            m_i[i] = mnew;
            float rs = 0.f;
#pragma unroll
            for (int j = 0; j < 4; j++) {
                s[i][j] = __expf(s[i][j] - mnew);
                rs += s[i][j];
            }
#pragma unroll
            for (int o = 8; o >= 1; o >>= 1)
                rs += __shfl_xor_sync(0xffffffffu, rs, o);
            l_i[i] = l_i[i] * alpha + rs;
#pragma unroll
            for (int j = 0; j < 4; j++) acc[i][j] *= alpha;
        }

        // store P [row][key], conflict-free float4 rows
#pragma unroll
        for (int i = 0; i < 4; i++) {
            float4 pv = make_float4(s[i][0], s[i][1], s[i][2], s[i][3]);
            *(float4*)&KPs[ty * 4 + i][tx * 4] = pv;
        }
        __syncthreads();

#pragma unroll 8
        for (int kk = 0; kk < 64; kk++) {
            float4 b = *(const float4*)&Vs[kk][tx * 4];
            float bb[4] = {b.x, b.y, b.z, b.w};
            float pa[4];
#pragma unroll
            for (int i = 0; i < 4; i++) pa[i] = KPs[ty * 4 + i][kk];
#pragma unroll
            for (int i = 0; i < 4; i++)
#pragma unroll
                for (int j = 0; j < 4; j++)
                    acc[i][j] = fmaf(pa[i], bb[j], acc[i][j]);
        }
    }
}

// load a 64x64 Q tile transposed into Qs[e][row]
__device__ __forceinline__ void load_q_tile(
    const float* __restrict__ Qg, int stride, int q0,
    float (*Qs)[64], int lrow, int lcol)
{
    const float* qrow = &Qg[(size_t)(q0 + lrow) * stride + lcol];
#pragma unroll
    for (int c = 0; c < 16; c += 4) {
        float4 qv = *(const float4*)&qrow[c];
        Qs[lcol + c + 0][lrow] = qv.x;
        Qs[lcol + c + 1][lrow] = qv.y;
        Qs[lcol + c + 2][lrow] = qv.z;
        Qs[lcol + c + 3][lrow] = qv.w;
    }
}

// ---------------- self attention over x ----------------
__global__ __launch_bounds__(256) void attn_self_kernel(
    const float* __restrict__ qkv, float* __restrict__ out)
{
    __shared__ float Qs[64][64], KPs[64][64], Vs[64][64];  // 48 KB
    const int bh = blockIdx.x;
    const int b = bh >> 4, h = bh & 15;
    const int q0 = blockIdx.y * 64;
    const int t = threadIdx.x;
    const int tx = t & 15, ty = t >> 4;
    const int lrow = t >> 2, lcol = (t & 3) << 4;

    const float* base = qkv + (size_t)b * N_ * 3072;
    const float* Qg = base + h * 64;
    const float* Kg = base + 1024 + h * 64;
    const float* Vg = base + 2048 + h * 64;

    load_q_tile(Qg, 3072, q0, Qs, lrow, lcol);

    float acc[4][4], m_i[4], l_i[4];
#pragma unroll
    for (int i = 0; i < 4; i++) {
        m_i[i] = -1e30f;
        l_i[i] = 0.f;
#pragma unroll
        for (int j = 0; j < 4; j++) acc[i][j] = 0.f;
    }

    flash_segment(Kg, Vg, 3072, N_, Qs, KPs, Vs, acc, m_i, l_i,
                  tx, ty, lrow, lcol, 0.125f);

#pragma unroll
    for (int i = 0; i < 4; i++) {
        float inv = 1.f / l_i[i];
        int row = q0 + ty * 4 + i;
        float* o = out + ((size_t)(b * N_ + row)) * D_ + h * 64 + tx * 4;
#pragma unroll
        for (int j = 0; j < 4; j++) o[j] = acc[i][j] * inv;
    }
}

// ---------------- gated split-softmax cross attention ----------------
__global__ __launch_bounds__(256) void attn_cross_kernel(
    const float* __restrict__ kv, const float* __restrict__ qqkv,
    const float* __restrict__ gate, float* __restrict__ out)
{
    __shared__ float Qs[64][64], KPs[64][64], Vs[64][64];
    const int bh = blockIdx.x;
    const int b = bh >> 4, h = bh & 15;
    const int q0 = blockIdx.y * 64;
    const int t = threadIdx.x;
    const int tx = t & 15, ty = t >> 4;
    const int lrow = t >> 2, lcol = (t & 3) << 4;

    const float* qb = qqkv + (size_t)b * QN_ * 3072;
    const float* kb = kv + (size_t)b * N_ * 2048;

    load_q_tile(qb + h * 64, 3072, q0, Qs, lrow, lcol);

    float acc[4][4], m_i[4], l_i[4];
#pragma unroll
    for (int i = 0; i < 4; i++) {
        m_i[i] = -1e30f;
        l_i[i] = 0.f;
#pragma unroll
        for (int j = 0; j < 4; j++) acc[i][j] = 0.f;
    }

    // segment A: keys/values from x (k2|v2), independently softmaxed, gated
    flash_segment(kb + h * 64, kb + 1024 + h * 64, 2048, N_,
                  Qs, KPs, Vs, acc, m_i, l_i, tx, ty, lrow, lcol, 0.125f);

    float outA[4][4];
#pragma unroll
    for (int i = 0; i < 4; i++) {
        float inv = 1.f / l_i[i];
#pragma unroll
        for (int j = 0; j < 4; j++) outA[i][j] = acc[i][j] * inv;
        m_i[i] = -1e30f;
        l_i[i] = 0.f;
#pragma unroll
        for (int j = 0; j < 4; j++) acc[i][j] = 0.f;
    }

    // segment B: keys/values from query stream (qk|qv), independent softmax
    flash_segment(qb + 1024 + h * 64, qb + 2048 + h * 64, 3072, QN_,
                  Qs, KPs, Vs, acc, m_i, l_i, tx, ty, lrow, lcol, 0.125f);

    const float g = tanhf(gate[h]);
#pragma unroll
    for (int i = 0; i < 4; i++) {
        float inv = 1.f / l_i[i];
        int row = q0 + ty * 4 + i;
        float* o = out + ((size_t)(b * QN_ + row)) * D_ + h * 64 + tx * 4;
#pragma unroll
        for (int j = 0; j < 4; j++)
            o[j] = g * outA[i][j] + acc[i][j] * inv;
    }
}

// ---------------- low_res scramble + tiny 64x64 projection ----------------
__global__ void lr_kernel(const float* __restrict__ low_res,
                          const float* __restrict__ W,
                          const float* __restrict__ bias,
                          float* __restrict__ out)
{
    __shared__ float xin[64];
    const int row = blockIdx.x;           // b*256 + i
    const int b = row >> 8;
    const int i = row & 255;
    const int t = threadIdx.x;            // output column j

    // lr_scrambled[b,i,c] = low_res[b, (i*64+c)%256, (i*64+c)/256]
    {
        int f = i * 64 + t;
        xin[t] = low_res[(size_t)b * (LN_ * LD_) + (f & 255) * 64 + (f >> 8)];
    }
    __syncthreads();

    float s = bias[t];
#pragma unroll 8
    for (int c = 0; c < 64; c++)
        s = fmaf(xin[c], W[c * 64 + t], s);
    out[(size_t)row * 64 + t] = s;
}

// ---------------- launch ----------------
extern "C" void kernel_launch(void* const* d_in, const int* in_sizes, int n_in,
                              void* d_out, int out_size)
{
    const float* x        = (const float*)d_in[0];
    const float* query    = (const float*)d_in[1];
    const float* low_res  = (const float*)d_in[2];
    const float* W_qkv    = (const float*)d_in[3];
    const float* W_xkv    = (const float*)d_in[4];
    const float* W_qlin   = (const float*)d_in[5];
    const float* gate     = (const float*)d_in[6];
    const float* W_proj   = (const float*)d_in[7];
    const float* b_proj   = (const float*)d_in[8];
    const float* W_qproj  = (const float*)d_in[9];
    const float* b_qproj  = (const float*)d_in[10];
    const float* W_lrproj = (const float*)d_in[11];
    const float* b_lrproj = (const float*)d_in[12];

    float *qkv, *kv, *qqkv, *xattn, *qattn;
    cudaGetSymbolAddress((void**)&qkv,   g_qkv);
    cudaGetSymbolAddress((void**)&kv,    g_kv);
    cudaGetSymbolAddress((void**)&qqkv,  g_qqkv);
    cudaGetSymbolAddress((void**)&xattn, g_xattn);
    cudaGetSymbolAddress((void**)&qattn, g_qattn);

    float* out   = (float*)d_out;
    float* x_out = out;                              // [B*N, D]
    float* q_out = out + (size_t)B_ * N_ * D_;       // [B*QN, QD]
    float* l_out = q_out + (size_t)B_ * QN_ * D_;    // [B*LN, LD]

    const dim3 blk(256);

    // input projections (independent)
    gemm_kernel<<<dim3(3072 / 64, (B_ * N_) / 64), blk>>>(x, W_qkv, nullptr, qkv,
                                                          B_ * N_, 3072, D_);
    gemm_kernel<<<dim3(2048 / 64, (B_ * N_) / 64), blk>>>(x, W_xkv, nullptr, kv,
                                                          B_ * N_, 2048, D_);
    gemm_kernel<<<dim3(3072 / 64, (B_ * QN_) / 64), blk>>>(query, W_qlin, nullptr, qqkv,
                                                           B_ * QN_, 3072, D_);

    // attention
    attn_self_kernel<<<dim3(B_ * H_, N_ / 64), blk>>>(qkv, xattn);
    attn_cross_kernel<<<dim3(B_ * H_, QN_ / 64), blk>>>(kv, qqkv, gate, qattn);

    // output projections
    gemm_kernel<<<dim3(1024 / 64, (B_ * N_) / 64), blk>>>(xattn, W_proj, b_proj, x_out,
                                                          B_ * N_, D_, D_);
    gemm_kernel<<<dim3(1024 / 64, (B_ * QN_) / 64), blk>>>(qattn, W_qproj, b_qproj, q_out,
                                                           B_ * QN_, D_, D_);

    // low_res branch
    lr_kernel<<<B_ * LN_, 64>>>(low_res, W_lrproj, b_lrproj, l_out);
}

// round 4
// speedup vs baseline: 1.4619x; 1.4619x over previous
#include <cuda_runtime.h>
#include <cuda_bf16.h>
#include <math.h>
#include <stdint.h>

#define B_  2
#define N_  2048
#define QN_ 512
#define D_  1024
#define H_  16
#define LN_ 256
#define LD_ 64

// ======================= helpers =======================
__device__ __forceinline__ uint32_t smem_u32(const void* p) {
    uint32_t a;
    asm("{ .reg .u64 t; cvta.to.shared.u64 t, %1; cvt.u32.u64 %0, t; }" : "=r"(a) : "l"(p));
    return a;
}
__device__ __forceinline__ void ldsm_x4(uint32_t* r, uint32_t addr) {
    asm volatile("ldmatrix.sync.aligned.m8n8.x4.shared.b16 {%0,%1,%2,%3}, [%4];"
                 : "=r"(r[0]), "=r"(r[1]), "=r"(r[2]), "=r"(r[3]) : "r"(addr));
}
__device__ __forceinline__ void mma_bf16(float* d, const uint32_t* a, const uint32_t* b) {
    asm volatile(
        "mma.sync.aligned.m16n8k16.row.col.f32.bf16.bf16.f32 "
        "{%0,%1,%2,%3}, {%4,%5,%6,%7}, {%8,%9}, {%0,%1,%2,%3};"
        : "+f"(d[0]), "+f"(d[1]), "+f"(d[2]), "+f"(d[3])
        : "r"(a[0]), "r"(a[1]), "r"(a[2]), "r"(a[3]), "r"(b[0]), "r"(b[1]));
}
__device__ __forceinline__ uint32_t pack_bf2(__nv_bfloat16 a, __nv_bfloat16 b) {
    __nv_bfloat162 t; t.x = a; t.y = b;
    return *reinterpret_cast<uint32_t*>(&t);
}

// ======================= scratch =======================
__device__ float g_qkv  [B_*N_*3*D_];
__device__ float g_kv   [B_*N_*2*D_];
__device__ float g_qqkv [B_*QN_*3*D_];
__device__ float g_xattn[B_*N_*D_];
__device__ float g_qattn[B_*QN_*D_];
#define WT_TOTAL 10485760  // (3072+2048+3072+1024+1024) x 1024
__device__ __nv_bfloat16 g_wt_hi[WT_TOTAL];
__device__ __nv_bfloat16 g_wt_lo[WT_TOTAL];
#define WOFF_QKV   0
#define WOFF_XKV   (3072*1024)
#define WOFF_QLIN  (WOFF_XKV + 2048*1024)
#define WOFF_PROJ  (WOFF_QLIN + 3072*1024)
#define WOFF_QPROJ (WOFF_PROJ + 1024*1024)

// ============ weight transpose + bf16 split: W[1024][N] -> Wt[N][1024] hi/lo ============
__global__ __launch_bounds__(256) void wsplit_kernel(
    const float* __restrict__ W, __nv_bfloat16* __restrict__ Whi,
    __nv_bfloat16* __restrict__ Wlo, int N)
{
    __shared__ float ts[32][33];
    const int n0 = blockIdx.x * 32, k0 = blockIdx.y * 32;
    const int tx = threadIdx.x & 31, ty = threadIdx.x >> 5;  // 32x8
#pragma unroll
    for (int i = 0; i < 4; i++) {
        int k = k0 + ty + i * 8;
        ts[ty + i * 8][tx] = W[(size_t)k * N + n0 + tx];
    }
    __syncthreads();
#pragma unroll
    for (int i = 0; i < 4; i++) {
        int n = n0 + ty + i * 8;
        float v = ts[tx][ty + i * 8];
        __nv_bfloat16 h = __float2bfloat16(v);
        float r = v - __bfloat162float(h);
        Whi[(size_t)n * 1024 + k0 + tx] = h;
        Wlo[(size_t)n * 1024 + k0 + tx] = __float2bfloat16(r);
    }
}

// ============ split-bf16 HMMA GEMM: C = A[MxK] @ Wt^T (+bias) ============
// A fp32 row-major; Bhi/Blo bf16 [N][K]. CTA tile 128x128, K chunks of 32.
// smem row pitch 80B (40 bf16): conflict-free ldmatrix (banks 0,20,8,28,16,4,24,12).
#define PITCH 80
#define OFS_AH 0
#define OFS_AL 10240
#define OFS_BH 20480
#define OFS_BL 30720
__global__ __launch_bounds__(256, 2) void gemm_mma(
    const float* __restrict__ A, const __nv_bfloat16* __restrict__ Bhi,
    const __nv_bfloat16* __restrict__ Blo, const float* __restrict__ bias,
    float* __restrict__ C, int M, int N, int K)
{
    __shared__ __align__(16) char sm[4 * 128 * PITCH];  // 40 KB
    const uint32_t sb = smem_u32(sm);
    const int t = threadIdx.x;
    const int lane = t & 31;
    const int w = t >> 5;
    const int wm = w & 3, wn = w >> 2;          // 4x2 warp grid
    const int bm = blockIdx.y * 128, bn = blockIdx.x * 128;

    float acc[2][8][4];
#pragma unroll
    for (int mf = 0; mf < 2; mf++)
#pragma unroll
        for (int nf = 0; nf < 8; nf++)
#pragma unroll
            for (int q = 0; q < 4; q++) acc[mf][nf][q] = 0.f;

    // per-thread load coords: row m = f>>3, k4 = (f&7)*4 elements
    for (int k0 = 0; k0 < K; k0 += 32) {
#pragma unroll
        for (int i = 0; i < 4; i++) {
            int f = t + i * 256;
            int m = f >> 3, k4 = (f & 7) << 2;
            // A: fp32 -> hi/lo bf16
            float4 v = *(const float4*)&A[(size_t)(bm + m) * K + k0 + k4];
            __nv_bfloat16 hx = __float2bfloat16(v.x), hy = __float2bfloat16(v.y);
            __nv_bfloat16 hz = __float2bfloat16(v.z), hw = __float2bfloat16(v.w);
            __nv_bfloat16 lx = __float2bfloat16(v.x - __bfloat162float(hx));
            __nv_bfloat16 ly = __float2bfloat16(v.y - __bfloat162float(hy));
            __nv_bfloat16 lz = __float2bfloat16(v.z - __bfloat162float(hz));
            __nv_bfloat16 lw = __float2bfloat16(v.w - __bfloat162float(hw));
            uint32_t off = (uint32_t)(m * PITCH + k4 * 2);
            *(uint2*)(sm + OFS_AH + off) = make_uint2(pack_bf2(hx, hy), pack_bf2(hz, hw));
            *(uint2*)(sm + OFS_AL + off) = make_uint2(pack_bf2(lx, ly), pack_bf2(lz, lw));
            // B: straight bf16 copy
            *(uint2*)(sm + OFS_BH + off) = *(const uint2*)&Bhi[(size_t)(bn + m) * K + k0 + k4];
            *(uint2*)(sm + OFS_BL + off) = *(const uint2*)&Blo[(size_t)(bn + m) * K + k0 + k4];
        }
        __syncthreads();

#pragma unroll
        for (int ks = 0; ks < 2; ks++) {
            uint32_t ah[2][4], al[2][4];
#pragma unroll
            for (int mf = 0; mf < 2; mf++) {
                uint32_t addr = sb + OFS_AH +
                    (uint32_t)((wm * 32 + mf * 16 + (lane & 15)) * PITCH +
                               ks * 32 + (lane >> 4) * 16);
                ldsm_x4(ah[mf], addr);
                ldsm_x4(al[mf], addr + (OFS_AL - OFS_AH));
            }
#pragma unroll
            for (int p = 0; p < 4; p++) {
                int g = lane >> 3;
                uint32_t baddr = sb + OFS_BH +
                    (uint32_t)((wn * 64 + (p * 2 + (g >> 1)) * 8 + (lane & 7)) * PITCH +
                               ks * 32 + (g & 1) * 16);
                uint32_t bh[4], bl[4];
                ldsm_x4(bh, baddr);
                ldsm_x4(bl, baddr + (OFS_BL - OFS_BH));
#pragma unroll
                for (int mf = 0; mf < 2; mf++) {
                    mma_bf16(acc[mf][p * 2 + 0], ah[mf], &bh[0]);
                    mma_bf16(acc[mf][p * 2 + 0], ah[mf], &bl[0]);
                    mma_bf16(acc[mf][p * 2 + 0], al[mf], &bh[0]);
                    mma_bf16(acc[mf][p * 2 + 1], ah[mf], &bh[2]);
                    mma_bf16(acc[mf][p * 2 + 1], ah[mf], &bl[2]);
                    mma_bf16(acc[mf][p * 2 + 1], al[mf], &bh[2]);
                }
            }
        }
        __syncthreads();
    }

    // epilogue: direct float2 stores (+bias)
#pragma unroll
    for (int mf = 0; mf < 2; mf++) {
        int m = bm + wm * 32 + mf * 16 + (lane >> 2);
#pragma unroll
        for (int nf = 0; nf < 8; nf++) {
            int n = bn + wn * 64 + nf * 8 + (lane & 3) * 2;
            float2 v0 = make_float2(acc[mf][nf][0], acc[mf][nf][1]);
            float2 v1 = make_float2(acc[mf][nf][2], acc[mf][nf][3]);
            if (bias) {
                float2 bv = *(const float2*)&bias[n];
                v0.x += bv.x; v0.y += bv.y;
                v1.x += bv.x; v1.y += bv.y;
            }
            *(float2*)&C[(size_t)m * N + n] = v0;
            *(float2*)&C[(size_t)(m + 8) * N + n] = v1;
        }
    }
}

// ======================= SIMT flash attention (unchanged, passing) =======================
__device__ __forceinline__ void flash_segment(
    const float* __restrict__ Kg, const float* __restrict__ Vg,
    int kstride, int nkeys,
    float (*Qs)[64], float (*KPs)[64], float (*Vs)[64],
    float acc[4][4], float* m_i, float* l_i,
    int tx, int ty, int lrow, int lcol, float scale)
{
    for (int k0 = 0; k0 < nkeys; k0 += 64) {
        __syncthreads();
        {
            const float* krow = &Kg[(size_t)(k0 + lrow) * kstride + lcol];
            const float* vrow = &Vg[(size_t)(k0 + lrow) * kstride + lcol];
#pragma unroll
            for (int c = 0; c < 16; c += 4) {
                float4 kv4 = *(const float4*)&krow[c];
                KPs[lcol + c + 0][lrow] = kv4.x;
                KPs[lcol + c + 1][lrow] = kv4.y;
                KPs[lcol + c + 2][lrow] = kv4.z;
                KPs[lcol + c + 3][lrow] = kv4.w;
                float4 vv = *(const float4*)&vrow[c];
                *(float4*)&Vs[lrow][lcol + c] = vv;
            }
        }
        __syncthreads();

        float s[4][4];
#pragma unroll
        for (int i = 0; i < 4; i++)
#pragma unroll
            for (int j = 0; j < 4; j++) s[i][j] = 0.f;

#pragma unroll 8
        for (int e = 0; e < 64; e++) {
            float4 a = *(const float4*)&Qs[e][ty * 4];
            float4 b = *(const float4*)&KPs[e][tx * 4];
            float aa[4] = {a.x, a.y, a.z, a.w};
            float bb[4] = {b.x, b.y, b.z, b.w};
#pragma unroll
            for (int i = 0; i < 4; i++)
#pragma unroll
                for (int j = 0; j < 4; j++)
                    s[i][j] = fmaf(aa[i], bb[j], s[i][j]);
        }
        __syncthreads();

#pragma unroll
        for (int i = 0; i < 4; i++) {
            float rm = -1e30f;
#pragma unroll
            for (int j = 0; j < 4; j++) {
                s[i][j] *= scale;
                rm = fmaxf(rm, s[i][j]);
            }
#pragma unroll
            for (int o = 8; o >= 1; o >>= 1)
                rm = fmaxf(rm, __shfl_xor_sync(0xffffffffu, rm, o));
            float mnew = fmaxf(m_i[i], rm);
            float alpha = __expf(m_i[i] - mnew);
            m_i[i] = mnew;
            float rs = 0.f;
#pragma unroll
            for (int j = 0; j < 4; j++) {
                s[i][j] = __expf(s[i][j] - mnew);
                rs += s[i][j];
            }
#pragma unroll
            for (int o = 8; o >= 1; o >>= 1)
                rs += __shfl_xor_sync(0xffffffffu, rs, o);
            l_i[i] = l_i[i] * alpha + rs;
#pragma unroll
            for (int j = 0; j < 4; j++) acc[i][j] *= alpha;
        }

#pragma unroll
        for (int i = 0; i < 4; i++) {
            float4 pv = make_float4(s[i][0], s[i][1], s[i][2], s[i][3]);
            *(float4*)&KPs[ty * 4 + i][tx * 4] = pv;
        }
        __syncthreads();

#pragma unroll 8
        for (int kk = 0; kk < 64; kk++) {
            float4 b = *(const float4*)&Vs[kk][tx * 4];
            float bb[4] = {b.x, b.y, b.z, b.w};
            float pa[4];
#pragma unroll
            for (int i = 0; i < 4; i++) pa[i] = KPs[ty * 4 + i][kk];
#pragma unroll
            for (int i = 0; i < 4; i++)
#pragma unroll
                for (int j = 0; j < 4; j++)
                    acc[i][j] = fmaf(pa[i], bb[j], acc[i][j]);
        }
    }
}

__device__ __forceinline__ void load_q_tile(
    const float* __restrict__ Qg, int stride, int q0,
    float (*Qs)[64], int lrow, int lcol)
{
    const float* qrow = &Qg[(size_t)(q0 + lrow) * stride + lcol];
#pragma unroll
    for (int c = 0; c < 16; c += 4) {
        float4 qv = *(const float4*)&qrow[c];
        Qs[lcol + c + 0][lrow] = qv.x;
        Qs[lcol + c + 1][lrow] = qv.y;
        Qs[lcol + c + 2][lrow] = qv.z;
        Qs[lcol + c + 3][lrow] = qv.w;
    }
}

__global__ __launch_bounds__(256) void attn_self_kernel(
    const float* __restrict__ qkv, float* __restrict__ out)
{
    __shared__ float Qs[64][64], KPs[64][64], Vs[64][64];
    const int bh = blockIdx.x;
    const int b = bh >> 4, h = bh & 15;
    const int q0 = blockIdx.y * 64;
    const int t = threadIdx.x;
    const int tx = t & 15, ty = t >> 4;
    const int lrow = t >> 2, lcol = (t & 3) << 4;

    const float* base = qkv + (size_t)b * N_ * 3072;
    load_q_tile(base + h * 64, 3072, q0, Qs, lrow, lcol);

    float acc[4][4], m_i[4], l_i[4];
#pragma unroll
    for (int i = 0; i < 4; i++) {
        m_i[i] = -1e30f; l_i[i] = 0.f;
#pragma unroll
        for (int j = 0; j < 4; j++) acc[i][j] = 0.f;
    }

    flash_segment(base + 1024 + h * 64, base + 2048 + h * 64, 3072, N_,
                  Qs, KPs, Vs, acc, m_i, l_i, tx, ty, lrow, lcol, 0.125f);

#pragma unroll
    for (int i = 0; i < 4; i++) {
        float inv = 1.f / l_i[i];
        int row = q0 + ty * 4 + i;
        float* o = out + ((size_t)(b * N_ + row)) * D_ + h * 64 + tx * 4;
#pragma unroll
        for (int j = 0; j < 4; j++) o[j] = acc[i][j] * inv;
    }
}

__global__ __launch_bounds__(256) void attn_cross_kernel(
    const float* __restrict__ kv, const float* __restrict__ qqkv,
    const float* __restrict__ gate, float* __restrict__ out)
{
    __shared__ float Qs[64][64], KPs[64][64], Vs[64][64];
    const int bh = blockIdx.x;
    const int b = bh >> 4, h = bh & 15;
    const int q0 = blockIdx.y * 64;
    const int t = threadIdx.x;
    const int tx = t & 15, ty = t >> 4;
    const int lrow = t >> 2, lcol = (t & 3) << 4;

    const float* qb = qqkv + (size_t)b * QN_ * 3072;
    const float* kb = kv + (size_t)b * N_ * 2048;

    load_q_tile(qb + h * 64, 3072, q0, Qs, lrow, lcol);

    float acc[4][4], m_i[4], l_i[4];
#pragma unroll
    for (int i = 0; i < 4; i++) {
        m_i[i] = -1e30f; l_i[i] = 0.f;
#pragma unroll
        for (int j = 0; j < 4; j++) acc[i][j] = 0.f;
    }

    flash_segment(kb + h * 64, kb + 1024 + h * 64, 2048, N_,
                  Qs, KPs, Vs, acc, m_i, l_i, tx, ty, lrow, lcol, 0.125f);

    float outA[4][4];
#pragma unroll
    for (int i = 0; i < 4; i++) {
        float inv = 1.f / l_i[i];
#pragma unroll
        for (int j = 0; j < 4; j++) outA[i][j] = acc[i][j] * inv;
        m_i[i] = -1e30f; l_i[i] = 0.f;
#pragma unroll
        for (int j = 0; j < 4; j++) acc[i][j] = 0.f;
    }

    flash_segment(qb + 1024 + h * 64, qb + 2048 + h * 64, 3072, QN_,
                  Qs, KPs, Vs, acc, m_i, l_i, tx, ty, lrow, lcol, 0.125f);

    const float g = tanhf(gate[h]);
#pragma unroll
    for (int i = 0; i < 4; i++) {
        float inv = 1.f / l_i[i];
        int row = q0 + ty * 4 + i;
        float* o = out + ((size_t)(b * QN_ + row)) * D_ + h * 64 + tx * 4;
#pragma unroll
        for (int j = 0; j < 4; j++)
            o[j] = g * outA[i][j] + acc[i][j] * inv;
    }
}

// ======================= low_res scramble + 64x64 proj =======================
__global__ void lr_kernel(const float* __restrict__ low_res,
                          const float* __restrict__ W,
                          const float* __restrict__ bias,
                          float* __restrict__ out)
{
    __shared__ float xin[64];
    const int row = blockIdx.x;
    const int b = row >> 8;
    const int i = row & 255;
    const int t = threadIdx.x;
    {
        int f = i * 64 + t;
        xin[t] = low_res[(size_t)b * (LN_ * LD_) + (f & 255) * 64 + (f >> 8)];
    }
    __syncthreads();
    float s = bias[t];
#pragma unroll 8
    for (int c = 0; c < 64; c++)
        s = fmaf(xin[c], W[c * 64 + t], s);
    out[(size_t)row * 64 + t] = s;
}

// ======================= launch =======================
extern "C" void kernel_launch(void* const* d_in, const int* in_sizes, int n_in,
                              void* d_out, int out_size)
{
    const float* x        = (const float*)d_in[0];
    const float* query    = (const float*)d_in[1];
    const float* low_res  = (const float*)d_in[2];
    const float* W_qkv    = (const float*)d_in[3];
    const float* W_xkv    = (const float*)d_in[4];
    const float* W_qlin   = (const float*)d_in[5];
    const float* gate     = (const float*)d_in[6];
    const float* W_proj   = (const float*)d_in[7];
    const float* b_proj   = (const float*)d_in[8];
    const float* W_qproj  = (const float*)d_in[9];
    const float* b_qproj  = (const float*)d_in[10];
    const float* W_lrproj = (const float*)d_in[11];
    const float* b_lrproj = (const float*)d_in[12];

    float *qkv, *kv, *qqkv, *xattn, *qattn;
    __nv_bfloat16 *wh, *wl;
    cudaGetSymbolAddress((void**)&qkv,   g_qkv);
    cudaGetSymbolAddress((void**)&kv,    g_kv);
    cudaGetSymbolAddress((void**)&qqkv,  g_qqkv);
    cudaGetSymbolAddress((void**)&xattn, g_xattn);
    cudaGetSymbolAddress((void**)&qattn, g_qattn);
    cudaGetSymbolAddress((void**)&wh,    g_wt_hi);
    cudaGetSymbolAddress((void**)&wl,    g_wt_lo);

    float* out   = (float*)d_out;
    float* x_out = out;
    float* q_out = out + (size_t)B_ * N_ * D_;
    float* l_out = q_out + (size_t)B_ * QN_ * D_;

    const dim3 blk(256);

    // weight transpose + split
    wsplit_kernel<<<dim3(3072 / 32, 32), blk>>>(W_qkv,   wh + WOFF_QKV,   wl + WOFF_QKV,   3072);
    wsplit_kernel<<<dim3(2048 / 32, 32), blk>>>(W_xkv,   wh + WOFF_XKV,   wl + WOFF_XKV,   2048);
    wsplit_kernel<<<dim3(3072 / 32, 32), blk>>>(W_qlin,  wh + WOFF_QLIN,  wl + WOFF_QLIN,  3072);
    wsplit_kernel<<<dim3(1024 / 32, 32), blk>>>(W_proj,  wh + WOFF_PROJ,  wl + WOFF_PROJ,  1024);
    wsplit_kernel<<<dim3(1024 / 32, 32), blk>>>(W_qproj, wh + WOFF_QPROJ, wl + WOFF_QPROJ, 1024);

    // input projections (HMMA split-bf16)
    gemm_mma<<<dim3(3072 / 128, 4096 / 128), blk>>>(
        x, wh + WOFF_QKV, wl + WOFF_QKV, nullptr, qkv, 4096, 3072, 1024);
    gemm_mma<<<dim3(2048 / 128, 4096 / 128), blk>>>(
        x, wh + WOFF_XKV, wl + WOFF_XKV, nullptr, kv, 4096, 2048, 1024);
    gemm_mma<<<dim3(3072 / 128, 1024 / 128), blk>>>(
        query, wh + WOFF_QLIN, wl + WOFF_QLIN, nullptr, qqkv, 1024, 3072, 1024);

    // attention (SIMT)
    attn_self_kernel<<<dim3(B_ * H_, N_ / 64), blk>>>(qkv, xattn);
    attn_cross_kernel<<<dim3(B_ * H_, QN_ / 64), blk>>>(kv, qqkv, gate, qattn);

    // output projections (HMMA)
    gemm_mma<<<dim3(1024 / 128, 4096 / 128), blk>>>(
        xattn, wh + WOFF_PROJ, wl + WOFF_PROJ, b_proj, x_out, 4096, 1024, 1024);
    gemm_mma<<<dim3(1024 / 128, 1024 / 128), blk>>>(
        qattn, wh + WOFF_QPROJ, wl + WOFF_QPROJ, b_qproj, q_out, 1024, 1024, 1024);

    // low_res branch
    lr_kernel<<<B_ * LN_, 64>>>(low_res, W_lrproj, b_lrproj, l_out);
}

// round 5
// speedup vs baseline: 2.4566x; 1.6804x over previous
#include <cuda_runtime.h>
#include <cuda_bf16.h>
#include <math.h>
#include <stdint.h>

#define B_  2
#define N_  2048
#define QN_ 512
#define D_  1024
#define H_  16
#define LN_ 256
#define LD_ 64

// ======================= helpers =======================
__device__ __forceinline__ uint32_t smem_u32(const void* p) {
    uint32_t a;
    asm("{ .reg .u64 t; cvta.to.shared.u64 t, %1; cvt.u32.u64 %0, t; }" : "=r"(a) : "l"(p));
    return a;
}
__device__ __forceinline__ void ldsm_x4(uint32_t* r, uint32_t addr) {
    asm volatile("ldmatrix.sync.aligned.m8n8.x4.shared.b16 {%0,%1,%2,%3}, [%4];"
                 : "=r"(r[0]), "=r"(r[1]), "=r"(r[2]), "=r"(r[3]) : "r"(addr));
}
__device__ __forceinline__ void ldsm_x4_t(uint32_t* r, uint32_t addr) {
    asm volatile("ldmatrix.sync.aligned.m8n8.x4.trans.shared.b16 {%0,%1,%2,%3}, [%4];"
                 : "=r"(r[0]), "=r"(r[1]), "=r"(r[2]), "=r"(r[3]) : "r"(addr));
}
__device__ __forceinline__ void mma_bf16(float* d, const uint32_t* a, const uint32_t* b) {
    asm volatile(
        "mma.sync.aligned.m16n8k16.row.col.f32.bf16.bf16.f32 "
        "{%0,%1,%2,%3}, {%4,%5,%6,%7}, {%8,%9}, {%0,%1,%2,%3};"
        : "+f"(d[0]), "+f"(d[1]), "+f"(d[2]), "+f"(d[3])
        : "r"(a[0]), "r"(a[1]), "r"(a[2]), "r"(a[3]), "r"(b[0]), "r"(b[1]));
}
__device__ __forceinline__ uint32_t pack_bf2(__nv_bfloat16 a, __nv_bfloat16 b) {
    __nv_bfloat162 t; t.x = a; t.y = b;
    return *reinterpret_cast<uint32_t*>(&t);
}
// split two fp32 into packed hi / packed lo bf16x2
__device__ __forceinline__ void split2(float x, float y, uint32_t& hi, uint32_t& lo) {
    __nv_bfloat16 hx = __float2bfloat16(x), hy = __float2bfloat16(y);
    __nv_bfloat16 lx = __float2bfloat16(x - __bfloat162float(hx));
    __nv_bfloat16 ly = __float2bfloat16(y - __bfloat162float(hy));
    hi = pack_bf2(hx, hy);
    lo = pack_bf2(lx, ly);
}

// ======================= scratch =======================
__device__ __nv_bfloat16 g_qkv_h [B_*N_*3*D_],  g_qkv_l [B_*N_*3*D_];
__device__ __nv_bfloat16 g_kv_h  [B_*N_*2*D_],  g_kv_l  [B_*N_*2*D_];
__device__ __nv_bfloat16 g_qqkv_h[B_*QN_*3*D_], g_qqkv_l[B_*QN_*3*D_];
__device__ float g_xattn[B_*N_*D_];
__device__ float g_qattn[B_*QN_*D_];
#define WT_TOTAL 10485760
__device__ __nv_bfloat16 g_wt_hi[WT_TOTAL];
__device__ __nv_bfloat16 g_wt_lo[WT_TOTAL];
#define WOFF_QKV   0
#define WOFF_XKV   (3072*1024)
#define WOFF_QLIN  (WOFF_XKV + 2048*1024)
#define WOFF_PROJ  (WOFF_QLIN + 3072*1024)
#define WOFF_QPROJ (WOFF_PROJ + 1024*1024)

// ============ weight transpose + bf16 split ============
__global__ __launch_bounds__(256) void wsplit_kernel(
    const float* __restrict__ W, __nv_bfloat16* __restrict__ Whi,
    __nv_bfloat16* __restrict__ Wlo, int N)
{
    __shared__ float ts[32][33];
    const int n0 = blockIdx.x * 32, k0 = blockIdx.y * 32;
    const int tx = threadIdx.x & 31, ty = threadIdx.x >> 5;
#pragma unroll
    for (int i = 0; i < 4; i++) {
        int k = k0 + ty + i * 8;
        ts[ty + i * 8][tx] = W[(size_t)k * N + n0 + tx];
    }
    __syncthreads();
#pragma unroll
    for (int i = 0; i < 4; i++) {
        int n = n0 + ty + i * 8;
        float v = ts[tx][ty + i * 8];
        __nv_bfloat16 h = __float2bfloat16(v);
        Whi[(size_t)n * 1024 + k0 + tx] = h;
        Wlo[(size_t)n * 1024 + k0 + tx] = __float2bfloat16(v - __bfloat162float(h));
    }
}

// ============ split-bf16 HMMA GEMM ============
// A fp32 [M][K]; Bhi/Blo bf16 [N][K]. Output: fp32 C (+bias) OR split bf16 Chi/Clo.
#define PITCH 80
#define OFS_AH 0
#define OFS_AL 10240
#define OFS_BH 20480
#define OFS_BL 30720
__global__ __launch_bounds__(256, 2) void gemm_mma(
    const float* __restrict__ A, const __nv_bfloat16* __restrict__ Bhi,
    const __nv_bfloat16* __restrict__ Blo, const float* __restrict__ bias,
    float* __restrict__ C, __nv_bfloat16* __restrict__ Chi,
    __nv_bfloat16* __restrict__ Clo, int M, int N, int K)
{
    __shared__ __align__(16) char sm[4 * 128 * PITCH];
    const uint32_t sb = smem_u32(sm);
    const int t = threadIdx.x;
    const int lane = t & 31;
    const int w = t >> 5;
    const int wm = w & 3, wn = w >> 2;
    const int bm = blockIdx.y * 128, bn = blockIdx.x * 128;

    float acc[2][8][4];
#pragma unroll
    for (int mf = 0; mf < 2; mf++)
#pragma unroll
        for (int nf = 0; nf < 8; nf++)
#pragma unroll
            for (int q = 0; q < 4; q++) acc[mf][nf][q] = 0.f;

    for (int k0 = 0; k0 < K; k0 += 32) {
#pragma unroll
        for (int i = 0; i < 4; i++) {
            int f = t + i * 256;
            int m = f >> 3, k4 = (f & 7) << 2;
            float4 v = *(const float4*)&A[(size_t)(bm + m) * K + k0 + k4];
            __nv_bfloat16 hx = __float2bfloat16(v.x), hy = __float2bfloat16(v.y);
            __nv_bfloat16 hz = __float2bfloat16(v.z), hw = __float2bfloat16(v.w);
            __nv_bfloat16 lx = __float2bfloat16(v.x - __bfloat162float(hx));
            __nv_bfloat16 ly = __float2bfloat16(v.y - __bfloat162float(hy));
            __nv_bfloat16 lz = __float2bfloat16(v.z - __bfloat162float(hz));
            __nv_bfloat16 lw = __float2bfloat16(v.w - __bfloat162float(hw));
            uint32_t off = (uint32_t)(m * PITCH + k4 * 2);
            *(uint2*)(sm + OFS_AH + off) = make_uint2(pack_bf2(hx, hy), pack_bf2(hz, hw));
            *(uint2*)(sm + OFS_AL + off) = make_uint2(pack_bf2(lx, ly), pack_bf2(lz, lw));
            *(uint2*)(sm + OFS_BH + off) = *(const uint2*)&Bhi[(size_t)(bn + m) * K + k0 + k4];
            *(uint2*)(sm + OFS_BL + off) = *(const uint2*)&Blo[(size_t)(bn + m) * K + k0 + k4];
        }
        __syncthreads();

#pragma unroll
        for (int ks = 0; ks < 2; ks++) {
            uint32_t ah[2][4], al[2][4];
#pragma unroll
            for (int mf = 0; mf < 2; mf++) {
                uint32_t addr = sb + OFS_AH +
                    (uint32_t)((wm * 32 + mf * 16 + (lane & 15)) * PITCH +
                               ks * 32 + (lane >> 4) * 16);
                ldsm_x4(ah[mf], addr);
                ldsm_x4(al[mf], addr + (OFS_AL - OFS_AH));
            }
#pragma unroll
            for (int p = 0; p < 4; p++) {
                int g = lane >> 3;
                uint32_t baddr = sb + OFS_BH +
                    (uint32_t)((wn * 64 + (p * 2 + (g >> 1)) * 8 + (lane & 7)) * PITCH +
                               ks * 32 + (g & 1) * 16);
                uint32_t bh[4], bl[4];
                ldsm_x4(bh, baddr);
                ldsm_x4(bl, baddr + (OFS_BL - OFS_BH));
#pragma unroll
                for (int mf = 0; mf < 2; mf++) {
                    mma_bf16(acc[mf][p * 2 + 0], ah[mf], &bh[0]);
                    mma_bf16(acc[mf][p * 2 + 0], ah[mf], &bl[0]);
                    mma_bf16(acc[mf][p * 2 + 0], al[mf], &bh[0]);
                    mma_bf16(acc[mf][p * 2 + 1], ah[mf], &bh[2]);
                    mma_bf16(acc[mf][p * 2 + 1], ah[mf], &bl[2]);
                    mma_bf16(acc[mf][p * 2 + 1], al[mf], &bh[2]);
                }
            }
        }
        __syncthreads();
    }

#pragma unroll
    for (int mf = 0; mf < 2; mf++) {
        int m = bm + wm * 32 + mf * 16 + (lane >> 2);
#pragma unroll
        for (int nf = 0; nf < 8; nf++) {
            int n = bn + wn * 64 + nf * 8 + (lane & 3) * 2;
            if (Chi) {
                uint32_t h0, l0, h1, l1;
                split2(acc[mf][nf][0], acc[mf][nf][1], h0, l0);
                split2(acc[mf][nf][2], acc[mf][nf][3], h1, l1);
                *(uint32_t*)&Chi[(size_t)m * N + n] = h0;
                *(uint32_t*)&Clo[(size_t)m * N + n] = l0;
                *(uint32_t*)&Chi[(size_t)(m + 8) * N + n] = h1;
                *(uint32_t*)&Clo[(size_t)(m + 8) * N + n] = l1;
            } else {
                float2 v0 = make_float2(acc[mf][nf][0], acc[mf][nf][1]);
                float2 v1 = make_float2(acc[mf][nf][2], acc[mf][nf][3]);
                if (bias) {
                    float2 bv = *(const float2*)&bias[n];
                    v0.x += bv.x; v0.y += bv.y;
                    v1.x += bv.x; v1.y += bv.y;
                }
                *(float2*)&C[(size_t)m * N + n] = v0;
                *(float2*)&C[(size_t)(m + 8) * N + n] = v1;
            }
        }
    }
}

// ======================= HMMA flash attention =======================
// smem: 4 buffers of 64 rows x 144B pitch (K hi/lo, V hi/lo). 36864 B total.
#define APITCH 144
#define AKH 0
#define AKL 9216
#define AVH 18432
#define AVL 27648

__device__ __forceinline__ void attn_segment_mma(
    const __nv_bfloat16* __restrict__ Kh, const __nv_bfloat16* __restrict__ Kl,
    const __nv_bfloat16* __restrict__ Vh, const __nv_bfloat16* __restrict__ Vl,
    int rstride, int nkeys, char* smp, uint32_t sb,
    const uint32_t (&qfh)[4][4], const uint32_t (&qfl)[4][4],
    float (&oacc)[8][4], float& m0, float& m1, float& l0, float& l1,
    int t, int lane)
{
    for (int k0 = 0; k0 < nkeys; k0 += 64) {
        __syncthreads();
#pragma unroll
        for (int i = 0; i < 4; i++) {
            int f = t + i * 256;
            int row = f >> 4, c8 = f & 15;
            size_t go = (size_t)(k0 + row) * rstride + c8 * 4;
            uint32_t so = (uint32_t)(row * APITCH + c8 * 8);
            *(uint2*)(smp + AKH + so) = *(const uint2*)&Kh[go];
            *(uint2*)(smp + AKL + so) = *(const uint2*)&Kl[go];
            *(uint2*)(smp + AVH + so) = *(const uint2*)&Vh[go];
            *(uint2*)(smp + AVL + so) = *(const uint2*)&Vl[go];
        }
        __syncthreads();

        // ---- S = Q K^T (scaled Q already) ----
        float sacc[8][4];
#pragma unroll
        for (int nt = 0; nt < 8; nt++)
#pragma unroll
            for (int q = 0; q < 4; q++) sacc[nt][q] = 0.f;

#pragma unroll
        for (int kc = 0; kc < 4; kc++) {
#pragma unroll
            for (int ntp = 0; ntp < 4; ntp++) {
                uint32_t baddr = sb + AKH +
                    (uint32_t)((ntp * 16 + (lane & 7) + ((lane >> 4)) * 8) * APITCH +
                               kc * 32 + ((lane >> 3) & 1) * 16);
                uint32_t bh4[4], bl4[4];
                ldsm_x4(bh4, baddr);
                ldsm_x4(bl4, baddr + (AKL - AKH));
                mma_bf16(sacc[ntp * 2 + 0], qfh[kc], &bh4[0]);
                mma_bf16(sacc[ntp * 2 + 0], qfh[kc], &bl4[0]);
                mma_bf16(sacc[ntp * 2 + 0], qfl[kc], &bh4[0]);
                mma_bf16(sacc[ntp * 2 + 1], qfh[kc], &bh4[2]);
                mma_bf16(sacc[ntp * 2 + 1], qfh[kc], &bl4[2]);
                mma_bf16(sacc[ntp * 2 + 1], qfl[kc], &bh4[2]);
            }
        }

        // ---- online softmax (rows r=lane>>2 and r+8) ----
        float mx0 = -1e30f, mx1 = -1e30f;
#pragma unroll
        for (int nt = 0; nt < 8; nt++) {
            mx0 = fmaxf(mx0, fmaxf(sacc[nt][0], sacc[nt][1]));
            mx1 = fmaxf(mx1, fmaxf(sacc[nt][2], sacc[nt][3]));
        }
        mx0 = fmaxf(mx0, __shfl_xor_sync(0xffffffffu, mx0, 1));
        mx0 = fmaxf(mx0, __shfl_xor_sync(0xffffffffu, mx0, 2));
        mx1 = fmaxf(mx1, __shfl_xor_sync(0xffffffffu, mx1, 1));
        mx1 = fmaxf(mx1, __shfl_xor_sync(0xffffffffu, mx1, 2));
        float mn0 = fmaxf(m0, mx0), mn1 = fmaxf(m1, mx1);
        float a0 = __expf(m0 - mn0), a1 = __expf(m1 - mn1);
        m0 = mn0; m1 = mn1;
        float rs0 = 0.f, rs1 = 0.f;
#pragma unroll
        for (int nt = 0; nt < 8; nt++) {
            sacc[nt][0] = __expf(sacc[nt][0] - mn0);
            sacc[nt][1] = __expf(sacc[nt][1] - mn0);
            sacc[nt][2] = __expf(sacc[nt][2] - mn1);
            sacc[nt][3] = __expf(sacc[nt][3] - mn1);
            rs0 += sacc[nt][0] + sacc[nt][1];
            rs1 += sacc[nt][2] + sacc[nt][3];
        }
        rs0 += __shfl_xor_sync(0xffffffffu, rs0, 1);
        rs0 += __shfl_xor_sync(0xffffffffu, rs0, 2);
        rs1 += __shfl_xor_sync(0xffffffffu, rs1, 1);
        rs1 += __shfl_xor_sync(0xffffffffu, rs1, 2);
        l0 = l0 * a0 + rs0;
        l1 = l1 * a1 + rs1;
#pragma unroll
        for (int dt = 0; dt < 8; dt++) {
            oacc[dt][0] *= a0; oacc[dt][1] *= a0;
            oacc[dt][2] *= a1; oacc[dt][3] *= a1;
        }

        // ---- O += P V ----
#pragma unroll
        for (int kc = 0; kc < 4; kc++) {
            uint32_t ph[4], pl[4];
            split2(sacc[2 * kc][0], sacc[2 * kc][1], ph[0], pl[0]);
            split2(sacc[2 * kc][2], sacc[2 * kc][3], ph[1], pl[1]);
            split2(sacc[2 * kc + 1][0], sacc[2 * kc + 1][1], ph[2], pl[2]);
            split2(sacc[2 * kc + 1][2], sacc[2 * kc + 1][3], ph[3], pl[3]);
#pragma unroll
            for (int dp = 0; dp < 4; dp++) {
                uint32_t vaddr = sb + AVH +
                    (uint32_t)((kc * 16 + (lane & 7) + ((lane >> 3) & 1) * 8) * APITCH +
                               (dp * 16 + (lane >> 4) * 8) * 2);
                uint32_t vh4[4], vl4[4];
                ldsm_x4_t(vh4, vaddr);
                ldsm_x4_t(vl4, vaddr + (AVL - AVH));
                mma_bf16(oacc[dp * 2 + 0], ph, &vh4[0]);
                mma_bf16(oacc[dp * 2 + 0], ph, &vl4[0]);
                mma_bf16(oacc[dp * 2 + 0], pl, &vh4[0]);
                mma_bf16(oacc[dp * 2 + 1], ph, &vh4[2]);
                mma_bf16(oacc[dp * 2 + 1], ph, &vl4[2]);
                mma_bf16(oacc[dp * 2 + 1], pl, &vh4[2]);
            }
        }
    }
}

// stage 128x64 Q tile (hi at smem+0, lo at smem+18432) scaled by 1/8, load frags
__device__ __forceinline__ void load_q_frags(
    const __nv_bfloat16* __restrict__ Qh, const __nv_bfloat16* __restrict__ Ql,
    int rstride, int q0, char* smp, uint32_t sb,
    uint32_t (&qfh)[4][4], uint32_t (&qfl)[4][4], int t, int lane, int w)
{
    const __nv_bfloat162 sc = __floats2bfloat162_rn(0.125f, 0.125f);
#pragma unroll
    for (int i = 0; i < 8; i++) {
        int f = t + i * 256;
        int row = f >> 4, c8 = f & 15;
        size_t go = (size_t)(q0 + row) * rstride + c8 * 4;
        uint32_t so = (uint32_t)(row * APITCH + c8 * 8);
        uint2 vh = *(const uint2*)&Qh[go];
        uint2 vl = *(const uint2*)&Ql[go];
        __nv_bfloat162* ph = (__nv_bfloat162*)&vh;
        __nv_bfloat162* pL = (__nv_bfloat162*)&vl;
        ph[0] = __hmul2(ph[0], sc); ph[1] = __hmul2(ph[1], sc);
        pL[0] = __hmul2(pL[0], sc); pL[1] = __hmul2(pL[1], sc);
        *(uint2*)(smp + so) = vh;
        *(uint2*)(smp + 18432 + so) = vl;
    }
    __syncthreads();
#pragma unroll
    for (int kc = 0; kc < 4; kc++) {
        uint32_t addr = sb + (uint32_t)((w * 16 + (lane & 15)) * APITCH +
                                        kc * 32 + (lane >> 4) * 16);
        ldsm_x4(qfh[kc], addr);
        ldsm_x4(qfl[kc], addr + 18432);
    }
    // segment loop begins with __syncthreads(), protecting this smem reuse
}

__global__ __launch_bounds__(256) void attn_self_mma(
    const __nv_bfloat16* __restrict__ qkv_h, const __nv_bfloat16* __restrict__ qkv_l,
    float* __restrict__ out)
{
    __shared__ __align__(16) char smp[36864];
    const uint32_t sb = smem_u32(smp);
    const int t = threadIdx.x, lane = t & 31, w = t >> 5;
    const int bh = blockIdx.x, b = bh >> 4, h = bh & 15;
    const int q0 = blockIdx.y * 128;

    const __nv_bfloat16* baseh = qkv_h + (size_t)b * N_ * 3072 + h * 64;
    const __nv_bfloat16* basel = qkv_l + (size_t)b * N_ * 3072 + h * 64;

    uint32_t qfh[4][4], qfl[4][4];
    load_q_frags(baseh, basel, 3072, q0, smp, sb, qfh, qfl, t, lane, w);

    float oacc[8][4];
#pragma unroll
    for (int dt = 0; dt < 8; dt++)
#pragma unroll
        for (int q = 0; q < 4; q++) oacc[dt][q] = 0.f;
    float m0 = -1e30f, m1 = -1e30f, l0 = 0.f, l1 = 0.f;

    attn_segment_mma(baseh + 1024, basel + 1024, baseh + 2048, basel + 2048,
                     3072, N_, smp, sb, qfh, qfl, oacc, m0, m1, l0, l1, t, lane);

    float inv0 = 1.f / l0, inv1 = 1.f / l1;
    int r0 = q0 + w * 16 + (lane >> 2);
    int cb = h * 64 + (lane & 3) * 2;
#pragma unroll
    for (int dt = 0; dt < 8; dt++) {
        *(float2*)&out[(size_t)(b * N_ + r0) * D_ + cb + dt * 8] =
            make_float2(oacc[dt][0] * inv0, oacc[dt][1] * inv0);
        *(float2*)&out[(size_t)(b * N_ + r0 + 8) * D_ + cb + dt * 8] =
            make_float2(oacc[dt][2] * inv1, oacc[dt][3] * inv1);
    }
}

__global__ __launch_bounds__(256) void attn_cross_mma(
    const __nv_bfloat16* __restrict__ kv_h, const __nv_bfloat16* __restrict__ kv_l,
    const __nv_bfloat16* __restrict__ qq_h, const __nv_bfloat16* __restrict__ qq_l,
    const float* __restrict__ gate, float* __restrict__ out)
{
    __shared__ __align__(16) char smp[36864];
    const uint32_t sb = smem_u32(smp);
    const int t = threadIdx.x, lane = t & 31, w = t >> 5;
    const int bh = blockIdx.x, b = bh >> 4, h = bh & 15;
    const int q0 = blockIdx.y * 128;

    const __nv_bfloat16* qbh = qq_h + (size_t)b * QN_ * 3072 + h * 64;
    const __nv_bfloat16* qbl = qq_l + (size_t)b * QN_ * 3072 + h * 64;
    const __nv_bfloat16* kbh = kv_h + (size_t)b * N_ * 2048 + h * 64;
    const __nv_bfloat16* kbl = kv_l + (size_t)b * N_ * 2048 + h * 64;

    uint32_t qfh[4][4], qfl[4][4];
    load_q_frags(qbh, qbl, 3072, q0, smp, sb, qfh, qfl, t, lane, w);

    float oacc[8][4];
#pragma unroll
    for (int dt = 0; dt < 8; dt++)
#pragma unroll
        for (int q = 0; q < 4; q++) oacc[dt][q] = 0.f;
    float m0 = -1e30f, m1 = -1e30f, l0 = 0.f, l1 = 0.f;

    // segment A: keys/values from x (gated)
    attn_segment_mma(kbh, kbl, kbh + 1024, kbl + 1024,
                     2048, N_, smp, sb, qfh, qfl, oacc, m0, m1, l0, l1, t, lane);

    const float g = tanhf(gate[h]);
    float gi0 = g / l0, gi1 = g / l1;
    int r0 = q0 + w * 16 + (lane >> 2);
    int cb = h * 64 + (lane & 3) * 2;
#pragma unroll
    for (int dt = 0; dt < 8; dt++) {
        *(float2*)&out[(size_t)(b * QN_ + r0) * D_ + cb + dt * 8] =
            make_float2(oacc[dt][0] * gi0, oacc[dt][1] * gi0);
        *(float2*)&out[(size_t)(b * QN_ + r0 + 8) * D_ + cb + dt * 8] =
            make_float2(oacc[dt][2] * gi1, oacc[dt][3] * gi1);
        oacc[dt][0] = oacc[dt][1] = oacc[dt][2] = oacc[dt][3] = 0.f;
    }
    m0 = -1e30f; m1 = -1e30f; l0 = 0.f; l1 = 0.f;

    // segment B: keys/values from query stream
    attn_segment_mma(qbh + 1024, qbl + 1024, qbh + 2048, qbl + 2048,
                     3072, QN_, smp, sb, qfh, qfl, oacc, m0, m1, l0, l1, t, lane);

    float inv0 = 1.f / l0, inv1 = 1.f / l1;
#pragma unroll
    for (int dt = 0; dt < 8; dt++) {
        float2 p0 = *(float2*)&out[(size_t)(b * QN_ + r0) * D_ + cb + dt * 8];
        float2 p1 = *(float2*)&out[(size_t)(b * QN_ + r0 + 8) * D_ + cb + dt * 8];
        p0.x += oacc[dt][0] * inv0; p0.y += oacc[dt][1] * inv0;
        p1.x += oacc[dt][2] * inv1; p1.y += oacc[dt][3] * inv1;
        *(float2*)&out[(size_t)(b * QN_ + r0) * D_ + cb + dt * 8] = p0;
        *(float2*)&out[(size_t)(b * QN_ + r0 + 8) * D_ + cb + dt * 8] = p1;
    }
}

// ======================= low_res scramble + 64x64 proj =======================
__global__ void lr_kernel(const float* __restrict__ low_res,
                          const float* __restrict__ W,
                          const float* __restrict__ bias,
                          float* __restrict__ out)
{
    __shared__ float xin[64];
    const int row = blockIdx.x;
    const int b = row >> 8;
    const int i = row & 255;
    const int t = threadIdx.x;
    {
        int f = i * 64 + t;
        xin[t] = low_res[(size_t)b * (LN_ * LD_) + (f & 255) * 64 + (f >> 8)];
    }
    __syncthreads();
    float s = bias[t];
#pragma unroll 8
    for (int c = 0; c < 64; c++)
        s = fmaf(xin[c], W[c * 64 + t], s);
    out[(size_t)row * 64 + t] = s;
}

// ======================= launch =======================
extern "C" void kernel_launch(void* const* d_in, const int* in_sizes, int n_in,
                              void* d_out, int out_size)
{
    const float* x        = (const float*)d_in[0];
    const float* query    = (const float*)d_in[1];
    const float* low_res  = (const float*)d_in[2];
    const float* W_qkv    = (const float*)d_in[3];
    const float* W_xkv    = (const float*)d_in[4];
    const float* W_qlin   = (const float*)d_in[5];
    const float* gate     = (const float*)d_in[6];
    const float* W_proj   = (const float*)d_in[7];
    const float* b_proj   = (const float*)d_in[8];
    const float* W_qproj  = (const float*)d_in[9];
    const float* b_qproj  = (const float*)d_in[10];
    const float* W_lrproj = (const float*)d_in[11];
    const float* b_lrproj = (const float*)d_in[12];

    float *xattn, *qattn;
    __nv_bfloat16 *wh, *wl, *qkvh, *qkvl, *kvh, *kvl, *qqh, *qql;
    cudaGetSymbolAddress((void**)&xattn, g_xattn);
    cudaGetSymbolAddress((void**)&qattn, g_qattn);
    cudaGetSymbolAddress((void**)&wh,    g_wt_hi);
    cudaGetSymbolAddress((void**)&wl,    g_wt_lo);
    cudaGetSymbolAddress((void**)&qkvh,  g_qkv_h);
    cudaGetSymbolAddress((void**)&qkvl,  g_qkv_l);
    cudaGetSymbolAddress((void**)&kvh,   g_kv_h);
    cudaGetSymbolAddress((void**)&kvl,   g_kv_l);
    cudaGetSymbolAddress((void**)&qqh,   g_qqkv_h);
    cudaGetSymbolAddress((void**)&qql,   g_qqkv_l);

    float* out   = (float*)d_out;
    float* x_out = out;
    float* q_out = out + (size_t)B_ * N_ * D_;
    float* l_out = q_out + (size_t)B_ * QN_ * D_;

    const dim3 blk(256);

    // weight transpose + split
    wsplit_kernel<<<dim3(3072 / 32, 32), blk>>>(W_qkv,   wh + WOFF_QKV,   wl + WOFF_QKV,   3072);
    wsplit_kernel<<<dim3(2048 / 32, 32), blk>>>(W_xkv,   wh + WOFF_XKV,   wl + WOFF_XKV,   2048);
    wsplit_kernel<<<dim3(3072 / 32, 32), blk>>>(W_qlin,  wh + WOFF_QLIN,  wl + WOFF_QLIN,  3072);
    wsplit_kernel<<<dim3(1024 / 32, 32), blk>>>(W_proj,  wh + WOFF_PROJ,  wl + WOFF_PROJ,  1024);
    wsplit_kernel<<<dim3(1024 / 32, 32), blk>>>(W_qproj, wh + WOFF_QPROJ, wl + WOFF_QPROJ, 1024);

    // input projections -> split bf16 outputs for attention
    gemm_mma<<<dim3(3072 / 128, 4096 / 128), blk>>>(
        x, wh + WOFF_QKV, wl + WOFF_QKV, nullptr, nullptr, qkvh, qkvl, 4096, 3072, 1024);
    gemm_mma<<<dim3(2048 / 128, 4096 / 128), blk>>>(
        x, wh + WOFF_XKV, wl + WOFF_XKV, nullptr, nullptr, kvh, kvl, 4096, 2048, 1024);
    gemm_mma<<<dim3(3072 / 128, 1024 / 128), blk>>>(
        query, wh + WOFF_QLIN, wl + WOFF_QLIN, nullptr, nullptr, qqh, qql, 1024, 3072, 1024);

    // attention (HMMA, split-bf16)
    attn_self_mma<<<dim3(B_ * H_, N_ / 128), blk>>>(qkvh, qkvl, xattn);
    attn_cross_mma<<<dim3(B_ * H_, QN_ / 128), blk>>>(kvh, kvl, qqh, qql, gate, qattn);

    // output projections (fp32 out + bias)
    gemm_mma<<<dim3(1024 / 128, 4096 / 128), blk>>>(
        xattn, wh + WOFF_PROJ, wl + WOFF_PROJ, b_proj, x_out, nullptr, nullptr, 4096, 1024, 1024);
    gemm_mma<<<dim3(1024 / 128, 1024 / 128), blk>>>(
        qattn, wh + WOFF_QPROJ, wl + WOFF_QPROJ, b_qproj, q_out, nullptr, nullptr, 1024, 1024, 1024);

    // low_res branch
    lr_kernel<<<B_ * LN_, 64>>>(low_res, W_lrproj, b_lrproj, l_out);
}

// round 6
// speedup vs baseline: 2.6677x; 1.0859x over previous
#include <cuda_runtime.h>
#include <cuda_bf16.h>
#include <math.h>
#include <stdint.h>

#define B_  2
#define N_  2048
#define QN_ 512
#define D_  1024
#define H_  16
#define LN_ 256
#define LD_ 64

// ======================= helpers =======================
__device__ __forceinline__ uint32_t smem_u32(const void* p) {
    uint32_t a;
    asm("{ .reg .u64 t; cvta.to.shared.u64 t, %1; cvt.u32.u64 %0, t; }" : "=r"(a) : "l"(p));
    return a;
}
__device__ __forceinline__ void ldsm_x4(uint32_t* r, uint32_t addr) {
    asm volatile("ldmatrix.sync.aligned.m8n8.x4.shared.b16 {%0,%1,%2,%3}, [%4];"
                 : "=r"(r[0]), "=r"(r[1]), "=r"(r[2]), "=r"(r[3]) : "r"(addr));
}
__device__ __forceinline__ void ldsm_x4_t(uint32_t* r, uint32_t addr) {
    asm volatile("ldmatrix.sync.aligned.m8n8.x4.trans.shared.b16 {%0,%1,%2,%3}, [%4];"
                 : "=r"(r[0]), "=r"(r[1]), "=r"(r[2]), "=r"(r[3]) : "r"(addr));
}
__device__ __forceinline__ void mma_bf16(float* d, const uint32_t* a, const uint32_t* b) {
    asm volatile(
        "mma.sync.aligned.m16n8k16.row.col.f32.bf16.bf16.f32 "
        "{%0,%1,%2,%3}, {%4,%5,%6,%7}, {%8,%9}, {%0,%1,%2,%3};"
        : "+f"(d[0]), "+f"(d[1]), "+f"(d[2]), "+f"(d[3])
        : "r"(a[0]), "r"(a[1]), "r"(a[2]), "r"(a[3]), "r"(b[0]), "r"(b[1]));
}
__device__ __forceinline__ uint32_t pack_bf2(__nv_bfloat16 a, __nv_bfloat16 b) {
    __nv_bfloat162 t; t.x = a; t.y = b;
    return *reinterpret_cast<uint32_t*>(&t);
}
__device__ __forceinline__ void split2(float x, float y, uint32_t& hi, uint32_t& lo) {
    __nv_bfloat16 hx = __float2bfloat16(x), hy = __float2bfloat16(y);
    __nv_bfloat16 lx = __float2bfloat16(x - __bfloat162float(hx));
    __nv_bfloat16 ly = __float2bfloat16(y - __bfloat162float(hy));
    hi = pack_bf2(hx, hy);
    lo = pack_bf2(lx, ly);
}
#define CP_ASYNC16(dst, src) \
    asm volatile("cp.async.cg.shared.global [%0], [%1], 16;" :: "r"(dst), "l"(src))
#define CP_COMMIT() asm volatile("cp.async.commit_group;" ::: "memory")
#define CP_WAIT1() asm volatile("cp.async.wait_group 1;" ::: "memory")
#define CP_WAIT0() asm volatile("cp.async.wait_group 0;" ::: "memory")

// ======================= scratch =======================
__device__ __nv_bfloat16 g_qkv_h [B_*N_*3*D_],  g_qkv_l [B_*N_*3*D_];
__device__ __nv_bfloat16 g_kv_h  [B_*N_*2*D_],  g_kv_l  [B_*N_*2*D_];
__device__ __nv_bfloat16 g_qqkv_h[B_*QN_*3*D_], g_qqkv_l[B_*QN_*3*D_];
__device__ __nv_bfloat16 g_x_h   [B_*N_*D_],    g_x_l   [B_*N_*D_];
__device__ __nv_bfloat16 g_q_h   [B_*QN_*D_],   g_q_l   [B_*QN_*D_];
__device__ __nv_bfloat16 g_xat_h [B_*N_*D_],    g_xat_l [B_*N_*D_];
__device__ __nv_bfloat16 g_qat_h [B_*QN_*D_],   g_qat_l [B_*QN_*D_];
__device__ float g_park[B_*QN_*D_];   // cross-attn segment-A fp32 parking
#define WT_TOTAL 10485760
__device__ __nv_bfloat16 g_wt_hi[WT_TOTAL];
__device__ __nv_bfloat16 g_wt_lo[WT_TOTAL];
#define WOFF_QKV   0
#define WOFF_XKV   (3072*1024)
#define WOFF_QLIN  (WOFF_XKV + 2048*1024)
#define WOFF_PROJ  (WOFF_QLIN + 3072*1024)
#define WOFF_QPROJ (WOFF_PROJ + 1024*1024)

// ============ weight transpose + bf16 split ============
__global__ __launch_bounds__(256) void wsplit_kernel(
    const float* __restrict__ W, __nv_bfloat16* __restrict__ Whi,
    __nv_bfloat16* __restrict__ Wlo, int N)
{
    __shared__ float ts[32][33];
    const int n0 = blockIdx.x * 32, k0 = blockIdx.y * 32;
    const int tx = threadIdx.x & 31, ty = threadIdx.x >> 5;
#pragma unroll
    for (int i = 0; i < 4; i++) {
        int k = k0 + ty + i * 8;
        ts[ty + i * 8][tx] = W[(size_t)k * N + n0 + tx];
    }
    __syncthreads();
#pragma unroll
    for (int i = 0; i < 4; i++) {
        int n = n0 + ty + i * 8;
        float v = ts[tx][ty + i * 8];
        __nv_bfloat16 h = __float2bfloat16(v);
        Whi[(size_t)n * 1024 + k0 + tx] = h;
        Wlo[(size_t)n * 1024 + k0 + tx] = __float2bfloat16(v - __bfloat162float(h));
    }
}

// ============ activation split: fp32 [M][K] -> bf16 hi/lo same layout ============
__global__ __launch_bounds__(256) void asplit_kernel(
    const float* __restrict__ A, __nv_bfloat16* __restrict__ Ah,
    __nv_bfloat16* __restrict__ Al)
{
    int i = blockIdx.x * 256 + threadIdx.x;
    float4 v = ((const float4*)A)[i];
    uint32_t h0, l0, h1, l1;
    split2(v.x, v.y, h0, l0);
    split2(v.z, v.w, h1, l1);
    ((uint2*)Ah)[i] = make_uint2(h0, h1);
    ((uint2*)Al)[i] = make_uint2(l0, l1);
}

// ============ split-bf16 HMMA GEMM, cp.async double-buffered ============
// Ah/Al bf16 [M][K]; Bh/Bl bf16 [N][K]. Output fp32 C(+bias) or split Chi/Clo.
#define PITCH 80
#define STG_BYTES 40960   // 4 buffers x 128 x 80
#define OFS_AH 0
#define OFS_AL 10240
#define OFS_BH 20480
#define OFS_BL 30720
#define GSMEM (2 * STG_BYTES)
__global__ __launch_bounds__(256, 2) void gemm_mma(
    const __nv_bfloat16* __restrict__ Ah, const __nv_bfloat16* __restrict__ Al,
    const __nv_bfloat16* __restrict__ Bh, const __nv_bfloat16* __restrict__ Bl,
    const float* __restrict__ bias, float* __restrict__ C,
    __nv_bfloat16* __restrict__ Chi, __nv_bfloat16* __restrict__ Clo,
    int M, int N, int K)
{
    extern __shared__ __align__(16) char dsm[];
    const uint32_t sb0 = smem_u32(dsm);
    const int t = threadIdx.x;
    const int lane = t & 31;
    const int w = t >> 5;
    const int wm = w & 3, wn = w >> 2;
    const int bm = blockIdx.y * 128, bn = blockIdx.x * 128;

    float acc[2][8][4];
#pragma unroll
    for (int mf = 0; mf < 2; mf++)
#pragma unroll
        for (int nf = 0; nf < 8; nf++)
#pragma unroll
            for (int q = 0; q < 4; q++) acc[mf][nf][q] = 0.f;

    const int ns = K >> 5;   // stages of 32

    // per-thread copy coords: f in [0,512): row = f>>2, c8 = (f&3)*8 (16B)
    auto prefetch = [&](int s, int buf) {
        const uint32_t base = sb0 + buf * STG_BYTES;
        const int k0 = s << 5;
#pragma unroll
        for (int i = 0; i < 2; i++) {
            int f = t + i * 256;
            int row = f >> 2, c8 = (f & 3) << 3;
            size_t goA = (size_t)(bm + row) * K + k0 + c8;
            size_t goB = (size_t)(bn + row) * K + k0 + c8;
            uint32_t so = (uint32_t)(row * PITCH + c8 * 2);
            CP_ASYNC16(base + OFS_AH + so, Ah + goA);
            CP_ASYNC16(base + OFS_AL + so, Al + goA);
            CP_ASYNC16(base + OFS_BH + so, Bh + goB);
            CP_ASYNC16(base + OFS_BL + so, Bl + goB);
        }
        CP_COMMIT();
    };

    prefetch(0, 0);
    int buf = 0;
    for (int s = 0; s < ns; s++) {
        if (s + 1 < ns) {
            prefetch(s + 1, buf ^ 1);
            CP_WAIT1();
        } else {
            CP_WAIT0();
        }
        __syncthreads();

        const uint32_t sb = sb0 + buf * STG_BYTES;
#pragma unroll
        for (int ks = 0; ks < 2; ks++) {
            uint32_t ah[2][4], al[2][4];
#pragma unroll
            for (int mf = 0; mf < 2; mf++) {
                uint32_t addr = sb + OFS_AH +
                    (uint32_t)((wm * 32 + mf * 16 + (lane & 15)) * PITCH +
                               ks * 32 + (lane >> 4) * 16);
                ldsm_x4(ah[mf], addr);
                ldsm_x4(al[mf], addr + (OFS_AL - OFS_AH));
            }
#pragma unroll
            for (int p = 0; p < 4; p++) {
                int g = lane >> 3;
                uint32_t baddr = sb + OFS_BH +
                    (uint32_t)((wn * 64 + (p * 2 + (g >> 1)) * 8 + (lane & 7)) * PITCH +
                               ks * 32 + (g & 1) * 16);
                uint32_t bh[4], bl[4];
                ldsm_x4(bh, baddr);
                ldsm_x4(bl, baddr + (OFS_BL - OFS_BH));
#pragma unroll
                for (int mf = 0; mf < 2; mf++) {
                    mma_bf16(acc[mf][p * 2 + 0], ah[mf], &bh[0]);
                    mma_bf16(acc[mf][p * 2 + 0], ah[mf], &bl[0]);
                    mma_bf16(acc[mf][p * 2 + 0], al[mf], &bh[0]);
                    mma_bf16(acc[mf][p * 2 + 1], ah[mf], &bh[2]);
                    mma_bf16(acc[mf][p * 2 + 1], ah[mf], &bl[2]);
                    mma_bf16(acc[mf][p * 2 + 1], al[mf], &bh[2]);
                }
            }
        }
        __syncthreads();   // all reads of buf done before stage s+2 prefetch overwrites it
        buf ^= 1;
    }

#pragma unroll
    for (int mf = 0; mf < 2; mf++) {
        int m = bm + wm * 32 + mf * 16 + (lane >> 2);
#pragma unroll
        for (int nf = 0; nf < 8; nf++) {
            int n = bn + wn * 64 + nf * 8 + (lane & 3) * 2;
            if (Chi) {
                uint32_t h0, l0, h1, l1;
                split2(acc[mf][nf][0], acc[mf][nf][1], h0, l0);
                split2(acc[mf][nf][2], acc[mf][nf][3], h1, l1);
                *(uint32_t*)&Chi[(size_t)m * N + n] = h0;
                *(uint32_t*)&Clo[(size_t)m * N + n] = l0;
                *(uint32_t*)&Chi[(size_t)(m + 8) * N + n] = h1;
                *(uint32_t*)&Clo[(size_t)(m + 8) * N + n] = l1;
            } else {
                float2 v0 = make_float2(acc[mf][nf][0], acc[mf][nf][1]);
                float2 v1 = make_float2(acc[mf][nf][2], acc[mf][nf][3]);
                if (bias) {
                    float2 bv = *(const float2*)&bias[n];
                    v0.x += bv.x; v0.y += bv.y;
                    v1.x += bv.x; v1.y += bv.y;
                }
                *(float2*)&C[(size_t)m * N + n] = v0;
                *(float2*)&C[(size_t)(m + 8) * N + n] = v1;
            }
        }
    }
}

// ======================= HMMA flash attention =======================
#define APITCH 144
#define AKH 0
#define AKL 9216
#define AVH 18432
#define AVL 27648

__device__ __forceinline__ void attn_segment_mma(
    const __nv_bfloat16* __restrict__ Kh, const __nv_bfloat16* __restrict__ Kl,
    const __nv_bfloat16* __restrict__ Vh, const __nv_bfloat16* __restrict__ Vl,
    int rstride, int nkeys, char* smp, uint32_t sb,
    const uint32_t (&qfh)[4][4], const uint32_t (&qfl)[4][4],
    float (&oacc)[8][4], float& m0, float& m1, float& l0, float& l1,
    int t, int lane)
{
    for (int k0 = 0; k0 < nkeys; k0 += 64) {
        __syncthreads();
#pragma unroll
        for (int i = 0; i < 4; i++) {
            int f = t + i * 256;
            int row = f >> 4, c8 = f & 15;
            size_t go = (size_t)(k0 + row) * rstride + c8 * 4;
            uint32_t so = (uint32_t)(row * APITCH + c8 * 8);
            *(uint2*)(smp + AKH + so) = *(const uint2*)&Kh[go];
            *(uint2*)(smp + AKL + so) = *(const uint2*)&Kl[go];
            *(uint2*)(smp + AVH + so) = *(const uint2*)&Vh[go];
            *(uint2*)(smp + AVL + so) = *(const uint2*)&Vl[go];
        }
        __syncthreads();

        float sacc[8][4];
#pragma unroll
        for (int nt = 0; nt < 8; nt++)
#pragma unroll
            for (int q = 0; q < 4; q++) sacc[nt][q] = 0.f;

#pragma unroll
        for (int kc = 0; kc < 4; kc++) {
#pragma unroll
            for (int ntp = 0; ntp < 4; ntp++) {
                uint32_t baddr = sb + AKH +
                    (uint32_t)((ntp * 16 + (lane & 7) + ((lane >> 4)) * 8) * APITCH +
                               kc * 32 + ((lane >> 3) & 1) * 16);
                uint32_t bh4[4], bl4[4];
                ldsm_x4(bh4, baddr);
                ldsm_x4(bl4, baddr + (AKL - AKH));
                mma_bf16(sacc[ntp * 2 + 0], qfh[kc], &bh4[0]);
                mma_bf16(sacc[ntp * 2 + 0], qfh[kc], &bl4[0]);
                mma_bf16(sacc[ntp * 2 + 0], qfl[kc], &bh4[0]);
                mma_bf16(sacc[ntp * 2 + 1], qfh[kc], &bh4[2]);
                mma_bf16(sacc[ntp * 2 + 1], qfh[kc], &bl4[2]);
                mma_bf16(sacc[ntp * 2 + 1], qfl[kc], &bh4[2]);
            }
        }

        float mx0 = -1e30f, mx1 = -1e30f;
#pragma unroll
        for (int nt = 0; nt < 8; nt++) {
            mx0 = fmaxf(mx0, fmaxf(sacc[nt][0], sacc[nt][1]));
            mx1 = fmaxf(mx1, fmaxf(sacc[nt][2], sacc[nt][3]));
        }
        mx0 = fmaxf(mx0, __shfl_xor_sync(0xffffffffu, mx0, 1));
        mx0 = fmaxf(mx0, __shfl_xor_sync(0xffffffffu, mx0, 2));
        mx1 = fmaxf(mx1, __shfl_xor_sync(0xffffffffu, mx1, 1));
        mx1 = fmaxf(mx1, __shfl_xor_sync(0xffffffffu, mx1, 2));
        float mn0 = fmaxf(m0, mx0), mn1 = fmaxf(m1, mx1);
        float a0 = __expf(m0 - mn0), a1 = __expf(m1 - mn1);
        m0 = mn0; m1 = mn1;
        float rs0 = 0.f, rs1 = 0.f;
#pragma unroll
        for (int nt = 0; nt < 8; nt++) {
            sacc[nt][0] = __expf(sacc[nt][0] - mn0);
            sacc[nt][1] = __expf(sacc[nt][1] - mn0);
            sacc[nt][2] = __expf(sacc[nt][2] - mn1);
            sacc[nt][3] = __expf(sacc[nt][3] - mn1);
            rs0 += sacc[nt][0] + sacc[nt][1];
            rs1 += sacc[nt][2] + sacc[nt][3];
        }
        rs0 += __shfl_xor_sync(0xffffffffu, rs0, 1);
        rs0 += __shfl_xor_sync(0xffffffffu, rs0, 2);
        rs1 += __shfl_xor_sync(0xffffffffu, rs1, 1);
        rs1 += __shfl_xor_sync(0xffffffffu, rs1, 2);
        l0 = l0 * a0 + rs0;
        l1 = l1 * a1 + rs1;
#pragma unroll
        for (int dt = 0; dt < 8; dt++) {
            oacc[dt][0] *= a0; oacc[dt][1] *= a0;
            oacc[dt][2] *= a1; oacc[dt][3] *= a1;
        }

#pragma unroll
        for (int kc = 0; kc < 4; kc++) {
            uint32_t ph[4], pl[4];
            split2(sacc[2 * kc][0], sacc[2 * kc][1], ph[0], pl[0]);
            split2(sacc[2 * kc][2], sacc[2 * kc][3], ph[1], pl[1]);
            split2(sacc[2 * kc + 1][0], sacc[2 * kc + 1][1], ph[2], pl[2]);
            split2(sacc[2 * kc + 1][2], sacc[2 * kc + 1][3], ph[3], pl[3]);
#pragma unroll
            for (int dp = 0; dp < 4; dp++) {
                uint32_t vaddr = sb + AVH +
                    (uint32_t)((kc * 16 + (lane & 7) + ((lane >> 3) & 1) * 8) * APITCH +
                               (dp * 16 + (lane >> 4) * 8) * 2);
                uint32_t vh4[4], vl4[4];
                ldsm_x4_t(vh4, vaddr);
                ldsm_x4_t(vl4, vaddr + (AVL - AVH));
                mma_bf16(oacc[dp * 2 + 0], ph, &vh4[0]);
                mma_bf16(oacc[dp * 2 + 0], ph, &vl4[0]);
                mma_bf16(oacc[dp * 2 + 0], pl, &vh4[0]);
                mma_bf16(oacc[dp * 2 + 1], ph, &vh4[2]);
                mma_bf16(oacc[dp * 2 + 1], ph, &vl4[2]);
                mma_bf16(oacc[dp * 2 + 1], pl, &vh4[2]);
            }
        }
    }
}

__device__ __forceinline__ void load_q_frags(
    const __nv_bfloat16* __restrict__ Qh, const __nv_bfloat16* __restrict__ Ql,
    int rstride, int q0, char* smp, uint32_t sb,
    uint32_t (&qfh)[4][4], uint32_t (&qfl)[4][4], int t, int lane, int w)
{
    const __nv_bfloat162 sc = __floats2bfloat162_rn(0.125f, 0.125f);
#pragma unroll
    for (int i = 0; i < 8; i++) {
        int f = t + i * 256;
        int row = f >> 4, c8 = f & 15;
        size_t go = (size_t)(q0 + row) * rstride + c8 * 4;
        uint32_t so = (uint32_t)(row * APITCH + c8 * 8);
        uint2 vh = *(const uint2*)&Qh[go];
        uint2 vl = *(const uint2*)&Ql[go];
        __nv_bfloat162* ph = (__nv_bfloat162*)&vh;
        __nv_bfloat162* pL = (__nv_bfloat162*)&vl;
        ph[0] = __hmul2(ph[0], sc); ph[1] = __hmul2(ph[1], sc);
        pL[0] = __hmul2(pL[0], sc); pL[1] = __hmul2(pL[1], sc);
        *(uint2*)(smp + so) = vh;
        *(uint2*)(smp + 18432 + so) = vl;
    }
    __syncthreads();
#pragma unroll
    for (int kc = 0; kc < 4; kc++) {
        uint32_t addr = sb + (uint32_t)((w * 16 + (lane & 15)) * APITCH +
                                        kc * 32 + (lane >> 4) * 16);
        ldsm_x4(qfh[kc], addr);
        ldsm_x4(qfl[kc], addr + 18432);
    }
}

__global__ __launch_bounds__(256) void attn_self_mma(
    const __nv_bfloat16* __restrict__ qkv_h, const __nv_bfloat16* __restrict__ qkv_l,
    __nv_bfloat16* __restrict__ oh, __nv_bfloat16* __restrict__ ol)
{
    __shared__ __align__(16) char smp[36864];
    const uint32_t sb = smem_u32(smp);
    const int t = threadIdx.x, lane = t & 31, w = t >> 5;
    const int bh = blockIdx.x, b = bh >> 4, h = bh & 15;
    const int q0 = blockIdx.y * 128;

    const __nv_bfloat16* baseh = qkv_h + (size_t)b * N_ * 3072 + h * 64;
    const __nv_bfloat16* basel = qkv_l + (size_t)b * N_ * 3072 + h * 64;

    uint32_t qfh[4][4], qfl[4][4];
    load_q_frags(baseh, basel, 3072, q0, smp, sb, qfh, qfl, t, lane, w);

    float oacc[8][4];
#pragma unroll
    for (int dt = 0; dt < 8; dt++)
#pragma unroll
        for (int q = 0; q < 4; q++) oacc[dt][q] = 0.f;
    float m0 = -1e30f, m1 = -1e30f, l0 = 0.f, l1 = 0.f;

    attn_segment_mma(baseh + 1024, basel + 1024, baseh + 2048, basel + 2048,
                     3072, N_, smp, sb, qfh, qfl, oacc, m0, m1, l0, l1, t, lane);

    float inv0 = 1.f / l0, inv1 = 1.f / l1;
    int r0 = q0 + w * 16 + (lane >> 2);
    int cb = h * 64 + (lane & 3) * 2;
#pragma unroll
    for (int dt = 0; dt < 8; dt++) {
        uint32_t h0, lo0, h1, lo1;
        split2(oacc[dt][0] * inv0, oacc[dt][1] * inv0, h0, lo0);
        split2(oacc[dt][2] * inv1, oacc[dt][3] * inv1, h1, lo1);
        size_t o0 = (size_t)(b * N_ + r0) * D_ + cb + dt * 8;
        size_t o1 = (size_t)(b * N_ + r0 + 8) * D_ + cb + dt * 8;
        *(uint32_t*)&oh[o0] = h0; *(uint32_t*)&ol[o0] = lo0;
        *(uint32_t*)&oh[o1] = h1; *(uint32_t*)&ol[o1] = lo1;
    }
}

__global__ __launch_bounds__(256) void attn_cross_mma(
    const __nv_bfloat16* __restrict__ kv_h, const __nv_bfloat16* __restrict__ kv_l,
    const __nv_bfloat16* __restrict__ qq_h, const __nv_bfloat16* __restrict__ qq_l,
    const float* __restrict__ gate, float* __restrict__ park,
    __nv_bfloat16* __restrict__ oh, __nv_bfloat16* __restrict__ ol)
{
    __shared__ __align__(16) char smp[36864];
    const uint32_t sb = smem_u32(smp);
    const int t = threadIdx.x, lane = t & 31, w = t >> 5;
    const int bh = blockIdx.x, b = bh >> 4, h = bh & 15;
    const int q0 = blockIdx.y * 128;

    const __nv_bfloat16* qbh = qq_h + (size_t)b * QN_ * 3072 + h * 64;
    const __nv_bfloat16* qbl = qq_l + (size_t)b * QN_ * 3072 + h * 64;
    const __nv_bfloat16* kbh = kv_h + (size_t)b * N_ * 2048 + h * 64;
    const __nv_bfloat16* kbl = kv_l + (size_t)b * N_ * 2048 + h * 64;

    uint32_t qfh[4][4], qfl[4][4];
    load_q_frags(qbh, qbl, 3072, q0, smp, sb, qfh, qfl, t, lane, w);

    float oacc[8][4];
#pragma unroll
    for (int dt = 0; dt < 8; dt++)
#pragma unroll
        for (int q = 0; q < 4; q++) oacc[dt][q] = 0.f;
    float m0 = -1e30f, m1 = -1e30f, l0 = 0.f, l1 = 0.f;

    attn_segment_mma(kbh, kbl, kbh + 1024, kbl + 1024,
                     2048, N_, smp, sb, qfh, qfl, oacc, m0, m1, l0, l1, t, lane);

    const float g = tanhf(gate[h]);
    float gi0 = g / l0, gi1 = g / l1;
    int r0 = q0 + w * 16 + (lane >> 2);
    int cb = h * 64 + (lane & 3) * 2;
#pragma unroll
    for (int dt = 0; dt < 8; dt++) {
        *(float2*)&park[(size_t)(b * QN_ + r0) * D_ + cb + dt * 8] =
            make_float2(oacc[dt][0] * gi0, oacc[dt][1] * gi0);
        *(float2*)&park[(size_t)(b * QN_ + r0 + 8) * D_ + cb + dt * 8] =
            make_float2(oacc[dt][2] * gi1, oacc[dt][3] * gi1);
        oacc[dt][0] = oacc[dt][1] = oacc[dt][2] = oacc[dt][3] = 0.f;
    }
    m0 = -1e30f; m1 = -1e30f; l0 = 0.f; l1 = 0.f;

    attn_segment_mma(qbh + 1024, qbl + 1024, qbh + 2048, qbl + 2048,
                     3072, QN_, smp, sb, qfh, qfl, oacc, m0, m1, l0, l1, t, lane);

    float inv0 = 1.f / l0, inv1 = 1.f / l1;
#pragma unroll
    for (int dt = 0; dt < 8; dt++) {
        size_t o0 = (size_t)(b * QN_ + r0) * D_ + cb + dt * 8;
        size_t o1 = (size_t)(b * QN_ + r0 + 8) * D_ + cb + dt * 8;
        float2 p0 = *(float2*)&park[o0];
        float2 p1 = *(float2*)&park[o1];
        uint32_t h0, lo0, h1, lo1;
        split2(p0.x + oacc[dt][0] * inv0, p0.y + oacc[dt][1] * inv0, h0, lo0);
        split2(p1.x + oacc[dt][2] * inv1, p1.y + oacc[dt][3] * inv1, h1, lo1);
        *(uint32_t*)&oh[o0] = h0; *(uint32_t*)&ol[o0] = lo0;
        *(uint32_t*)&oh[o1] = h1; *(uint32_t*)&ol[o1] = lo1;
    }
}

// ======================= low_res scramble + 64x64 proj =======================
__global__ void lr_kernel(const float* __restrict__ low_res,
                          const float* __restrict__ W,
                          const float* __restrict__ bias,
                          float* __restrict__ out)
{
    __shared__ float xin[64];
    const int row = blockIdx.x;
    const int b = row >> 8;
    const int i = row & 255;
    const int t = threadIdx.x;
    {
        int f = i * 64 + t;
        xin[t] = low_res[(size_t)b * (LN_ * LD_) + (f & 255) * 64 + (f >> 8)];
    }
    __syncthreads();
    float s = bias[t];
#pragma unroll 8
    for (int c = 0; c < 64; c++)
        s = fmaf(xin[c], W[c * 64 + t], s);
    out[(size_t)row * 64 + t] = s;
}

// ======================= launch =======================
extern "C" void kernel_launch(void* const* d_in, const int* in_sizes, int n_in,
                              void* d_out, int out_size)
{
    const float* x        = (const float*)d_in[0];
    const float* query    = (const float*)d_in[1];
    const float* low_res  = (const float*)d_in[2];
    const float* W_qkv    = (const float*)d_in[3];
    const float* W_xkv    = (const float*)d_in[4];
    const float* W_qlin   = (const float*)d_in[5];
    const float* gate     = (const float*)d_in[6];
    const float* W_proj   = (const float*)d_in[7];
    const float* b_proj   = (const float*)d_in[8];
    const float* W_qproj  = (const float*)d_in[9];
    const float* b_qproj  = (const float*)d_in[10];
    const float* W_lrproj = (const float*)d_in[11];
    const float* b_lrproj = (const float*)d_in[12];

    __nv_bfloat16 *wh, *wl, *qkvh, *qkvl, *kvh, *kvl, *qqh, *qql;
    __nv_bfloat16 *xh, *xl, *qh, *ql, *xah, *xal, *qah, *qal;
    float* park;
    cudaGetSymbolAddress((void**)&wh,   g_wt_hi);
    cudaGetSymbolAddress((void**)&wl,   g_wt_lo);
    cudaGetSymbolAddress((void**)&qkvh, g_qkv_h);
    cudaGetSymbolAddress((void**)&qkvl, g_qkv_l);
    cudaGetSymbolAddress((void**)&kvh,  g_kv_h);
    cudaGetSymbolAddress((void**)&kvl,  g_kv_l);
    cudaGetSymbolAddress((void**)&qqh,  g_qqkv_h);
    cudaGetSymbolAddress((void**)&qql,  g_qqkv_l);
    cudaGetSymbolAddress((void**)&xh,   g_x_h);
    cudaGetSymbolAddress((void**)&xl,   g_x_l);
    cudaGetSymbolAddress((void**)&qh,   g_q_h);
    cudaGetSymbolAddress((void**)&ql,   g_q_l);
    cudaGetSymbolAddress((void**)&xah,  g_xat_h);
    cudaGetSymbolAddress((void**)&xal,  g_xat_l);
    cudaGetSymbolAddress((void**)&qah,  g_qat_h);
    cudaGetSymbolAddress((void**)&qal,  g_qat_l);
    cudaGetSymbolAddress((void**)&park, g_park);

    float* out   = (float*)d_out;
    float* x_out = out;
    float* q_out = out + (size_t)B_ * N_ * D_;
    float* l_out = q_out + (size_t)B_ * QN_ * D_;

    cudaFuncSetAttribute(gemm_mma, cudaFuncAttributeMaxDynamicSharedMemorySize, GSMEM);
    const dim3 blk(256);

    // weight transpose + split; activation split
    wsplit_kernel<<<dim3(3072 / 32, 32), blk>>>(W_qkv,   wh + WOFF_QKV,   wl + WOFF_QKV,   3072);
    wsplit_kernel<<<dim3(2048 / 32, 32), blk>>>(W_xkv,   wh + WOFF_XKV,   wl + WOFF_XKV,   2048);
    wsplit_kernel<<<dim3(3072 / 32, 32), blk>>>(W_qlin,  wh + WOFF_QLIN,  wl + WOFF_QLIN,  3072);
    wsplit_kernel<<<dim3(1024 / 32, 32), blk>>>(W_proj,  wh + WOFF_PROJ,  wl + WOFF_PROJ,  1024);
    wsplit_kernel<<<dim3(1024 / 32, 32), blk>>>(W_qproj, wh + WOFF_QPROJ, wl + WOFF_QPROJ, 1024);
    asplit_kernel<<<(B_ * N_ * D_ / 4) / 256, blk>>>(x, xh, xl);
    asplit_kernel<<<(B_ * QN_ * D_ / 4) / 256, blk>>>(query, qh, ql);

    // input projections -> split bf16 outputs
    gemm_mma<<<dim3(3072 / 128, 4096 / 128), blk, GSMEM>>>(
        xh, xl, wh + WOFF_QKV, wl + WOFF_QKV, nullptr, nullptr, qkvh, qkvl, 4096, 3072, 1024);
    gemm_mma<<<dim3(2048 / 128, 4096 / 128), blk, GSMEM>>>(
        xh, xl, wh + WOFF_XKV, wl + WOFF_XKV, nullptr, nullptr, kvh, kvl, 4096, 2048, 1024);
    gemm_mma<<<dim3(3072 / 128, 1024 / 128), blk, GSMEM>>>(
        qh, ql, wh + WOFF_QLIN, wl + WOFF_QLIN, nullptr, nullptr, qqh, qql, 1024, 3072, 1024);

    // attention (HMMA) -> split bf16 outputs
    attn_self_mma<<<dim3(B_ * H_, N_ / 128), blk>>>(qkvh, qkvl, xah, xal);
    attn_cross_mma<<<dim3(B_ * H_, QN_ / 128), blk>>>(kvh, kvl, qqh, qql, gate, park, qah, qal);

    // output projections (fp32 out + bias)
    gemm_mma<<<dim3(1024 / 128, 4096 / 128), blk, GSMEM>>>(
        xah, xal, wh + WOFF_PROJ, wl + WOFF_PROJ, b_proj, x_out, nullptr, nullptr, 4096, 1024, 1024);
    gemm_mma<<<dim3(1024 / 128, 1024 / 128), blk, GSMEM>>>(
        qah, qal, wh + WOFF_QPROJ, wl + WOFF_QPROJ, b_qproj, q_out, nullptr, nullptr, 1024, 1024, 1024);

    // low_res branch
    lr_kernel<<<B_ * LN_, 64>>>(low_res, W_lrproj, b_lrproj, l_out);
}

// round 7
// speedup vs baseline: 2.7838x; 1.0435x over previous
#include <cuda_runtime.h>
#include <cuda_bf16.h>
#include <math.h>
#include <stdint.h>

#define B_  2
#define N_  2048
#define QN_ 512
#define D_  1024
#define H_  16
#define LN_ 256
#define LD_ 64

// ======================= helpers =======================
__device__ __forceinline__ uint32_t smem_u32(const void* p) {
    uint32_t a;
    asm("{ .reg .u64 t; cvta.to.shared.u64 t, %1; cvt.u32.u64 %0, t; }" : "=r"(a) : "l"(p));
    return a;
}
__device__ __forceinline__ void ldsm_x4(uint32_t* r, uint32_t addr) {
    asm volatile("ldmatrix.sync.aligned.m8n8.x4.shared.b16 {%0,%1,%2,%3}, [%4];"
                 : "=r"(r[0]), "=r"(r[1]), "=r"(r[2]), "=r"(r[3]) : "r"(addr));
}
__device__ __forceinline__ void ldsm_x4_t(uint32_t* r, uint32_t addr) {
    asm volatile("ldmatrix.sync.aligned.m8n8.x4.trans.shared.b16 {%0,%1,%2,%3}, [%4];"
                 : "=r"(r[0]), "=r"(r[1]), "=r"(r[2]), "=r"(r[3]) : "r"(addr));
}
__device__ __forceinline__ void mma_bf16(float* d, const uint32_t* a, const uint32_t* b) {
    asm volatile(
        "mma.sync.aligned.m16n8k16.row.col.f32.bf16.bf16.f32 "
        "{%0,%1,%2,%3}, {%4,%5,%6,%7}, {%8,%9}, {%0,%1,%2,%3};"
        : "+f"(d[0]), "+f"(d[1]), "+f"(d[2]), "+f"(d[3])
        : "r"(a[0]), "r"(a[1]), "r"(a[2]), "r"(a[3]), "r"(b[0]), "r"(b[1]));
}
__device__ __forceinline__ uint32_t pack_bf2(__nv_bfloat16 a, __nv_bfloat16 b) {
    __nv_bfloat162 t; t.x = a; t.y = b;
    return *reinterpret_cast<uint32_t*>(&t);
}
__device__ __forceinline__ void split2(float x, float y, uint32_t& hi, uint32_t& lo) {
    __nv_bfloat16 hx = __float2bfloat16(x), hy = __float2bfloat16(y);
    __nv_bfloat16 lx = __float2bfloat16(x - __bfloat162float(hx));
    __nv_bfloat16 ly = __float2bfloat16(y - __bfloat162float(hy));
    hi = pack_bf2(hx, hy);
    lo = pack_bf2(lx, ly);
}
#define CP_ASYNC16(dst, src) \
    asm volatile("cp.async.cg.shared.global [%0], [%1], 16;" :: "r"(dst), "l"(src))
#define CP_COMMIT() asm volatile("cp.async.commit_group;" ::: "memory")
#define CP_WAIT1() asm volatile("cp.async.wait_group 1;" ::: "memory")
#define CP_WAIT0() asm volatile("cp.async.wait_group 0;" ::: "memory")

// ======================= scratch =======================
__device__ __nv_bfloat16 g_qkv_h [B_*N_*3*D_],  g_qkv_l [B_*N_*3*D_];
__device__ __nv_bfloat16 g_kv_h  [B_*N_*2*D_],  g_kv_l  [B_*N_*2*D_];
__device__ __nv_bfloat16 g_qqkv_h[B_*QN_*3*D_], g_qqkv_l[B_*QN_*3*D_];
__device__ __nv_bfloat16 g_x_h   [B_*N_*D_],    g_x_l   [B_*N_*D_];
__device__ __nv_bfloat16 g_q_h   [B_*QN_*D_],   g_q_l   [B_*QN_*D_];
__device__ __nv_bfloat16 g_xat_h [B_*N_*D_],    g_xat_l [B_*N_*D_];
__device__ __nv_bfloat16 g_qat_h [B_*QN_*D_],   g_qat_l [B_*QN_*D_];
__device__ float g_park[B_*QN_*D_];
#define WT_TOTAL 10485760
__device__ __nv_bfloat16 g_wt_hi[WT_TOTAL];
__device__ __nv_bfloat16 g_wt_lo[WT_TOTAL];
#define WOFF_QKV   0
#define WOFF_XKV   (3072*1024)
#define WOFF_QLIN  (WOFF_XKV + 2048*1024)
#define WOFF_PROJ  (WOFF_QLIN + 3072*1024)
#define WOFF_QPROJ (WOFF_PROJ + 1024*1024)

// ============ weight transpose + bf16 split ============
__global__ __launch_bounds__(256) void wsplit_kernel(
    const float* __restrict__ W, __nv_bfloat16* __restrict__ Whi,
    __nv_bfloat16* __restrict__ Wlo, int N)
{
    __shared__ float ts[32][33];
    const int n0 = blockIdx.x * 32, k0 = blockIdx.y * 32;
    const int tx = threadIdx.x & 31, ty = threadIdx.x >> 5;
#pragma unroll
    for (int i = 0; i < 4; i++) {
        int k = k0 + ty + i * 8;
        ts[ty + i * 8][tx] = W[(size_t)k * N + n0 + tx];
    }
    __syncthreads();
#pragma unroll
    for (int i = 0; i < 4; i++) {
        int n = n0 + ty + i * 8;
        float v = ts[tx][ty + i * 8];
        __nv_bfloat16 h = __float2bfloat16(v);
        Whi[(size_t)n * 1024 + k0 + tx] = h;
        Wlo[(size_t)n * 1024 + k0 + tx] = __float2bfloat16(v - __bfloat162float(h));
    }
}

// ============ activation split ============
__global__ __launch_bounds__(256) void asplit_kernel(
    const float* __restrict__ A, __nv_bfloat16* __restrict__ Ah,
    __nv_bfloat16* __restrict__ Al)
{
    int i = blockIdx.x * 256 + threadIdx.x;
    float4 v = ((const float4*)A)[i];
    uint32_t h0, l0, h1, l1;
    split2(v.x, v.y, h0, l0);
    split2(v.z, v.w, h1, l1);
    ((uint2*)Ah)[i] = make_uint2(h0, h1);
    ((uint2*)Al)[i] = make_uint2(l0, l1);
}

// ============ split-bf16 HMMA GEMM, cp.async double-buffered ============
#define PITCH 80
#define STG_BYTES 40960
#define OFS_AH 0
#define OFS_AL 10240
#define OFS_BH 20480
#define OFS_BL 30720
#define GSMEM (2 * STG_BYTES)
__global__ __launch_bounds__(256, 2) void gemm_mma(
    const __nv_bfloat16* __restrict__ Ah, const __nv_bfloat16* __restrict__ Al,
    const __nv_bfloat16* __restrict__ Bh, const __nv_bfloat16* __restrict__ Bl,
    const float* __restrict__ bias, float* __restrict__ C,
    __nv_bfloat16* __restrict__ Chi, __nv_bfloat16* __restrict__ Clo,
    int M, int N, int K)
{
    extern __shared__ __align__(16) char dsm[];
    const uint32_t sb0 = smem_u32(dsm);
    const int t = threadIdx.x;
    const int lane = t & 31;
    const int w = t >> 5;
    const int wm = w & 3, wn = w >> 2;
    const int bm = blockIdx.y * 128, bn = blockIdx.x * 128;

    float acc[2][8][4];
#pragma unroll
    for (int mf = 0; mf < 2; mf++)
#pragma unroll
        for (int nf = 0; nf < 8; nf++)
#pragma unroll
            for (int q = 0; q < 4; q++) acc[mf][nf][q] = 0.f;

    const int ns = K >> 5;

    auto prefetch = [&](int s, int buf) {
        const uint32_t base = sb0 + buf * STG_BYTES;
        const int k0 = s << 5;
#pragma unroll
        for (int i = 0; i < 2; i++) {
            int f = t + i * 256;
            int row = f >> 2, c8 = (f & 3) << 3;
            size_t goA = (size_t)(bm + row) * K + k0 + c8;
            size_t goB = (size_t)(bn + row) * K + k0 + c8;
            uint32_t so = (uint32_t)(row * PITCH + c8 * 2);
            CP_ASYNC16(base + OFS_AH + so, Ah + goA);
            CP_ASYNC16(base + OFS_AL + so, Al + goA);
            CP_ASYNC16(base + OFS_BH + so, Bh + goB);
            CP_ASYNC16(base + OFS_BL + so, Bl + goB);
        }
        CP_COMMIT();
    };

    prefetch(0, 0);
    int buf = 0;
    for (int s = 0; s < ns; s++) {
        if (s + 1 < ns) {
            prefetch(s + 1, buf ^ 1);
            CP_WAIT1();
        } else {
            CP_WAIT0();
        }
        __syncthreads();

        const uint32_t sb = sb0 + buf * STG_BYTES;
#pragma unroll
        for (int ks = 0; ks < 2; ks++) {
            uint32_t ah[2][4], al[2][4];
#pragma unroll
            for (int mf = 0; mf < 2; mf++) {
                uint32_t addr = sb + OFS_AH +
                    (uint32_t)((wm * 32 + mf * 16 + (lane & 15)) * PITCH +
                               ks * 32 + (lane >> 4) * 16);
                ldsm_x4(ah[mf], addr);
                ldsm_x4(al[mf], addr + (OFS_AL - OFS_AH));
            }
#pragma unroll
            for (int p = 0; p < 4; p++) {
                int g = lane >> 3;
                uint32_t baddr = sb + OFS_BH +
                    (uint32_t)((wn * 64 + (p * 2 + (g >> 1)) * 8 + (lane & 7)) * PITCH +
                               ks * 32 + (g & 1) * 16);
                uint32_t bh[4], bl[4];
                ldsm_x4(bh, baddr);
                ldsm_x4(bl, baddr + (OFS_BL - OFS_BH));
#pragma unroll
                for (int mf = 0; mf < 2; mf++) {
                    mma_bf16(acc[mf][p * 2 + 0], ah[mf], &bh[0]);
                    mma_bf16(acc[mf][p * 2 + 0], ah[mf], &bl[0]);
                    mma_bf16(acc[mf][p * 2 + 0], al[mf], &bh[0]);
                    mma_bf16(acc[mf][p * 2 + 1], ah[mf], &bh[2]);
                    mma_bf16(acc[mf][p * 2 + 1], ah[mf], &bl[2]);
                    mma_bf16(acc[mf][p * 2 + 1], al[mf], &bh[2]);
                }
            }
        }
        __syncthreads();
        buf ^= 1;
    }

#pragma unroll
    for (int mf = 0; mf < 2; mf++) {
        int m = bm + wm * 32 + mf * 16 + (lane >> 2);
#pragma unroll
        for (int nf = 0; nf < 8; nf++) {
            int n = bn + wn * 64 + nf * 8 + (lane & 3) * 2;
            if (Chi) {
                uint32_t h0, l0, h1, l1;
                split2(acc[mf][nf][0], acc[mf][nf][1], h0, l0);
                split2(acc[mf][nf][2], acc[mf][nf][3], h1, l1);
                *(uint32_t*)&Chi[(size_t)m * N + n] = h0;
                *(uint32_t*)&Clo[(size_t)m * N + n] = l0;
                *(uint32_t*)&Chi[(size_t)(m + 8) * N + n] = h1;
                *(uint32_t*)&Clo[(size_t)(m + 8) * N + n] = l1;
            } else {
                float2 v0 = make_float2(acc[mf][nf][0], acc[mf][nf][1]);
                float2 v1 = make_float2(acc[mf][nf][2], acc[mf][nf][3]);
                if (bias) {
                    float2 bv = *(const float2*)&bias[n];
                    v0.x += bv.x; v0.y += bv.y;
                    v1.x += bv.x; v1.y += bv.y;
                }
                *(float2*)&C[(size_t)m * N + n] = v0;
                *(float2*)&C[(size_t)(m + 8) * N + n] = v1;
            }
        }
    }
}

// ======================= HMMA flash attention (double-buffered cp.async) =======================
#define APITCH 144
#define ABUF 36864    // one buffer: KH 0 | KL 9216 | VH 18432 | VL 27648
#define ASMEM (2 * ABUF)

__device__ __forceinline__ void seg_prefetch(
    const __nv_bfloat16* __restrict__ Kh, const __nv_bfloat16* __restrict__ Kl,
    const __nv_bfloat16* __restrict__ Vh, const __nv_bfloat16* __restrict__ Vl,
    int rstride, int k0, uint32_t bufbase, int t)
{
#pragma unroll
    for (int i = 0; i < 2; i++) {
        int f = t + i * 256;
        int row = f >> 3, cb = (f & 7) << 4;           // byte offset in 128B row
        size_t go = (size_t)(k0 + row) * rstride + (cb >> 1);
        uint32_t so = (uint32_t)(row * APITCH + cb);
        CP_ASYNC16(bufbase + 0     + so, Kh + go);
        CP_ASYNC16(bufbase + 9216  + so, Kl + go);
        CP_ASYNC16(bufbase + 18432 + so, Vh + go);
        CP_ASYNC16(bufbase + 27648 + so, Vl + go);
    }
    CP_COMMIT();
}

__device__ __forceinline__ void attn_segment_pipe(
    const __nv_bfloat16* __restrict__ Kh, const __nv_bfloat16* __restrict__ Kl,
    const __nv_bfloat16* __restrict__ Vh, const __nv_bfloat16* __restrict__ Vl,
    int rstride, int nkeys, uint32_t sb,
    const uint32_t (&qfh)[4][4], const uint32_t (&qfl)[4][4],
    float (&oacc)[8][4], float& m0, float& m1, float& l0, float& l1,
    int t, int lane)
{
    const int nch = nkeys >> 6;
    seg_prefetch(Kh, Kl, Vh, Vl, rstride, 0, sb, t);
    int buf = 0;
    for (int s = 0; s < nch; s++) {
        if (s + 1 < nch) {
            seg_prefetch(Kh, Kl, Vh, Vl, rstride, (s + 1) << 6, sb + (buf ^ 1) * ABUF, t);
            CP_WAIT1();
        } else {
            CP_WAIT0();
        }
        __syncthreads();
        const uint32_t cb = sb + buf * ABUF;

        // ---- S = Q K^T ----
        float sacc[8][4];
#pragma unroll
        for (int nt = 0; nt < 8; nt++)
#pragma unroll
            for (int q = 0; q < 4; q++) sacc[nt][q] = 0.f;

#pragma unroll
        for (int kc = 0; kc < 4; kc++) {
#pragma unroll
            for (int ntp = 0; ntp < 4; ntp++) {
                uint32_t baddr = cb +
                    (uint32_t)((ntp * 16 + (lane & 7) + ((lane >> 4)) * 8) * APITCH +
                               kc * 32 + ((lane >> 3) & 1) * 16);
                uint32_t bh4[4], bl4[4];
                ldsm_x4(bh4, baddr);
                ldsm_x4(bl4, baddr + 9216);
                mma_bf16(sacc[ntp * 2 + 0], qfh[kc], &bh4[0]);
                mma_bf16(sacc[ntp * 2 + 0], qfh[kc], &bl4[0]);
                mma_bf16(sacc[ntp * 2 + 0], qfl[kc], &bh4[0]);
                mma_bf16(sacc[ntp * 2 + 1], qfh[kc], &bh4[2]);
                mma_bf16(sacc[ntp * 2 + 1], qfh[kc], &bl4[2]);
                mma_bf16(sacc[ntp * 2 + 1], qfl[kc], &bh4[2]);
            }
        }

        // ---- online softmax ----
        float mx0 = -1e30f, mx1 = -1e30f;
#pragma unroll
        for (int nt = 0; nt < 8; nt++) {
            mx0 = fmaxf(mx0, fmaxf(sacc[nt][0], sacc[nt][1]));
            mx1 = fmaxf(mx1, fmaxf(sacc[nt][2], sacc[nt][3]));
        }
        mx0 = fmaxf(mx0, __shfl_xor_sync(0xffffffffu, mx0, 1));
        mx0 = fmaxf(mx0, __shfl_xor_sync(0xffffffffu, mx0, 2));
        mx1 = fmaxf(mx1, __shfl_xor_sync(0xffffffffu, mx1, 1));
        mx1 = fmaxf(mx1, __shfl_xor_sync(0xffffffffu, mx1, 2));
        float mn0 = fmaxf(m0, mx0), mn1 = fmaxf(m1, mx1);
        float a0 = __expf(m0 - mn0), a1 = __expf(m1 - mn1);
        m0 = mn0; m1 = mn1;
        float rs0 = 0.f, rs1 = 0.f;
#pragma unroll
        for (int nt = 0; nt < 8; nt++) {
            sacc[nt][0] = __expf(sacc[nt][0] - mn0);
            sacc[nt][1] = __expf(sacc[nt][1] - mn0);
            sacc[nt][2] = __expf(sacc[nt][2] - mn1);
            sacc[nt][3] = __expf(sacc[nt][3] - mn1);
            rs0 += sacc[nt][0] + sacc[nt][1];
            rs1 += sacc[nt][2] + sacc[nt][3];
        }
        rs0 += __shfl_xor_sync(0xffffffffu, rs0, 1);
        rs0 += __shfl_xor_sync(0xffffffffu, rs0, 2);
        rs1 += __shfl_xor_sync(0xffffffffu, rs1, 1);
        rs1 += __shfl_xor_sync(0xffffffffu, rs1, 2);
        l0 = l0 * a0 + rs0;
        l1 = l1 * a1 + rs1;
#pragma unroll
        for (int dt = 0; dt < 8; dt++) {
            oacc[dt][0] *= a0; oacc[dt][1] *= a0;
            oacc[dt][2] *= a1; oacc[dt][3] *= a1;
        }

        // ---- O += P V ----
#pragma unroll
        for (int kc = 0; kc < 4; kc++) {
            uint32_t ph[4], pl[4];
            split2(sacc[2 * kc][0], sacc[2 * kc][1], ph[0], pl[0]);
            split2(sacc[2 * kc][2], sacc[2 * kc][3], ph[1], pl[1]);
            split2(sacc[2 * kc + 1][0], sacc[2 * kc + 1][1], ph[2], pl[2]);
            split2(sacc[2 * kc + 1][2], sacc[2 * kc + 1][3], ph[3], pl[3]);
#pragma unroll
            for (int dp = 0; dp < 4; dp++) {
                uint32_t vaddr = cb + 18432 +
                    (uint32_t)((kc * 16 + (lane & 7) + ((lane >> 3) & 1) * 8) * APITCH +
                               (dp * 16 + (lane >> 4) * 8) * 2);
                uint32_t vh4[4], vl4[4];
                ldsm_x4_t(vh4, vaddr);
                ldsm_x4_t(vl4, vaddr + 9216);
                mma_bf16(oacc[dp * 2 + 0], ph, &vh4[0]);
                mma_bf16(oacc[dp * 2 + 0], ph, &vl4[0]);
                mma_bf16(oacc[dp * 2 + 0], pl, &vh4[0]);
                mma_bf16(oacc[dp * 2 + 1], ph, &vh4[2]);
                mma_bf16(oacc[dp * 2 + 1], ph, &vl4[2]);
                mma_bf16(oacc[dp * 2 + 1], pl, &vh4[2]);
            }
        }
        __syncthreads();
        buf ^= 1;
    }
}

__device__ __forceinline__ void load_q_frags(
    const __nv_bfloat16* __restrict__ Qh, const __nv_bfloat16* __restrict__ Ql,
    int rstride, int q0, char* smp, uint32_t sb,
    uint32_t (&qfh)[4][4], uint32_t (&qfl)[4][4], int t, int lane, int w)
{
    const __nv_bfloat162 sc = __floats2bfloat162_rn(0.125f, 0.125f);
#pragma unroll
    for (int i = 0; i < 8; i++) {
        int f = t + i * 256;
        int row = f >> 4, c8 = f & 15;
        size_t go = (size_t)(q0 + row) * rstride + c8 * 4;
        uint32_t so = (uint32_t)(row * APITCH + c8 * 8);
        uint2 vh = *(const uint2*)&Qh[go];
        uint2 vl = *(const uint2*)&Ql[go];
        __nv_bfloat162* ph = (__nv_bfloat162*)&vh;
        __nv_bfloat162* pL = (__nv_bfloat162*)&vl;
        ph[0] = __hmul2(ph[0], sc); ph[1] = __hmul2(ph[1], sc);
        pL[0] = __hmul2(pL[0], sc); pL[1] = __hmul2(pL[1], sc);
        *(uint2*)(smp + so) = vh;
        *(uint2*)(smp + 18432 + so) = vl;
    }
    __syncthreads();
#pragma unroll
    for (int kc = 0; kc < 4; kc++) {
        uint32_t addr = sb + (uint32_t)((w * 16 + (lane & 15)) * APITCH +
                                        kc * 32 + (lane >> 4) * 16);
        ldsm_x4(qfh[kc], addr);
        ldsm_x4(qfl[kc], addr + 18432);
    }
    __syncthreads();   // ldsm complete everywhere before buffer 0 is overwritten
}

// fused self + cross attention: blocks [0,512) self, [512,640) cross
__global__ __launch_bounds__(256) void attn_fused(
    const __nv_bfloat16* __restrict__ qkv_h, const __nv_bfloat16* __restrict__ qkv_l,
    const __nv_bfloat16* __restrict__ kv_h,  const __nv_bfloat16* __restrict__ kv_l,
    const __nv_bfloat16* __restrict__ qq_h,  const __nv_bfloat16* __restrict__ qq_l,
    const float* __restrict__ gate, float* __restrict__ park,
    __nv_bfloat16* __restrict__ xoh, __nv_bfloat16* __restrict__ xol,
    __nv_bfloat16* __restrict__ qoh, __nv_bfloat16* __restrict__ qol)
{
    extern __shared__ __align__(16) char smp[];   // 2 * ABUF
    const uint32_t sb = smem_u32(smp);
    const int t = threadIdx.x, lane = t & 31, w = t >> 5;

    float oacc[8][4];
#pragma unroll
    for (int dt = 0; dt < 8; dt++)
#pragma unroll
        for (int q = 0; q < 4; q++) oacc[dt][q] = 0.f;
    float m0 = -1e30f, m1 = -1e30f, l0 = 0.f, l1 = 0.f;
    uint32_t qfh[4][4], qfl[4][4];

    if (blockIdx.x < 512) {
        // ---------- self attention ----------
        const int bh = blockIdx.x & 31, b = bh >> 4, h = bh & 15;
        const int q0 = (blockIdx.x >> 5) * 128;
        const __nv_bfloat16* baseh = qkv_h + (size_t)b * N_ * 3072 + h * 64;
        const __nv_bfloat16* basel = qkv_l + (size_t)b * N_ * 3072 + h * 64;

        load_q_frags(baseh, basel, 3072, q0, smp, sb, qfh, qfl, t, lane, w);
        attn_segment_pipe(baseh + 1024, basel + 1024, baseh + 2048, basel + 2048,
                          3072, N_, sb, qfh, qfl, oacc, m0, m1, l0, l1, t, lane);

        float inv0 = 1.f / l0, inv1 = 1.f / l1;
        int r0 = q0 + w * 16 + (lane >> 2);
        int cbc = h * 64 + (lane & 3) * 2;
#pragma unroll
        for (int dt = 0; dt < 8; dt++) {
            uint32_t h0, lo0, h1, lo1;
            split2(oacc[dt][0] * inv0, oacc[dt][1] * inv0, h0, lo0);
            split2(oacc[dt][2] * inv1, oacc[dt][3] * inv1, h1, lo1);
            size_t o0 = (size_t)(b * N_ + r0) * D_ + cbc + dt * 8;
            size_t o1 = (size_t)(b * N_ + r0 + 8) * D_ + cbc + dt * 8;
            *(uint32_t*)&xoh[o0] = h0; *(uint32_t*)&xol[o0] = lo0;
            *(uint32_t*)&xoh[o1] = h1; *(uint32_t*)&xol[o1] = lo1;
        }
    } else {
        // ---------- gated split-softmax cross attention ----------
        const int cid = blockIdx.x - 512;
        const int bh = cid & 31, b = bh >> 4, h = bh & 15;
        const int q0 = (cid >> 5) * 128;
        const __nv_bfloat16* qbh = qq_h + (size_t)b * QN_ * 3072 + h * 64;
        const __nv_bfloat16* qbl = qq_l + (size_t)b * QN_ * 3072 + h * 64;
        const __nv_bfloat16* kbh = kv_h + (size_t)b * N_ * 2048 + h * 64;
        const __nv_bfloat16* kbl = kv_l + (size_t)b * N_ * 2048 + h * 64;

        load_q_frags(qbh, qbl, 3072, q0, smp, sb, qfh, qfl, t, lane, w);

        // segment A: keys/values from x (gated)
        attn_segment_pipe(kbh, kbl, kbh + 1024, kbl + 1024,
                          2048, N_, sb, qfh, qfl, oacc, m0, m1, l0, l1, t, lane);

        const float g = tanhf(gate[h]);
        float gi0 = g / l0, gi1 = g / l1;
        int r0 = q0 + w * 16 + (lane >> 2);
        int cbc = h * 64 + (lane & 3) * 2;
#pragma unroll
        for (int dt = 0; dt < 8; dt++) {
            *(float2*)&park[(size_t)(b * QN_ + r0) * D_ + cbc + dt * 8] =
                make_float2(oacc[dt][0] * gi0, oacc[dt][1] * gi0);
            *(float2*)&park[(size_t)(b * QN_ + r0 + 8) * D_ + cbc + dt * 8] =
                make_float2(oacc[dt][2] * gi1, oacc[dt][3] * gi1);
            oacc[dt][0] = oacc[dt][1] = oacc[dt][2] = oacc[dt][3] = 0.f;
        }
        m0 = -1e30f; m1 = -1e30f; l0 = 0.f; l1 = 0.f;

        // segment B: keys/values from query stream
        attn_segment_pipe(qbh + 1024, qbl + 1024, qbh + 2048, qbl + 2048,
                          3072, QN_, sb, qfh, qfl, oacc, m0, m1, l0, l1, t, lane);

        float inv0 = 1.f / l0, inv1 = 1.f / l1;
#pragma unroll
        for (int dt = 0; dt < 8; dt++) {
            size_t o0 = (size_t)(b * QN_ + r0) * D_ + cbc + dt * 8;
            size_t o1 = (size_t)(b * QN_ + r0 + 8) * D_ + cbc + dt * 8;
            float2 p0 = *(float2*)&park[o0];
            float2 p1 = *(float2*)&park[o1];
            uint32_t h0, lo0, h1, lo1;
            split2(p0.x + oacc[dt][0] * inv0, p0.y + oacc[dt][1] * inv0, h0, lo0);
            split2(p1.x + oacc[dt][2] * inv1, p1.y + oacc[dt][3] * inv1, h1, lo1);
            *(uint32_t*)&qoh[o0] = h0; *(uint32_t*)&qol[o0] = lo0;
            *(uint32_t*)&qoh[o1] = h1; *(uint32_t*)&qol[o1] = lo1;
        }
    }
}

// ======================= low_res scramble + 64x64 proj =======================
__global__ void lr_kernel(const float* __restrict__ low_res,
                          const float* __restrict__ W,
                          const float* __restrict__ bias,
                          float* __restrict__ out)
{
    __shared__ float xin[64];
    const int row = blockIdx.x;
    const int b = row >> 8;
    const int i = row & 255;
    const int t = threadIdx.x;
    {
        int f = i * 64 + t;
        xin[t] = low_res[(size_t)b * (LN_ * LD_) + (f & 255) * 64 + (f >> 8)];
    }
    __syncthreads();
    float s = bias[t];
#pragma unroll 8
    for (int c = 0; c < 64; c++)
        s = fmaf(xin[c], W[c * 64 + t], s);
    out[(size_t)row * 64 + t] = s;
}

// ======================= launch =======================
extern "C" void kernel_launch(void* const* d_in, const int* in_sizes, int n_in,
                              void* d_out, int out_size)
{
    const float* x        = (const float*)d_in[0];
    const float* query    = (const float*)d_in[1];
    const float* low_res  = (const float*)d_in[2];
    const float* W_qkv    = (const float*)d_in[3];
    const float* W_xkv    = (const float*)d_in[4];
    const float* W_qlin   = (const float*)d_in[5];
    const float* gate     = (const float*)d_in[6];
    const float* W_proj   = (const float*)d_in[7];
    const float* b_proj   = (const float*)d_in[8];
    const float* W_qproj  = (const float*)d_in[9];
    const float* b_qproj  = (const float*)d_in[10];
    const float* W_lrproj = (const float*)d_in[11];
    const float* b_lrproj = (const float*)d_in[12];

    __nv_bfloat16 *wh, *wl, *qkvh, *qkvl, *kvh, *kvl, *qqh, *qql;
    __nv_bfloat16 *xh, *xl, *qh, *ql, *xah, *xal, *qah, *qal;
    float* park;
    cudaGetSymbolAddress((void**)&wh,   g_wt_hi);
    cudaGetSymbolAddress((void**)&wl,   g_wt_lo);
    cudaGetSymbolAddress((void**)&qkvh, g_qkv_h);
    cudaGetSymbolAddress((void**)&qkvl, g_qkv_l);
    cudaGetSymbolAddress((void**)&kvh,  g_kv_h);
    cudaGetSymbolAddress((void**)&kvl,  g_kv_l);
    cudaGetSymbolAddress((void**)&qqh,  g_qqkv_h);
    cudaGetSymbolAddress((void**)&qql,  g_qqkv_l);
    cudaGetSymbolAddress((void**)&xh,   g_x_h);
    cudaGetSymbolAddress((void**)&xl,   g_x_l);
    cudaGetSymbolAddress((void**)&qh,   g_q_h);
    cudaGetSymbolAddress((void**)&ql,   g_q_l);
    cudaGetSymbolAddress((void**)&xah,  g_xat_h);
    cudaGetSymbolAddress((void**)&xal,  g_xat_l);
    cudaGetSymbolAddress((void**)&qah,  g_qat_h);
    cudaGetSymbolAddress((void**)&qal,  g_qat_l);
    cudaGetSymbolAddress((void**)&park, g_park);

    float* out   = (float*)d_out;
    float* x_out = out;
    float* q_out = out + (size_t)B_ * N_ * D_;
    float* l_out = q_out + (size_t)B_ * QN_ * D_;

    cudaFuncSetAttribute(gemm_mma, cudaFuncAttributeMaxDynamicSharedMemorySize, GSMEM);
    cudaFuncSetAttribute(attn_fused, cudaFuncAttributeMaxDynamicSharedMemorySize, ASMEM);
    const dim3 blk(256);

    // weight transpose + split; activation split
    wsplit_kernel<<<dim3(3072 / 32, 32), blk>>>(W_qkv,   wh + WOFF_QKV,   wl + WOFF_QKV,   3072);
    wsplit_kernel<<<dim3(2048 / 32, 32), blk>>>(W_xkv,   wh + WOFF_XKV,   wl + WOFF_XKV,   2048);
    wsplit_kernel<<<dim3(3072 / 32, 32), blk>>>(W_qlin,  wh + WOFF_QLIN,  wl + WOFF_QLIN,  3072);
    wsplit_kernel<<<dim3(1024 / 32, 32), blk>>>(W_proj,  wh + WOFF_PROJ,  wl + WOFF_PROJ,  1024);
    wsplit_kernel<<<dim3(1024 / 32, 32), blk>>>(W_qproj, wh + WOFF_QPROJ, wl + WOFF_QPROJ, 1024);
    asplit_kernel<<<(B_ * N_ * D_ / 4) / 256, blk>>>(x, xh, xl);
    asplit_kernel<<<(B_ * QN_ * D_ / 4) / 256, blk>>>(query, qh, ql);

    // input projections -> split bf16 outputs
    gemm_mma<<<dim3(3072 / 128, 4096 / 128), blk, GSMEM>>>(
        xh, xl, wh + WOFF_QKV, wl + WOFF_QKV, nullptr, nullptr, qkvh, qkvl, 4096, 3072, 1024);
    gemm_mma<<<dim3(2048 / 128, 4096 / 128), blk, GSMEM>>>(
        xh, xl, wh + WOFF_XKV, wl + WOFF_XKV, nullptr, nullptr, kvh, kvl, 4096, 2048, 1024);
    gemm_mma<<<dim3(3072 / 128, 1024 / 128), blk, GSMEM>>>(
        qh, ql, wh + WOFF_QLIN, wl + WOFF_QLIN, nullptr, nullptr, qqh, qql, 1024, 3072, 1024);

    // fused attention (self 512 CTAs + cross 128 CTAs)
    attn_fused<<<640, blk, ASMEM>>>(qkvh, qkvl, kvh, kvl, qqh, qql, gate, park,
                                    xah, xal, qah, qal);

    // output projections (fp32 out + bias)
    gemm_mma<<<dim3(1024 / 128, 4096 / 128), blk, GSMEM>>>(
        xah, xal, wh + WOFF_PROJ, wl + WOFF_PROJ, b_proj, x_out, nullptr, nullptr, 4096, 1024, 1024);
    gemm_mma<<<dim3(1024 / 128, 1024 / 128), blk, GSMEM>>>(
        qah, qal, wh + WOFF_QPROJ, wl + WOFF_QPROJ, b_qproj, q_out, nullptr, nullptr, 1024, 1024, 1024);

    // low_res branch
    lr_kernel<<<B_ * LN_, 64>>>(low_res, W_lrproj, b_lrproj, l_out);
}

// round 8
// speedup vs baseline: 3.0404x; 1.0922x over previous
#include <cuda_runtime.h>
#include <cuda_bf16.h>
#include <math.h>
#include <stdint.h>

#define B_  2
#define N_  2048
#define QN_ 512
#define D_  1024
#define H_  16
#define LN_ 256
#define LD_ 64

// ======================= helpers =======================
__device__ __forceinline__ uint32_t smem_u32(const void* p) {
    uint32_t a;
    asm("{ .reg .u64 t; cvta.to.shared.u64 t, %1; cvt.u32.u64 %0, t; }" : "=r"(a) : "l"(p));
    return a;
}
__device__ __forceinline__ void ldsm_x4(uint32_t* r, uint32_t addr) {
    asm volatile("ldmatrix.sync.aligned.m8n8.x4.shared.b16 {%0,%1,%2,%3}, [%4];"
                 : "=r"(r[0]), "=r"(r[1]), "=r"(r[2]), "=r"(r[3]) : "r"(addr));
}
__device__ __forceinline__ void ldsm_x4_t(uint32_t* r, uint32_t addr) {
    asm volatile("ldmatrix.sync.aligned.m8n8.x4.trans.shared.b16 {%0,%1,%2,%3}, [%4];"
                 : "=r"(r[0]), "=r"(r[1]), "=r"(r[2]), "=r"(r[3]) : "r"(addr));
}
__device__ __forceinline__ void mma_bf16(float* d, const uint32_t* a, const uint32_t* b) {
    asm volatile(
        "mma.sync.aligned.m16n8k16.row.col.f32.bf16.bf16.f32 "
        "{%0,%1,%2,%3}, {%4,%5,%6,%7}, {%8,%9}, {%0,%1,%2,%3};"
        : "+f"(d[0]), "+f"(d[1]), "+f"(d[2]), "+f"(d[3])
        : "r"(a[0]), "r"(a[1]), "r"(a[2]), "r"(a[3]), "r"(b[0]), "r"(b[1]));
}
__device__ __forceinline__ uint32_t pack_bf2(__nv_bfloat16 a, __nv_bfloat16 b) {
    __nv_bfloat162 t; t.x = a; t.y = b;
    return *reinterpret_cast<uint32_t*>(&t);
}
__device__ __forceinline__ void split2(float x, float y, uint32_t& hi, uint32_t& lo) {
    __nv_bfloat16 hx = __float2bfloat16(x), hy = __float2bfloat16(y);
    __nv_bfloat16 lx = __float2bfloat16(x - __bfloat162float(hx));
    __nv_bfloat16 ly = __float2bfloat16(y - __bfloat162float(hy));
    hi = pack_bf2(hx, hy);
    lo = pack_bf2(lx, ly);
}
#define CP_ASYNC16(dst, src) \
    asm volatile("cp.async.cg.shared.global [%0], [%1], 16;" :: "r"(dst), "l"(src))
#define CP_COMMIT() asm volatile("cp.async.commit_group;" ::: "memory")
#define CP_WAIT1() asm volatile("cp.async.wait_group 1;" ::: "memory")
#define CP_WAIT0() asm volatile("cp.async.wait_group 0;" ::: "memory")

// ======================= scratch =======================
// combined x projection output: [B*N][5120] = qkv(3072) | kv(2048), stride 5120
#define XPW 5120
__device__ __nv_bfloat16 g_xp_h [B_*N_*XPW], g_xp_l [B_*N_*XPW];
__device__ __nv_bfloat16 g_qqkv_h[B_*QN_*3*D_], g_qqkv_l[B_*QN_*3*D_];
__device__ __nv_bfloat16 g_x_h  [B_*N_*D_],  g_x_l  [B_*N_*D_];
__device__ __nv_bfloat16 g_q_h  [B_*QN_*D_], g_q_l  [B_*QN_*D_];
__device__ __nv_bfloat16 g_xat_h[B_*N_*D_],  g_xat_l[B_*N_*D_];
__device__ __nv_bfloat16 g_qat_h[B_*QN_*D_], g_qat_l[B_*QN_*D_];
__device__ float g_park[B_*QN_*D_];
#define WT_TOTAL 10485760
__device__ __nv_bfloat16 g_wt_hi[WT_TOTAL];
__device__ __nv_bfloat16 g_wt_lo[WT_TOTAL];
#define WOFF_QKV   0
#define WOFF_XKV   (3072*1024)
#define WOFF_QLIN  (WOFF_XKV + 2048*1024)
#define WOFF_PROJ  (WOFF_QLIN + 3072*1024)
#define WOFF_QPROJ (WOFF_PROJ + 1024*1024)

// ============ weight transpose + bf16 split ============
__global__ __launch_bounds__(256) void wsplit_kernel(
    const float* __restrict__ W, __nv_bfloat16* __restrict__ Whi,
    __nv_bfloat16* __restrict__ Wlo, int N)
{
    __shared__ float ts[32][33];
    const int n0 = blockIdx.x * 32, k0 = blockIdx.y * 32;
    const int tx = threadIdx.x & 31, ty = threadIdx.x >> 5;
#pragma unroll
    for (int i = 0; i < 4; i++) {
        int k = k0 + ty + i * 8;
        ts[ty + i * 8][tx] = W[(size_t)k * N + n0 + tx];
    }
    __syncthreads();
#pragma unroll
    for (int i = 0; i < 4; i++) {
        int n = n0 + ty + i * 8;
        float v = ts[tx][ty + i * 8];
        __nv_bfloat16 h = __float2bfloat16(v);
        Whi[(size_t)n * 1024 + k0 + tx] = h;
        Wlo[(size_t)n * 1024 + k0 + tx] = __float2bfloat16(v - __bfloat162float(h));
    }
}

// ============ activation split ============
__global__ __launch_bounds__(256) void asplit_kernel(
    const float* __restrict__ A, __nv_bfloat16* __restrict__ Ah,
    __nv_bfloat16* __restrict__ Al)
{
    int i = blockIdx.x * 256 + threadIdx.x;
    float4 v = ((const float4*)A)[i];
    uint32_t h0, l0, h1, l1;
    split2(v.x, v.y, h0, l0);
    split2(v.z, v.w, h1, l1);
    ((uint2*)Ah)[i] = make_uint2(h0, h1);
    ((uint2*)Al)[i] = make_uint2(l0, l1);
}

// ============ split-bf16 HMMA GEMM body: 128x128 CTA tile, 4 warps (64x64 each) ============
#define PITCH 80
#define STG_BYTES 40960
#define OFS_AH 0
#define OFS_AL 10240
#define OFS_BH 20480
#define OFS_BL 30720
#define GSMEM (2 * STG_BYTES)

__device__ __forceinline__ void gemm_body(
    const __nv_bfloat16* __restrict__ Ah, const __nv_bfloat16* __restrict__ Al,
    const __nv_bfloat16* __restrict__ Bh, const __nv_bfloat16* __restrict__ Bl,
    const float* __restrict__ bias, float* __restrict__ C,
    __nv_bfloat16* __restrict__ Chi, __nv_bfloat16* __restrict__ Clo,
    int bm, int bn, int N, int K, char* dsm)
{
    const uint32_t sb0 = smem_u32(dsm);
    const int t = threadIdx.x;
    const int lane = t & 31;
    const int w = t >> 5;            // 4 warps
    const int wm = w & 1, wn = w >> 1;

    float acc[4][8][4];
#pragma unroll
    for (int mf = 0; mf < 4; mf++)
#pragma unroll
        for (int nf = 0; nf < 8; nf++)
#pragma unroll
            for (int q = 0; q < 4; q++) acc[mf][nf][q] = 0.f;

    const int ns = K >> 5;

    auto prefetch = [&](int s, int buf) {
        const uint32_t base = sb0 + buf * STG_BYTES;
        const int k0 = s << 5;
#pragma unroll
        for (int i = 0; i < 4; i++) {
            int f = t + i * 128;
            int row = f >> 2, c8 = (f & 3) << 3;
            size_t goA = (size_t)(bm + row) * K + k0 + c8;
            size_t goB = (size_t)(bn + row) * K + k0 + c8;
            uint32_t so = (uint32_t)(row * PITCH + c8 * 2);
            CP_ASYNC16(base + OFS_AH + so, Ah + goA);
            CP_ASYNC16(base + OFS_AL + so, Al + goA);
            CP_ASYNC16(base + OFS_BH + so, Bh + goB);
            CP_ASYNC16(base + OFS_BL + so, Bl + goB);
        }
        CP_COMMIT();
    };

    prefetch(0, 0);
    int buf = 0;
    for (int s = 0; s < ns; s++) {
        if (s + 1 < ns) {
            prefetch(s + 1, buf ^ 1);
            CP_WAIT1();
        } else {
            CP_WAIT0();
        }
        __syncthreads();

        const uint32_t sb = sb0 + buf * STG_BYTES;
#pragma unroll
        for (int ks = 0; ks < 2; ks++) {
            uint32_t ah[4][4], al[4][4];
#pragma unroll
            for (int mf = 0; mf < 4; mf++) {
                uint32_t addr = sb + OFS_AH +
                    (uint32_t)((wm * 64 + mf * 16 + (lane & 15)) * PITCH +
                               ks * 32 + (lane >> 4) * 16);
                ldsm_x4(ah[mf], addr);
                ldsm_x4(al[mf], addr + (OFS_AL - OFS_AH));
            }
#pragma unroll
            for (int p = 0; p < 4; p++) {
                int g = lane >> 3;
                uint32_t baddr = sb + OFS_BH +
                    (uint32_t)((wn * 64 + (p * 2 + (g >> 1)) * 8 + (lane & 7)) * PITCH +
                               ks * 32 + (g & 1) * 16);
                uint32_t bh[4], bl[4];
                ldsm_x4(bh, baddr);
                ldsm_x4(bl, baddr + (OFS_BL - OFS_BH));
#pragma unroll
                for (int mf = 0; mf < 4; mf++) {
                    mma_bf16(acc[mf][p * 2 + 0], ah[mf], &bh[0]);
                    mma_bf16(acc[mf][p * 2 + 0], ah[mf], &bl[0]);
                    mma_bf16(acc[mf][p * 2 + 0], al[mf], &bh[0]);
                    mma_bf16(acc[mf][p * 2 + 1], ah[mf], &bh[2]);
                    mma_bf16(acc[mf][p * 2 + 1], ah[mf], &bl[2]);
                    mma_bf16(acc[mf][p * 2 + 1], al[mf], &bh[2]);
                }
            }
        }
        __syncthreads();
        buf ^= 1;
    }

#pragma unroll
    for (int mf = 0; mf < 4; mf++) {
        int m = bm + wm * 64 + mf * 16 + (lane >> 2);
#pragma unroll
        for (int nf = 0; nf < 8; nf++) {
            int n = bn + wn * 64 + nf * 8 + (lane & 3) * 2;
            if (Chi) {
                uint32_t h0, l0, h1, l1;
                split2(acc[mf][nf][0], acc[mf][nf][1], h0, l0);
                split2(acc[mf][nf][2], acc[mf][nf][3], h1, l1);
                *(uint32_t*)&Chi[(size_t)m * N + n] = h0;
                *(uint32_t*)&Clo[(size_t)m * N + n] = l0;
                *(uint32_t*)&Chi[(size_t)(m + 8) * N + n] = h1;
                *(uint32_t*)&Clo[(size_t)(m + 8) * N + n] = l1;
            } else {
                float2 v0 = make_float2(acc[mf][nf][0], acc[mf][nf][1]);
                float2 v1 = make_float2(acc[mf][nf][2], acc[mf][nf][3]);
                if (bias) {
                    float2 bv = *(const float2*)&bias[n];
                    v0.x += bv.x; v0.y += bv.y;
                    v1.x += bv.x; v1.y += bv.y;
                }
                *(float2*)&C[(size_t)m * N + n] = v0;
                *(float2*)&C[(size_t)(m + 8) * N + n] = v1;
            }
        }
    }
}

// fused input projections: CTAs [0,1280) -> x@W(qkv|xkv) N=5120; [1280,1472) -> query@Wqlin
__global__ __launch_bounds__(128, 2) void gemm_in_fused(
    const __nv_bfloat16* __restrict__ xh, const __nv_bfloat16* __restrict__ xl,
    const __nv_bfloat16* __restrict__ qh, const __nv_bfloat16* __restrict__ ql,
    const __nv_bfloat16* __restrict__ wh, const __nv_bfloat16* __restrict__ wl,
    __nv_bfloat16* __restrict__ xph, __nv_bfloat16* __restrict__ xpl,
    __nv_bfloat16* __restrict__ qqh, __nv_bfloat16* __restrict__ qql)
{
    extern __shared__ __align__(16) char dsm[];
    int cta = blockIdx.x;
    if (cta < 1280) {
        int bn = (cta % 40) * 128, bm = (cta / 40) * 128;
        gemm_body(xh, xl, wh + WOFF_QKV, wl + WOFF_QKV, nullptr, nullptr,
                  xph, xpl, bm, bn, XPW, 1024, dsm);
    } else {
        int c2 = cta - 1280;
        int bn = (c2 % 24) * 128, bm = (c2 / 24) * 128;
        gemm_body(qh, ql, wh + WOFF_QLIN, wl + WOFF_QLIN, nullptr, nullptr,
                  qqh, qql, bm, bn, 3072, 1024, dsm);
    }
}

// fused output projections: CTAs [0,256) -> xattn@Wproj; [256,320) -> qattn@Wqproj
__global__ __launch_bounds__(128, 2) void gemm_out_fused(
    const __nv_bfloat16* __restrict__ xah, const __nv_bfloat16* __restrict__ xal,
    const __nv_bfloat16* __restrict__ qah, const __nv_bfloat16* __restrict__ qal,
    const __nv_bfloat16* __restrict__ wh, const __nv_bfloat16* __restrict__ wl,
    const float* __restrict__ b_proj, const float* __restrict__ b_qproj,
    float* __restrict__ x_out, float* __restrict__ q_out)
{
    extern __shared__ __align__(16) char dsm[];
    int cta = blockIdx.x;
    if (cta < 256) {
        int bn = (cta % 8) * 128, bm = (cta / 8) * 128;
        gemm_body(xah, xal, wh + WOFF_PROJ, wl + WOFF_PROJ, b_proj, x_out,
                  nullptr, nullptr, bm, bn, 1024, 1024, dsm);
    } else {
        int c2 = cta - 256;
        int bn = (c2 % 8) * 128, bm = (c2 / 8) * 128;
        gemm_body(qah, qal, wh + WOFF_QPROJ, wl + WOFF_QPROJ, b_qproj, q_out,
                  nullptr, nullptr, bm, bn, 1024, 1024, dsm);
    }
}

// ======================= HMMA flash attention (double-buffered cp.async) =======================
#define APITCH 144
#define ABUF 36864
#define ASMEM (2 * ABUF)

__device__ __forceinline__ void seg_prefetch(
    const __nv_bfloat16* __restrict__ Kh, const __nv_bfloat16* __restrict__ Kl,
    const __nv_bfloat16* __restrict__ Vh, const __nv_bfloat16* __restrict__ Vl,
    int rstride, int k0, uint32_t bufbase, int t)
{
#pragma unroll
    for (int i = 0; i < 2; i++) {
        int f = t + i * 256;
        int row = f >> 3, cb = (f & 7) << 4;
        size_t go = (size_t)(k0 + row) * rstride + (cb >> 1);
        uint32_t so = (uint32_t)(row * APITCH + cb);
        CP_ASYNC16(bufbase + 0     + so, Kh + go);
        CP_ASYNC16(bufbase + 9216  + so, Kl + go);
        CP_ASYNC16(bufbase + 18432 + so, Vh + go);
        CP_ASYNC16(bufbase + 27648 + so, Vl + go);
    }
    CP_COMMIT();
}

__device__ __forceinline__ void attn_segment_pipe(
    const __nv_bfloat16* __restrict__ Kh, const __nv_bfloat16* __restrict__ Kl,
    const __nv_bfloat16* __restrict__ Vh, const __nv_bfloat16* __restrict__ Vl,
    int rstride, int nkeys, uint32_t sb,
    const uint32_t (&qfh)[4][4], const uint32_t (&qfl)[4][4],
    float (&oacc)[8][4], float& m0, float& m1, float& l0, float& l1,
    int t, int lane)
{
    const int nch = nkeys >> 6;
    seg_prefetch(Kh, Kl, Vh, Vl, rstride, 0, sb, t);
    int buf = 0;
    for (int s = 0; s < nch; s++) {
        if (s + 1 < nch) {
            seg_prefetch(Kh, Kl, Vh, Vl, rstride, (s + 1) << 6, sb + (buf ^ 1) * ABUF, t);
            CP_WAIT1();
        } else {
            CP_WAIT0();
        }
        __syncthreads();
        const uint32_t cb = sb + buf * ABUF;

        float sacc[8][4];
#pragma unroll
        for (int nt = 0; nt < 8; nt++)
#pragma unroll
            for (int q = 0; q < 4; q++) sacc[nt][q] = 0.f;

#pragma unroll
        for (int kc = 0; kc < 4; kc++) {
#pragma unroll
            for (int ntp = 0; ntp < 4; ntp++) {
                uint32_t baddr = cb +
                    (uint32_t)((ntp * 16 + (lane & 7) + ((lane >> 4)) * 8) * APITCH +
                               kc * 32 + ((lane >> 3) & 1) * 16);
                uint32_t bh4[4], bl4[4];
                ldsm_x4(bh4, baddr);
                ldsm_x4(bl4, baddr + 9216);
                mma_bf16(sacc[ntp * 2 + 0], qfh[kc], &bh4[0]);
                mma_bf16(sacc[ntp * 2 + 0], qfh[kc], &bl4[0]);
                mma_bf16(sacc[ntp * 2 + 0], qfl[kc], &bh4[0]);
                mma_bf16(sacc[ntp * 2 + 1], qfh[kc], &bh4[2]);
                mma_bf16(sacc[ntp * 2 + 1], qfh[kc], &bl4[2]);
                mma_bf16(sacc[ntp * 2 + 1], qfl[kc], &bh4[2]);
            }
        }

        float mx0 = -1e30f, mx1 = -1e30f;
#pragma unroll
        for (int nt = 0; nt < 8; nt++) {
            mx0 = fmaxf(mx0, fmaxf(sacc[nt][0], sacc[nt][1]));
            mx1 = fmaxf(mx1, fmaxf(sacc[nt][2], sacc[nt][3]));
        }
        mx0 = fmaxf(mx0, __shfl_xor_sync(0xffffffffu, mx0, 1));
        mx0 = fmaxf(mx0, __shfl_xor_sync(0xffffffffu, mx0, 2));
        mx1 = fmaxf(mx1, __shfl_xor_sync(0xffffffffu, mx1, 1));
        mx1 = fmaxf(mx1, __shfl_xor_sync(0xffffffffu, mx1, 2));
        float mn0 = fmaxf(m0, mx0), mn1 = fmaxf(m1, mx1);
        float a0 = __expf(m0 - mn0), a1 = __expf(m1 - mn1);
        m0 = mn0; m1 = mn1;
        float rs0 = 0.f, rs1 = 0.f;
#pragma unroll
        for (int nt = 0; nt < 8; nt++) {
            sacc[nt][0] = __expf(sacc[nt][0] - mn0);
            sacc[nt][1] = __expf(sacc[nt][1] - mn0);
            sacc[nt][2] = __expf(sacc[nt][2] - mn1);
            sacc[nt][3] = __expf(sacc[nt][3] - mn1);
            rs0 += sacc[nt][0] + sacc[nt][1];
            rs1 += sacc[nt][2] + sacc[nt][3];
        }
        rs0 += __shfl_xor_sync(0xffffffffu, rs0, 1);
        rs0 += __shfl_xor_sync(0xffffffffu, rs0, 2);
        rs1 += __shfl_xor_sync(0xffffffffu, rs1, 1);
        rs1 += __shfl_xor_sync(0xffffffffu, rs1, 2);
        l0 = l0 * a0 + rs0;
        l1 = l1 * a1 + rs1;
#pragma unroll
        for (int dt = 0; dt < 8; dt++) {
            oacc[dt][0] *= a0; oacc[dt][1] *= a0;
            oacc[dt][2] *= a1; oacc[dt][3] *= a1;
        }

#pragma unroll
        for (int kc = 0; kc < 4; kc++) {
            uint32_t ph[4], pl[4];
            split2(sacc[2 * kc][0], sacc[2 * kc][1], ph[0], pl[0]);
            split2(sacc[2 * kc][2], sacc[2 * kc][3], ph[1], pl[1]);
            split2(sacc[2 * kc + 1][0], sacc[2 * kc + 1][1], ph[2], pl[2]);
            split2(sacc[2 * kc + 1][2], sacc[2 * kc + 1][3], ph[3], pl[3]);
#pragma unroll
            for (int dp = 0; dp < 4; dp++) {
                uint32_t vaddr = cb + 18432 +
                    (uint32_t)((kc * 16 + (lane & 7) + ((lane >> 3) & 1) * 8) * APITCH +
                               (dp * 16 + (lane >> 4) * 8) * 2);
                uint32_t vh4[4], vl4[4];
                ldsm_x4_t(vh4, vaddr);
                ldsm_x4_t(vl4, vaddr + 9216);
                mma_bf16(oacc[dp * 2 + 0], ph, &vh4[0]);
                mma_bf16(oacc[dp * 2 + 0], ph, &vl4[0]);
                mma_bf16(oacc[dp * 2 + 0], pl, &vh4[0]);
                mma_bf16(oacc[dp * 2 + 1], ph, &vh4[2]);
                mma_bf16(oacc[dp * 2 + 1], ph, &vl4[2]);
                mma_bf16(oacc[dp * 2 + 1], pl, &vh4[2]);
            }
        }
        __syncthreads();
        buf ^= 1;
    }
}

__device__ __forceinline__ void load_q_frags(
    const __nv_bfloat16* __restrict__ Qh, const __nv_bfloat16* __restrict__ Ql,
    int rstride, int q0, char* smp, uint32_t sb,
    uint32_t (&qfh)[4][4], uint32_t (&qfl)[4][4], int t, int lane, int w)
{
    const __nv_bfloat162 sc = __floats2bfloat162_rn(0.125f, 0.125f);
#pragma unroll
    for (int i = 0; i < 8; i++) {
        int f = t + i * 256;
        int row = f >> 4, c8 = f & 15;
        size_t go = (size_t)(q0 + row) * rstride + c8 * 4;
        uint32_t so = (uint32_t)(row * APITCH + c8 * 8);
        uint2 vh = *(const uint2*)&Qh[go];
        uint2 vl = *(const uint2*)&Ql[go];
        __nv_bfloat162* ph = (__nv_bfloat162*)&vh;
        __nv_bfloat162* pL = (__nv_bfloat162*)&vl;
        ph[0] = __hmul2(ph[0], sc); ph[1] = __hmul2(ph[1], sc);
        pL[0] = __hmul2(pL[0], sc); pL[1] = __hmul2(pL[1], sc);
        *(uint2*)(smp + so) = vh;
        *(uint2*)(smp + 18432 + so) = vl;
    }
    __syncthreads();
#pragma unroll
    for (int kc = 0; kc < 4; kc++) {
        uint32_t addr = sb + (uint32_t)((w * 16 + (lane & 15)) * APITCH +
                                        kc * 32 + (lane >> 4) * 16);
        ldsm_x4(qfh[kc], addr);
        ldsm_x4(qfl[kc], addr + 18432);
    }
    __syncthreads();
}

// fused self + cross attention: blocks [0,512) self, [512,640) cross
__global__ __launch_bounds__(256) void attn_fused(
    const __nv_bfloat16* __restrict__ xp_h, const __nv_bfloat16* __restrict__ xp_l,
    const __nv_bfloat16* __restrict__ qq_h, const __nv_bfloat16* __restrict__ qq_l,
    const float* __restrict__ gate, float* __restrict__ park,
    __nv_bfloat16* __restrict__ xoh, __nv_bfloat16* __restrict__ xol,
    __nv_bfloat16* __restrict__ qoh, __nv_bfloat16* __restrict__ qol)
{
    extern __shared__ __align__(16) char smp[];
    const uint32_t sb = smem_u32(smp);
    const int t = threadIdx.x, lane = t & 31, w = t >> 5;

    float oacc[8][4];
#pragma unroll
    for (int dt = 0; dt < 8; dt++)
#pragma unroll
        for (int q = 0; q < 4; q++) oacc[dt][q] = 0.f;
    float m0 = -1e30f, m1 = -1e30f, l0 = 0.f, l1 = 0.f;
    uint32_t qfh[4][4], qfl[4][4];

    if (blockIdx.x < 512) {
        // self attention; q|k|v at cols 0|1024|2048 of xp (stride 5120)
        const int bh = blockIdx.x & 31, b = bh >> 4, h = bh & 15;
        const int q0 = (blockIdx.x >> 5) * 128;
        const __nv_bfloat16* baseh = xp_h + (size_t)b * N_ * XPW + h * 64;
        const __nv_bfloat16* basel = xp_l + (size_t)b * N_ * XPW + h * 64;

        load_q_frags(baseh, basel, XPW, q0, smp, sb, qfh, qfl, t, lane, w);
        attn_segment_pipe(baseh + 1024, basel + 1024, baseh + 2048, basel + 2048,
                          XPW, N_, sb, qfh, qfl, oacc, m0, m1, l0, l1, t, lane);

        float inv0 = 1.f / l0, inv1 = 1.f / l1;
        int r0 = q0 + w * 16 + (lane >> 2);
        int cbc = h * 64 + (lane & 3) * 2;
#pragma unroll
        for (int dt = 0; dt < 8; dt++) {
            uint32_t h0, lo0, h1, lo1;
            split2(oacc[dt][0] * inv0, oacc[dt][1] * inv0, h0, lo0);
            split2(oacc[dt][2] * inv1, oacc[dt][3] * inv1, h1, lo1);
            size_t o0 = (size_t)(b * N_ + r0) * D_ + cbc + dt * 8;
            size_t o1 = (size_t)(b * N_ + r0 + 8) * D_ + cbc + dt * 8;
            *(uint32_t*)&xoh[o0] = h0; *(uint32_t*)&xol[o0] = lo0;
            *(uint32_t*)&xoh[o1] = h1; *(uint32_t*)&xol[o1] = lo1;
        }
    } else {
        // cross attention; k2|v2 at cols 3072|4096 of xp (stride 5120)
        const int cid = blockIdx.x - 512;
        const int bh = cid & 31, b = bh >> 4, h = bh & 15;
        const int q0 = (cid >> 5) * 128;
        const __nv_bfloat16* qbh = qq_h + (size_t)b * QN_ * 3072 + h * 64;
        const __nv_bfloat16* qbl = qq_l + (size_t)b * QN_ * 3072 + h * 64;
        const __nv_bfloat16* kbh = xp_h + (size_t)b * N_ * XPW + 3072 + h * 64;
        const __nv_bfloat16* kbl = xp_l + (size_t)b * N_ * XPW + 3072 + h * 64;

        load_q_frags(qbh, qbl, 3072, q0, smp, sb, qfh, qfl, t, lane, w);

        attn_segment_pipe(kbh, kbl, kbh + 1024, kbl + 1024,
                          XPW, N_, sb, qfh, qfl, oacc, m0, m1, l0, l1, t, lane);

        const float g = tanhf(gate[h]);
        float gi0 = g / l0, gi1 = g / l1;
        int r0 = q0 + w * 16 + (lane >> 2);
        int cbc = h * 64 + (lane & 3) * 2;
#pragma unroll
        for (int dt = 0; dt < 8; dt++) {
            *(float2*)&park[(size_t)(b * QN_ + r0) * D_ + cbc + dt * 8] =
                make_float2(oacc[dt][0] * gi0, oacc[dt][1] * gi0);
            *(float2*)&park[(size_t)(b * QN_ + r0 + 8) * D_ + cbc + dt * 8] =
                make_float2(oacc[dt][2] * gi1, oacc[dt][3] * gi1);
            oacc[dt][0] = oacc[dt][1] = oacc[dt][2] = oacc[dt][3] = 0.f;
        }
        m0 = -1e30f; m1 = -1e30f; l0 = 0.f; l1 = 0.f;

        attn_segment_pipe(qbh + 1024, qbl + 1024, qbh + 2048, qbl + 2048,
                          3072, QN_, sb, qfh, qfl, oacc, m0, m1, l0, l1, t, lane);

        float inv0 = 1.f / l0, inv1 = 1.f / l1;
#pragma unroll
        for (int dt = 0; dt < 8; dt++) {
            size_t o0 = (size_t)(b * QN_ + r0) * D_ + cbc + dt * 8;
            size_t o1 = (size_t)(b * QN_ + r0 + 8) * D_ + cbc + dt * 8;
            float2 p0 = *(float2*)&park[o0];
            float2 p1 = *(float2*)&park[o1];
            uint32_t h0, lo0, h1, lo1;
            split2(p0.x + oacc[dt][0] * inv0, p0.y + oacc[dt][1] * inv0, h0, lo0);
            split2(p1.x + oacc[dt][2] * inv1, p1.y + oacc[dt][3] * inv1, h1, lo1);
            *(uint32_t*)&qoh[o0] = h0; *(uint32_t*)&qol[o0] = lo0;
            *(uint32_t*)&qoh[o1] = h1; *(uint32_t*)&qol[o1] = lo1;
        }
    }
}

// ======================= low_res scramble + 64x64 proj =======================
__global__ void lr_kernel(const float* __restrict__ low_res,
                          const float* __restrict__ W,
                          const float* __restrict__ bias,
                          float* __restrict__ out)
{
    __shared__ float xin[64];
    const int row = blockIdx.x;
    const int b = row >> 8;
    const int i = row & 255;
    const int t = threadIdx.x;
    {
        int f = i * 64 + t;
        xin[t] = low_res[(size_t)b * (LN_ * LD_) + (f & 255) * 64 + (f >> 8)];
    }
    __syncthreads();
    float s = bias[t];
#pragma unroll 8
    for (int c = 0; c < 64; c++)
        s = fmaf(xin[c], W[c * 64 + t], s);
    out[(size_t)row * 64 + t] = s;
}

// ======================= launch =======================
extern "C" void kernel_launch(void* const* d_in, const int* in_sizes, int n_in,
                              void* d_out, int out_size)
{
    const float* x        = (const float*)d_in[0];
    const float* query    = (const float*)d_in[1];
    const float* low_res  = (const float*)d_in[2];
    const float* W_qkv    = (const float*)d_in[3];
    const float* W_xkv    = (const float*)d_in[4];
    const float* W_qlin   = (const float*)d_in[5];
    const float* gate     = (const float*)d_in[6];
    const float* W_proj   = (const float*)d_in[7];
    const float* b_proj   = (const float*)d_in[8];
    const float* W_qproj  = (const float*)d_in[9];
    const float* b_qproj  = (const float*)d_in[10];
    const float* W_lrproj = (const float*)d_in[11];
    const float* b_lrproj = (const float*)d_in[12];

    __nv_bfloat16 *wh, *wl, *xph, *xpl, *qqh, *qql;
    __nv_bfloat16 *xh, *xl, *qh, *ql, *xah, *xal, *qah, *qal;
    float* park;
    cudaGetSymbolAddress((void**)&wh,  g_wt_hi);
    cudaGetSymbolAddress((void**)&wl,  g_wt_lo);
    cudaGetSymbolAddress((void**)&xph, g_xp_h);
    cudaGetSymbolAddress((void**)&xpl, g_xp_l);
    cudaGetSymbolAddress((void**)&qqh, g_qqkv_h);
    cudaGetSymbolAddress((void**)&qql, g_qqkv_l);
    cudaGetSymbolAddress((void**)&xh,  g_x_h);
    cudaGetSymbolAddress((void**)&xl,  g_x_l);
    cudaGetSymbolAddress((void**)&qh,  g_q_h);
    cudaGetSymbolAddress((void**)&ql,  g_q_l);
    cudaGetSymbolAddress((void**)&xah, g_xat_h);
    cudaGetSymbolAddress((void**)&xal, g_xat_l);
    cudaGetSymbolAddress((void**)&qah, g_qat_h);
    cudaGetSymbolAddress((void**)&qal, g_qat_l);
    cudaGetSymbolAddress((void**)&park, g_park);

    float* out   = (float*)d_out;
    float* x_out = out;
    float* q_out = out + (size_t)B_ * N_ * D_;
    float* l_out = q_out + (size_t)B_ * QN_ * D_;

    cudaFuncSetAttribute(gemm_in_fused,  cudaFuncAttributeMaxDynamicSharedMemorySize, GSMEM);
    cudaFuncSetAttribute(gemm_out_fused, cudaFuncAttributeMaxDynamicSharedMemorySize, GSMEM);
    cudaFuncSetAttribute(attn_fused,     cudaFuncAttributeMaxDynamicSharedMemorySize, ASMEM);

    // weight transpose + split; activation split
    wsplit_kernel<<<dim3(3072 / 32, 32), 256>>>(W_qkv,   wh + WOFF_QKV,   wl + WOFF_QKV,   3072);
    wsplit_kernel<<<dim3(2048 / 32, 32), 256>>>(W_xkv,   wh + WOFF_XKV,   wl + WOFF_XKV,   2048);
    wsplit_kernel<<<dim3(3072 / 32, 32), 256>>>(W_qlin,  wh + WOFF_QLIN,  wl + WOFF_QLIN,  3072);
    wsplit_kernel<<<dim3(1024 / 32, 32), 256>>>(W_proj,  wh + WOFF_PROJ,  wl + WOFF_PROJ,  1024);
    wsplit_kernel<<<dim3(1024 / 32, 32), 256>>>(W_qproj, wh + WOFF_QPROJ, wl + WOFF_QPROJ, 1024);
    asplit_kernel<<<(B_ * N_ * D_ / 4) / 256, 256>>>(x, xh, xl);
    asplit_kernel<<<(B_ * QN_ * D_ / 4) / 256, 256>>>(query, qh, ql);

    // fused input projections (x->qkv|kv combined N=5120, query->qqkv)
    gemm_in_fused<<<1472, 128, GSMEM>>>(xh, xl, qh, ql, wh, wl, xph, xpl, qqh, qql);

    // fused attention (self 512 CTAs + cross 128 CTAs)
    attn_fused<<<640, 256, ASMEM>>>(xph, xpl, qqh, qql, gate, park, xah, xal, qah, qal);

    // fused output projections
    gemm_out_fused<<<320, 128, GSMEM>>>(xah, xal, qah, qal, wh, wl,
                                        b_proj, b_qproj, x_out, q_out);

    // low_res branch
    lr_kernel<<<B_ * LN_, 64>>>(low_res, W_lrproj, b_lrproj, l_out);
}

// round 9
// speedup vs baseline: 3.1484x; 1.0355x over previous
#include <cuda_runtime.h>
#include <cuda_bf16.h>
#include <math.h>
#include <stdint.h>

#define B_  2
#define N_  2048
#define QN_ 512
#define D_  1024
#define H_  16
#define LN_ 256
#define LD_ 64

// ======================= helpers =======================
__device__ __forceinline__ uint32_t smem_u32(const void* p) {
    uint32_t a;
    asm("{ .reg .u64 t; cvta.to.shared.u64 t, %1; cvt.u32.u64 %0, t; }" : "=r"(a) : "l"(p));
    return a;
}
__device__ __forceinline__ void ldsm_x4(uint32_t* r, uint32_t addr) {
    asm volatile("ldmatrix.sync.aligned.m8n8.x4.shared.b16 {%0,%1,%2,%3}, [%4];"
                 : "=r"(r[0]), "=r"(r[1]), "=r"(r[2]), "=r"(r[3]) : "r"(addr));
}
__device__ __forceinline__ void ldsm_x4_t(uint32_t* r, uint32_t addr) {
    asm volatile("ldmatrix.sync.aligned.m8n8.x4.trans.shared.b16 {%0,%1,%2,%3}, [%4];"
                 : "=r"(r[0]), "=r"(r[1]), "=r"(r[2]), "=r"(r[3]) : "r"(addr));
}
__device__ __forceinline__ void mma_bf16(float* d, const uint32_t* a, const uint32_t* b) {
    asm volatile(
        "mma.sync.aligned.m16n8k16.row.col.f32.bf16.bf16.f32 "
        "{%0,%1,%2,%3}, {%4,%5,%6,%7}, {%8,%9}, {%0,%1,%2,%3};"
        : "+f"(d[0]), "+f"(d[1]), "+f"(d[2]), "+f"(d[3])
        : "r"(a[0]), "r"(a[1]), "r"(a[2]), "r"(a[3]), "r"(b[0]), "r"(b[1]));
}
__device__ __forceinline__ uint32_t pack_bf2(__nv_bfloat16 a, __nv_bfloat16 b) {
    __nv_bfloat162 t; t.x = a; t.y = b;
    return *reinterpret_cast<uint32_t*>(&t);
}
__device__ __forceinline__ void split2(float x, float y, uint32_t& hi, uint32_t& lo) {
    __nv_bfloat16 hx = __float2bfloat16(x), hy = __float2bfloat16(y);
    __nv_bfloat16 lx = __float2bfloat16(x - __bfloat162float(hx));
    __nv_bfloat16 ly = __float2bfloat16(y - __bfloat162float(hy));
    hi = pack_bf2(hx, hy);
    lo = pack_bf2(lx, ly);
}
#define CP_ASYNC16(dst, src) \
    asm volatile("cp.async.cg.shared.global [%0], [%1], 16;" :: "r"(dst), "l"(src))
#define CP_COMMIT() asm volatile("cp.async.commit_group;" ::: "memory")
#define CP_WAIT1() asm volatile("cp.async.wait_group 1;" ::: "memory")
#define CP_WAIT0() asm volatile("cp.async.wait_group 0;" ::: "memory")

// ======================= scratch =======================
#define XPW 5120
__device__ __nv_bfloat16 g_xp_h [B_*N_*XPW], g_xp_l [B_*N_*XPW];
__device__ __nv_bfloat16 g_qqkv_h[B_*QN_*3*D_], g_qqkv_l[B_*QN_*3*D_];
__device__ __nv_bfloat16 g_x_h  [B_*N_*D_],  g_x_l  [B_*N_*D_];
__device__ __nv_bfloat16 g_q_h  [B_*QN_*D_], g_q_l  [B_*QN_*D_];
__device__ __nv_bfloat16 g_xat_h[B_*N_*D_],  g_xat_l[B_*N_*D_];
__device__ __nv_bfloat16 g_qat_h[B_*QN_*D_], g_qat_l[B_*QN_*D_];
__device__ float g_park[B_*QN_*D_];
#define WT_TOTAL 10485760
__device__ __nv_bfloat16 g_wt_hi[WT_TOTAL];
__device__ __nv_bfloat16 g_wt_lo[WT_TOTAL];
#define WOFF_QKV   0
#define WOFF_XKV   (3072*1024)
#define WOFF_QLIN  (WOFF_XKV + 2048*1024)
#define WOFF_PROJ  (WOFF_QLIN + 3072*1024)
#define WOFF_QPROJ (WOFF_PROJ + 1024*1024)

// ============ fused weight transpose + bf16 split (all 5 weights, one launch) ============
__global__ __launch_bounds__(256) void wsplit_all(
    const float* __restrict__ Wqkv, const float* __restrict__ Wxkv,
    const float* __restrict__ Wqlin, const float* __restrict__ Wproj,
    const float* __restrict__ Wqproj,
    __nv_bfloat16* __restrict__ WH, __nv_bfloat16* __restrict__ WL)
{
    __shared__ float ts[32][33];
    const int nb = blockIdx.x;  // 0..319
    const float* W; int N, n0; size_t woff;
    if (nb < 96)       { W = Wqkv;   N = 3072; n0 = nb * 32;         woff = WOFF_QKV; }
    else if (nb < 160) { W = Wxkv;   N = 2048; n0 = (nb - 96) * 32;  woff = WOFF_XKV; }
    else if (nb < 256) { W = Wqlin;  N = 3072; n0 = (nb - 160) * 32; woff = WOFF_QLIN; }
    else if (nb < 288) { W = Wproj;  N = 1024; n0 = (nb - 256) * 32; woff = WOFF_PROJ; }
    else               { W = Wqproj; N = 1024; n0 = (nb - 288) * 32; woff = WOFF_QPROJ; }
    const int k0 = blockIdx.y * 32;
    const int tx = threadIdx.x & 31, ty = threadIdx.x >> 5;
#pragma unroll
    for (int i = 0; i < 4; i++) {
        int k = k0 + ty + i * 8;
        ts[ty + i * 8][tx] = W[(size_t)k * N + n0 + tx];
    }
    __syncthreads();
#pragma unroll
    for (int i = 0; i < 4; i++) {
        int n = n0 + ty + i * 8;
        float v = ts[tx][ty + i * 8];
        __nv_bfloat16 h = __float2bfloat16(v);
        WH[woff + (size_t)n * 1024 + k0 + tx] = h;
        WL[woff + (size_t)n * 1024 + k0 + tx] = __float2bfloat16(v - __bfloat162float(h));
    }
}

// ============ fused activation split (x + query, one launch) ============
__global__ __launch_bounds__(256) void asplit_all(
    const float* __restrict__ x, const float* __restrict__ query,
    __nv_bfloat16* __restrict__ xh, __nv_bfloat16* __restrict__ xl,
    __nv_bfloat16* __restrict__ qh, __nv_bfloat16* __restrict__ ql)
{
    int cta = blockIdx.x;
    const float* A; __nv_bfloat16 *Ah, *Al; int i;
    if (cta < 4096) { A = x; Ah = xh; Al = xl; i = cta * 256 + threadIdx.x; }
    else { A = query; Ah = qh; Al = ql; i = (cta - 4096) * 256 + threadIdx.x; }
    float4 v = ((const float4*)A)[i];
    uint32_t h0, l0, h1, l1;
    split2(v.x, v.y, h0, l0);
    split2(v.z, v.w, h1, l1);
    ((uint2*)Ah)[i] = make_uint2(h0, h1);
    ((uint2*)Al)[i] = make_uint2(l0, l1);
}

// ============ split-bf16 HMMA GEMM body: 128x128 CTA tile, 4 warps (64x64 each) ============
#define PITCH 80
#define STG_BYTES 40960
#define OFS_AH 0
#define OFS_AL 10240
#define OFS_BH 20480
#define OFS_BL 30720
#define GSMEM (2 * STG_BYTES)

__device__ __forceinline__ void gemm_body(
    const __nv_bfloat16* __restrict__ Ah, const __nv_bfloat16* __restrict__ Al,
    const __nv_bfloat16* __restrict__ Bh, const __nv_bfloat16* __restrict__ Bl,
    const float* __restrict__ bias, float* __restrict__ C,
    __nv_bfloat16* __restrict__ Chi, __nv_bfloat16* __restrict__ Clo,
    int bm, int bn, int N, int K, char* dsm)
{
    const uint32_t sb0 = smem_u32(dsm);
    const int t = threadIdx.x;
    const int lane = t & 31;
    const int w = t >> 5;
    const int wm = w & 1, wn = w >> 1;

    float acc[4][8][4];
#pragma unroll
    for (int mf = 0; mf < 4; mf++)
#pragma unroll
        for (int nf = 0; nf < 8; nf++)
#pragma unroll
            for (int q = 0; q < 4; q++) acc[mf][nf][q] = 0.f;

    const int ns = K >> 5;

    auto prefetch = [&](int s, int buf) {
        const uint32_t base = sb0 + buf * STG_BYTES;
        const int k0 = s << 5;
#pragma unroll
        for (int i = 0; i < 4; i++) {
            int f = t + i * 128;
            int row = f >> 2, c8 = (f & 3) << 3;
            size_t goA = (size_t)(bm + row) * K + k0 + c8;
            size_t goB = (size_t)(bn + row) * K + k0 + c8;
            uint32_t so = (uint32_t)(row * PITCH + c8 * 2);
            CP_ASYNC16(base + OFS_AH + so, Ah + goA);
            CP_ASYNC16(base + OFS_AL + so, Al + goA);
            CP_ASYNC16(base + OFS_BH + so, Bh + goB);
            CP_ASYNC16(base + OFS_BL + so, Bl + goB);
        }
        CP_COMMIT();
    };

    prefetch(0, 0);
    int buf = 0;
    for (int s = 0; s < ns; s++) {
        if (s + 1 < ns) {
            prefetch(s + 1, buf ^ 1);
            CP_WAIT1();
        } else {
            CP_WAIT0();
        }
        __syncthreads();

        const uint32_t sb = sb0 + buf * STG_BYTES;
#pragma unroll
        for (int ks = 0; ks < 2; ks++) {
            uint32_t ah[4][4], al[4][4];
#pragma unroll
            for (int mf = 0; mf < 4; mf++) {
                uint32_t addr = sb + OFS_AH +
                    (uint32_t)((wm * 64 + mf * 16 + (lane & 15)) * PITCH +
                               ks * 32 + (lane >> 4) * 16);
                ldsm_x4(ah[mf], addr);
                ldsm_x4(al[mf], addr + (OFS_AL - OFS_AH));
            }
#pragma unroll
            for (int p = 0; p < 4; p++) {
                int g = lane >> 3;
                uint32_t baddr = sb + OFS_BH +
                    (uint32_t)((wn * 64 + (p * 2 + (g >> 1)) * 8 + (lane & 7)) * PITCH +
                               ks * 32 + (g & 1) * 16);
                uint32_t bh[4], bl[4];
                ldsm_x4(bh, baddr);
                ldsm_x4(bl, baddr + (OFS_BL - OFS_BH));
#pragma unroll
                for (int mf = 0; mf < 4; mf++) {
                    mma_bf16(acc[mf][p * 2 + 0], ah[mf], &bh[0]);
                    mma_bf16(acc[mf][p * 2 + 0], ah[mf], &bl[0]);
                    mma_bf16(acc[mf][p * 2 + 0], al[mf], &bh[0]);
                    mma_bf16(acc[mf][p * 2 + 1], ah[mf], &bh[2]);
                    mma_bf16(acc[mf][p * 2 + 1], ah[mf], &bl[2]);
                    mma_bf16(acc[mf][p * 2 + 1], al[mf], &bh[2]);
                }
            }
        }
        __syncthreads();
        buf ^= 1;
    }

#pragma unroll
    for (int mf = 0; mf < 4; mf++) {
        int m = bm + wm * 64 + mf * 16 + (lane >> 2);
#pragma unroll
        for (int nf = 0; nf < 8; nf++) {
            int n = bn + wn * 64 + nf * 8 + (lane & 3) * 2;
            if (Chi) {
                uint32_t h0, l0, h1, l1;
                split2(acc[mf][nf][0], acc[mf][nf][1], h0, l0);
                split2(acc[mf][nf][2], acc[mf][nf][3], h1, l1);
                *(uint32_t*)&Chi[(size_t)m * N + n] = h0;
                *(uint32_t*)&Clo[(size_t)m * N + n] = l0;
                *(uint32_t*)&Chi[(size_t)(m + 8) * N + n] = h1;
                *(uint32_t*)&Clo[(size_t)(m + 8) * N + n] = l1;
            } else {
                float2 v0 = make_float2(acc[mf][nf][0], acc[mf][nf][1]);
                float2 v1 = make_float2(acc[mf][nf][2], acc[mf][nf][3]);
                if (bias) {
                    float2 bv = *(const float2*)&bias[n];
                    v0.x += bv.x; v0.y += bv.y;
                    v1.x += bv.x; v1.y += bv.y;
                }
                *(float2*)&C[(size_t)m * N + n] = v0;
                *(float2*)&C[(size_t)(m + 8) * N + n] = v1;
            }
        }
    }
}

__global__ __launch_bounds__(128, 2) void gemm_in_fused(
    const __nv_bfloat16* __restrict__ xh, const __nv_bfloat16* __restrict__ xl,
    const __nv_bfloat16* __restrict__ qh, const __nv_bfloat16* __restrict__ ql,
    const __nv_bfloat16* __restrict__ wh, const __nv_bfloat16* __restrict__ wl,
    __nv_bfloat16* __restrict__ xph, __nv_bfloat16* __restrict__ xpl,
    __nv_bfloat16* __restrict__ qqh, __nv_bfloat16* __restrict__ qql)
{
    extern __shared__ __align__(16) char dsm[];
    int cta = blockIdx.x;
    if (cta < 1280) {
        int bn = (cta % 40) * 128, bm = (cta / 40) * 128;
        gemm_body(xh, xl, wh + WOFF_QKV, wl + WOFF_QKV, nullptr, nullptr,
                  xph, xpl, bm, bn, XPW, 1024, dsm);
    } else {
        int c2 = cta - 1280;
        int bn = (c2 % 24) * 128, bm = (c2 / 24) * 128;
        gemm_body(qh, ql, wh + WOFF_QLIN, wl + WOFF_QLIN, nullptr, nullptr,
                  qqh, qql, bm, bn, 3072, 1024, dsm);
    }
}

__global__ __launch_bounds__(128, 2) void gemm_out_fused(
    const __nv_bfloat16* __restrict__ xah, const __nv_bfloat16* __restrict__ xal,
    const __nv_bfloat16* __restrict__ qah, const __nv_bfloat16* __restrict__ qal,
    const __nv_bfloat16* __restrict__ wh, const __nv_bfloat16* __restrict__ wl,
    const float* __restrict__ b_proj, const float* __restrict__ b_qproj,
    float* __restrict__ x_out, float* __restrict__ q_out)
{
    extern __shared__ __align__(16) char dsm[];
    int cta = blockIdx.x;
    if (cta < 256) {
        int bn = (cta % 8) * 128, bm = (cta / 8) * 128;
        gemm_body(xah, xal, wh + WOFF_PROJ, wl + WOFF_PROJ, b_proj, x_out,
                  nullptr, nullptr, bm, bn, 1024, 1024, dsm);
    } else {
        int c2 = cta - 256;
        int bn = (c2 % 8) * 128, bm = (c2 / 8) * 128;
        gemm_body(qah, qal, wh + WOFF_QPROJ, wl + WOFF_QPROJ, b_qproj, q_out,
                  nullptr, nullptr, bm, bn, 1024, 1024, dsm);
    }
}

// ======================= HMMA flash attention (4 warps x 32 Q-rows) =======================
#define APITCH 144
#define ABUF 36864
#define ASMEM (2 * ABUF)

__device__ __forceinline__ void seg_prefetch(
    const __nv_bfloat16* __restrict__ Kh, const __nv_bfloat16* __restrict__ Kl,
    const __nv_bfloat16* __restrict__ Vh, const __nv_bfloat16* __restrict__ Vl,
    int rstride, int k0, uint32_t bufbase, int t)
{
#pragma unroll
    for (int i = 0; i < 4; i++) {
        int f = t + i * 128;
        int row = f >> 3, cb = (f & 7) << 4;
        size_t go = (size_t)(k0 + row) * rstride + (cb >> 1);
        uint32_t so = (uint32_t)(row * APITCH + cb);
        CP_ASYNC16(bufbase + 0     + so, Kh + go);
        CP_ASYNC16(bufbase + 9216  + so, Kl + go);
        CP_ASYNC16(bufbase + 18432 + so, Vh + go);
        CP_ASYNC16(bufbase + 27648 + so, Vl + go);
    }
    CP_COMMIT();
}

__device__ __forceinline__ void attn_segment_pipe(
    const __nv_bfloat16* __restrict__ Kh, const __nv_bfloat16* __restrict__ Kl,
    const __nv_bfloat16* __restrict__ Vh, const __nv_bfloat16* __restrict__ Vl,
    int rstride, int nkeys, uint32_t sb,
    const uint32_t (&qfh)[2][4][4], const uint32_t (&qfl)[2][4][4],
    float (&oacc)[2][8][4], float (&mm)[2][2], float (&ll)[2][2],
    int t, int lane)
{
    const int nch = nkeys >> 6;
    seg_prefetch(Kh, Kl, Vh, Vl, rstride, 0, sb, t);
    int buf = 0;
    for (int s = 0; s < nch; s++) {
        if (s + 1 < nch) {
            seg_prefetch(Kh, Kl, Vh, Vl, rstride, (s + 1) << 6, sb + (buf ^ 1) * ABUF, t);
            CP_WAIT1();
        } else {
            CP_WAIT0();
        }
        __syncthreads();
        const uint32_t cb = sb + buf * ABUF;

        // ---- S = Q K^T ----
        float sacc[2][8][4];
#pragma unroll
        for (int mf = 0; mf < 2; mf++)
#pragma unroll
            for (int nt = 0; nt < 8; nt++)
#pragma unroll
                for (int q = 0; q < 4; q++) sacc[mf][nt][q] = 0.f;

#pragma unroll
        for (int kc = 0; kc < 4; kc++) {
#pragma unroll
            for (int ntp = 0; ntp < 4; ntp++) {
                uint32_t baddr = cb +
                    (uint32_t)((ntp * 16 + (lane & 7) + ((lane >> 4)) * 8) * APITCH +
                               kc * 32 + ((lane >> 3) & 1) * 16);
                uint32_t bh4[4], bl4[4];
                ldsm_x4(bh4, baddr);
                ldsm_x4(bl4, baddr + 9216);
#pragma unroll
                for (int mf = 0; mf < 2; mf++) {
                    mma_bf16(sacc[mf][ntp * 2 + 0], qfh[mf][kc], &bh4[0]);
                    mma_bf16(sacc[mf][ntp * 2 + 0], qfh[mf][kc], &bl4[0]);
                    mma_bf16(sacc[mf][ntp * 2 + 0], qfl[mf][kc], &bh4[0]);
                    mma_bf16(sacc[mf][ntp * 2 + 1], qfh[mf][kc], &bh4[2]);
                    mma_bf16(sacc[mf][ntp * 2 + 1], qfh[mf][kc], &bl4[2]);
                    mma_bf16(sacc[mf][ntp * 2 + 1], qfl[mf][kc], &bh4[2]);
                }
            }
        }

        // ---- online softmax (per mf, rows r and r+8) ----
#pragma unroll
        for (int mf = 0; mf < 2; mf++) {
            float mx0 = -1e30f, mx1 = -1e30f;
#pragma unroll
            for (int nt = 0; nt < 8; nt++) {
                mx0 = fmaxf(mx0, fmaxf(sacc[mf][nt][0], sacc[mf][nt][1]));
                mx1 = fmaxf(mx1, fmaxf(sacc[mf][nt][2], sacc[mf][nt][3]));
            }
            mx0 = fmaxf(mx0, __shfl_xor_sync(0xffffffffu, mx0, 1));
            mx0 = fmaxf(mx0, __shfl_xor_sync(0xffffffffu, mx0, 2));
            mx1 = fmaxf(mx1, __shfl_xor_sync(0xffffffffu, mx1, 1));
            mx1 = fmaxf(mx1, __shfl_xor_sync(0xffffffffu, mx1, 2));
            float mn0 = fmaxf(mm[mf][0], mx0), mn1 = fmaxf(mm[mf][1], mx1);
            float a0 = __expf(mm[mf][0] - mn0), a1 = __expf(mm[mf][1] - mn1);
            mm[mf][0] = mn0; mm[mf][1] = mn1;
            float rs0 = 0.f, rs1 = 0.f;
#pragma unroll
            for (int nt = 0; nt < 8; nt++) {
                sacc[mf][nt][0] = __expf(sacc[mf][nt][0] - mn0);
                sacc[mf][nt][1] = __expf(sacc[mf][nt][1] - mn0);
                sacc[mf][nt][2] = __expf(sacc[mf][nt][2] - mn1);
                sacc[mf][nt][3] = __expf(sacc[mf][nt][3] - mn1);
                rs0 += sacc[mf][nt][0] + sacc[mf][nt][1];
                rs1 += sacc[mf][nt][2] + sacc[mf][nt][3];
            }
            rs0 += __shfl_xor_sync(0xffffffffu, rs0, 1);
            rs0 += __shfl_xor_sync(0xffffffffu, rs0, 2);
            rs1 += __shfl_xor_sync(0xffffffffu, rs1, 1);
            rs1 += __shfl_xor_sync(0xffffffffu, rs1, 2);
            ll[mf][0] = ll[mf][0] * a0 + rs0;
            ll[mf][1] = ll[mf][1] * a1 + rs1;
#pragma unroll
            for (int dt = 0; dt < 8; dt++) {
                oacc[mf][dt][0] *= a0; oacc[mf][dt][1] *= a0;
                oacc[mf][dt][2] *= a1; oacc[mf][dt][3] *= a1;
            }
        }

        // ---- O += P V ----
#pragma unroll
        for (int kc = 0; kc < 4; kc++) {
            uint32_t ph[2][4], pl[2][4];
#pragma unroll
            for (int mf = 0; mf < 2; mf++) {
                split2(sacc[mf][2 * kc][0], sacc[mf][2 * kc][1], ph[mf][0], pl[mf][0]);
                split2(sacc[mf][2 * kc][2], sacc[mf][2 * kc][3], ph[mf][1], pl[mf][1]);
                split2(sacc[mf][2 * kc + 1][0], sacc[mf][2 * kc + 1][1], ph[mf][2], pl[mf][2]);
                split2(sacc[mf][2 * kc + 1][2], sacc[mf][2 * kc + 1][3], ph[mf][3], pl[mf][3]);
            }
#pragma unroll
            for (int dp = 0; dp < 4; dp++) {
                uint32_t vaddr = cb + 18432 +
                    (uint32_t)((kc * 16 + (lane & 7) + ((lane >> 3) & 1) * 8) * APITCH +
                               (dp * 16 + (lane >> 4) * 8) * 2);
                uint32_t vh4[4], vl4[4];
                ldsm_x4_t(vh4, vaddr);
                ldsm_x4_t(vl4, vaddr + 9216);
#pragma unroll
                for (int mf = 0; mf < 2; mf++) {
                    mma_bf16(oacc[mf][dp * 2 + 0], ph[mf], &vh4[0]);
                    mma_bf16(oacc[mf][dp * 2 + 0], ph[mf], &vl4[0]);
                    mma_bf16(oacc[mf][dp * 2 + 0], pl[mf], &vh4[0]);
                    mma_bf16(oacc[mf][dp * 2 + 1], ph[mf], &vh4[2]);
                    mma_bf16(oacc[mf][dp * 2 + 1], ph[mf], &vl4[2]);
                    mma_bf16(oacc[mf][dp * 2 + 1], pl[mf], &vh4[2]);
                }
            }
        }
        __syncthreads();
        buf ^= 1;
    }
}

__device__ __forceinline__ void load_q_frags(
    const __nv_bfloat16* __restrict__ Qh, const __nv_bfloat16* __restrict__ Ql,
    int rstride, int q0, char* smp, uint32_t sb,
    uint32_t (&qfh)[2][4][4], uint32_t (&qfl)[2][4][4], int t, int lane, int w)
{
    const __nv_bfloat162 sc = __floats2bfloat162_rn(0.125f, 0.125f);
#pragma unroll
    for (int i = 0; i < 16; i++) {
        int f = t + i * 128;
        int row = f >> 4, c8 = f & 15;
        size_t go = (size_t)(q0 + row) * rstride + c8 * 4;
        uint32_t so = (uint32_t)(row * APITCH + c8 * 8);
        uint2 vh = *(const uint2*)&Qh[go];
        uint2 vl = *(const uint2*)&Ql[go];
        __nv_bfloat162* ph = (__nv_bfloat162*)&vh;
        __nv_bfloat162* pL = (__nv_bfloat162*)&vl;
        ph[0] = __hmul2(ph[0], sc); ph[1] = __hmul2(ph[1], sc);
        pL[0] = __hmul2(pL[0], sc); pL[1] = __hmul2(pL[1], sc);
        *(uint2*)(smp + so) = vh;
        *(uint2*)(smp + 18432 + so) = vl;
    }
    __syncthreads();
#pragma unroll
    for (int mf = 0; mf < 2; mf++)
#pragma unroll
        for (int kc = 0; kc < 4; kc++) {
            uint32_t addr = sb + (uint32_t)((w * 32 + mf * 16 + (lane & 15)) * APITCH +
                                            kc * 32 + (lane >> 4) * 16);
            ldsm_x4(qfh[mf][kc], addr);
            ldsm_x4(qfl[mf][kc], addr + 18432);
        }
    __syncthreads();
}

// fused self + cross attention: blocks [0,512) self, [512,640) cross; 128 threads
__global__ __launch_bounds__(128, 2) void attn_fused(
    const __nv_bfloat16* __restrict__ xp_h, const __nv_bfloat16* __restrict__ xp_l,
    const __nv_bfloat16* __restrict__ qq_h, const __nv_bfloat16* __restrict__ qq_l,
    const float* __restrict__ gate, float* __restrict__ park,
    __nv_bfloat16* __restrict__ xoh, __nv_bfloat16* __restrict__ xol,
    __nv_bfloat16* __restrict__ qoh, __nv_bfloat16* __restrict__ qol)
{
    extern __shared__ __align__(16) char smp[];
    const uint32_t sb = smem_u32(smp);
    const int t = threadIdx.x, lane = t & 31, w = t >> 5;

    float oacc[2][8][4];
#pragma unroll
    for (int mf = 0; mf < 2; mf++)
#pragma unroll
        for (int dt = 0; dt < 8; dt++)
#pragma unroll
            for (int q = 0; q < 4; q++) oacc[mf][dt][q] = 0.f;
    float mm[2][2] = {{-1e30f, -1e30f}, {-1e30f, -1e30f}};
    float ll[2][2] = {{0.f, 0.f}, {0.f, 0.f}};
    uint32_t qfh[2][4][4], qfl[2][4][4];

    if (blockIdx.x < 512) {
        // self attention; q|k|v at cols 0|1024|2048 of xp (stride 5120)
        const int bh = blockIdx.x & 31, b = bh >> 4, h = bh & 15;
        const int q0 = (blockIdx.x >> 5) * 128;
        const __nv_bfloat16* baseh = xp_h + (size_t)b * N_ * XPW + h * 64;
        const __nv_bfloat16* basel = xp_l + (size_t)b * N_ * XPW + h * 64;

        load_q_frags(baseh, basel, XPW, q0, smp, sb, qfh, qfl, t, lane, w);
        attn_segment_pipe(baseh + 1024, basel + 1024, baseh + 2048, basel + 2048,
                          XPW, N_, sb, qfh, qfl, oacc, mm, ll, t, lane);

        int cbc = h * 64 + (lane & 3) * 2;
#pragma unroll
        for (int mf = 0; mf < 2; mf++) {
            float inv0 = 1.f / ll[mf][0], inv1 = 1.f / ll[mf][1];
            int r0 = q0 + w * 32 + mf * 16 + (lane >> 2);
#pragma unroll
            for (int dt = 0; dt < 8; dt++) {
                uint32_t h0, lo0, h1, lo1;
                split2(oacc[mf][dt][0] * inv0, oacc[mf][dt][1] * inv0, h0, lo0);
                split2(oacc[mf][dt][2] * inv1, oacc[mf][dt][3] * inv1, h1, lo1);
                size_t o0 = (size_t)(b * N_ + r0) * D_ + cbc + dt * 8;
                size_t o1 = (size_t)(b * N_ + r0 + 8) * D_ + cbc + dt * 8;
                *(uint32_t*)&xoh[o0] = h0; *(uint32_t*)&xol[o0] = lo0;
                *(uint32_t*)&xoh[o1] = h1; *(uint32_t*)&xol[o1] = lo1;
            }
        }
    } else {
        // cross attention; k2|v2 at cols 3072|4096 of xp (stride 5120)
        const int cid = blockIdx.x - 512;
        const int bh = cid & 31, b = bh >> 4, h = bh & 15;
        const int q0 = (cid >> 5) * 128;
        const __nv_bfloat16* qbh = qq_h + (size_t)b * QN_ * 3072 + h * 64;
        const __nv_bfloat16* qbl = qq_l + (size_t)b * QN_ * 3072 + h * 64;
        const __nv_bfloat16* kbh = xp_h + (size_t)b * N_ * XPW + 3072 + h * 64;
        const __nv_bfloat16* kbl = xp_l + (size_t)b * N_ * XPW + 3072 + h * 64;

        load_q_frags(qbh, qbl, 3072, q0, smp, sb, qfh, qfl, t, lane, w);

        // segment A: keys/values from x (gated)
        attn_segment_pipe(kbh, kbl, kbh + 1024, kbl + 1024,
                          XPW, N_, sb, qfh, qfl, oacc, mm, ll, t, lane);

        const float g = tanhf(gate[h]);
        int cbc = h * 64 + (lane & 3) * 2;
#pragma unroll
        for (int mf = 0; mf < 2; mf++) {
            float gi0 = g / ll[mf][0], gi1 = g / ll[mf][1];
            int r0 = q0 + w * 32 + mf * 16 + (lane >> 2);
#pragma unroll
            for (int dt = 0; dt < 8; dt++) {
                *(float2*)&park[(size_t)(b * QN_ + r0) * D_ + cbc + dt * 8] =
                    make_float2(oacc[mf][dt][0] * gi0, oacc[mf][dt][1] * gi0);
                *(float2*)&park[(size_t)(b * QN_ + r0 + 8) * D_ + cbc + dt * 8] =
                    make_float2(oacc[mf][dt][2] * gi1, oacc[mf][dt][3] * gi1);
                oacc[mf][dt][0] = oacc[mf][dt][1] = oacc[mf][dt][2] = oacc[mf][dt][3] = 0.f;
            }
            mm[mf][0] = -1e30f; mm[mf][1] = -1e30f;
            ll[mf][0] = 0.f; ll[mf][1] = 0.f;
        }

        // segment B: keys/values from query stream
        attn_segment_pipe(qbh + 1024, qbl + 1024, qbh + 2048, qbl + 2048,
                          3072, QN_, sb, qfh, qfl, oacc, mm, ll, t, lane);

#pragma unroll
        for (int mf = 0; mf < 2; mf++) {
            float inv0 = 1.f / ll[mf][0], inv1 = 1.f / ll[mf][1];
            int r0 = q0 + w * 32 + mf * 16 + (lane >> 2);
#pragma unroll
            for (int dt = 0; dt < 8; dt++) {
                size_t o0 = (size_t)(b * QN_ + r0) * D_ + cbc + dt * 8;
                size_t o1 = (size_t)(b * QN_ + r0 + 8) * D_ + cbc + dt * 8;
                float2 p0 = *(float2*)&park[o0];
                float2 p1 = *(float2*)&park[o1];
                uint32_t h0, lo0, h1, lo1;
                split2(p0.x + oacc[mf][dt][0] * inv0, p0.y + oacc[mf][dt][1] * inv0, h0, lo0);
                split2(p1.x + oacc[mf][dt][2] * inv1, p1.y + oacc[mf][dt][3] * inv1, h1, lo1);
                *(uint32_t*)&qoh[o0] = h0; *(uint32_t*)&qol[o0] = lo0;
                *(uint32_t*)&qoh[o1] = h1; *(uint32_t*)&qol[o1] = lo1;
            }
        }
    }
}

// ======================= low_res scramble + 64x64 proj =======================
__global__ void lr_kernel(const float* __restrict__ low_res,
                          const float* __restrict__ W,
                          const float* __restrict__ bias,
                          float* __restrict__ out)
{
    __shared__ float xin[64];
    const int row = blockIdx.x;
    const int b = row >> 8;
    const int i = row & 255;
    const int t = threadIdx.x;
    {
        int f = i * 64 + t;
        xin[t] = low_res[(size_t)b * (LN_ * LD_) + (f & 255) * 64 + (f >> 8)];
    }
    __syncthreads();
    float s = bias[t];
#pragma unroll 8
    for (int c = 0; c < 64; c++)
        s = fmaf(xin[c], W[c * 64 + t], s);
    out[(size_t)row * 64 + t] = s;
}

// ======================= launch =======================
extern "C" void kernel_launch(void* const* d_in, const int* in_sizes, int n_in,
                              void* d_out, int out_size)
{
    const float* x        = (const float*)d_in[0];
    const float* query    = (const float*)d_in[1];
    const float* low_res  = (const float*)d_in[2];
    const float* W_qkv    = (const float*)d_in[3];
    const float* W_xkv    = (const float*)d_in[4];
    const float* W_qlin   = (const float*)d_in[5];
    const float* gate     = (const float*)d_in[6];
    const float* W_proj   = (const float*)d_in[7];
    const float* b_proj   = (const float*)d_in[8];
    const float* W_qproj  = (const float*)d_in[9];
    const float* b_qproj  = (const float*)d_in[10];
    const float* W_lrproj = (const float*)d_in[11];
    const float* b_lrproj = (const float*)d_in[12];

    __nv_bfloat16 *wh, *wl, *xph, *xpl, *qqh, *qql;
    __nv_bfloat16 *xh, *xl, *qh, *ql, *xah, *xal, *qah, *qal;
    float* park;
    cudaGetSymbolAddress((void**)&wh,  g_wt_hi);
    cudaGetSymbolAddress((void**)&wl,  g_wt_lo);
    cudaGetSymbolAddress((void**)&xph, g_xp_h);
    cudaGetSymbolAddress((void**)&xpl, g_xp_l);
    cudaGetSymbolAddress((void**)&qqh, g_qqkv_h);
    cudaGetSymbolAddress((void**)&qql, g_qqkv_l);
    cudaGetSymbolAddress((void**)&xh,  g_x_h);
    cudaGetSymbolAddress((void**)&xl,  g_x_l);
    cudaGetSymbolAddress((void**)&qh,  g_q_h);
    cudaGetSymbolAddress((void**)&ql,  g_q_l);
    cudaGetSymbolAddress((void**)&xah, g_xat_h);
    cudaGetSymbolAddress((void**)&xal, g_xat_l);
    cudaGetSymbolAddress((void**)&qah, g_qat_h);
    cudaGetSymbolAddress((void**)&qal, g_qat_l);
    cudaGetSymbolAddress((void**)&park, g_park);

    float* out   = (float*)d_out;
    float* x_out = out;
    float* q_out = out + (size_t)B_ * N_ * D_;
    float* l_out = q_out + (size_t)B_ * QN_ * D_;

    cudaFuncSetAttribute(gemm_in_fused,  cudaFuncAttributeMaxDynamicSharedMemorySize, GSMEM);
    cudaFuncSetAttribute(gemm_out_fused, cudaFuncAttributeMaxDynamicSharedMemorySize, GSMEM);
    cudaFuncSetAttribute(attn_fused,     cudaFuncAttributeMaxDynamicSharedMemorySize, ASMEM);

    // fused prep: all weight splits in one launch; both activation splits in one
    wsplit_all<<<dim3(320, 32), 256>>>(W_qkv, W_xkv, W_qlin, W_proj, W_qproj, wh, wl);
    asplit_all<<<5120, 256>>>(x, query, xh, xl, qh, ql);

    // fused input projections (x->qkv|kv combined N=5120, query->qqkv)
    gemm_in_fused<<<1472, 128, GSMEM>>>(xh, xl, qh, ql, wh, wl, xph, xpl, qqh, qql);

    // fused attention (self 512 CTAs + cross 128 CTAs), 4 warps/CTA
    attn_fused<<<640, 128, ASMEM>>>(xph, xpl, qqh, qql, gate, park, xah, xal, qah, qal);

    // fused output projections
    gemm_out_fused<<<320, 128, GSMEM>>>(xah, xal, qah, qal, wh, wl,
                                        b_proj, b_qproj, x_out, q_out);

    // low_res branch
    lr_kernel<<<B_ * LN_, 64>>>(low_res, W_lrproj, b_lrproj, l_out);
}

// round 10
// speedup vs baseline: 3.2529x; 1.0332x over previous
#include <cuda_runtime.h>
#include <cuda_bf16.h>
#include <math.h>
#include <stdint.h>

#define B_  2
#define N_  2048
#define QN_ 512
#define D_  1024
#define H_  16
#define LN_ 256
#define LD_ 64

// ======================= helpers =======================
__device__ __forceinline__ uint32_t smem_u32(const void* p) {
    uint32_t a;
    asm("{ .reg .u64 t; cvta.to.shared.u64 t, %1; cvt.u32.u64 %0, t; }" : "=r"(a) : "l"(p));
    return a;
}
__device__ __forceinline__ void ldsm_x4(uint32_t* r, uint32_t addr) {
    asm volatile("ldmatrix.sync.aligned.m8n8.x4.shared.b16 {%0,%1,%2,%3}, [%4];"
                 : "=r"(r[0]), "=r"(r[1]), "=r"(r[2]), "=r"(r[3]) : "r"(addr));
}
__device__ __forceinline__ void ldsm_x4_t(uint32_t* r, uint32_t addr) {
    asm volatile("ldmatrix.sync.aligned.m8n8.x4.trans.shared.b16 {%0,%1,%2,%3}, [%4];"
                 : "=r"(r[0]), "=r"(r[1]), "=r"(r[2]), "=r"(r[3]) : "r"(addr));
}
__device__ __forceinline__ void mma_bf16(float* d, const uint32_t* a, const uint32_t* b) {
    asm volatile(
        "mma.sync.aligned.m16n8k16.row.col.f32.bf16.bf16.f32 "
        "{%0,%1,%2,%3}, {%4,%5,%6,%7}, {%8,%9}, {%0,%1,%2,%3};"
        : "+f"(d[0]), "+f"(d[1]), "+f"(d[2]), "+f"(d[3])
        : "r"(a[0]), "r"(a[1]), "r"(a[2]), "r"(a[3]), "r"(b[0]), "r"(b[1]));
}
__device__ __forceinline__ uint32_t pack_bf2(__nv_bfloat16 a, __nv_bfloat16 b) {
    __nv_bfloat162 t; t.x = a; t.y = b;
    return *reinterpret_cast<uint32_t*>(&t);
}
__device__ __forceinline__ void split2(float x, float y, uint32_t& hi, uint32_t& lo) {
    __nv_bfloat16 hx = __float2bfloat16(x), hy = __float2bfloat16(y);
    __nv_bfloat16 lx = __float2bfloat16(x - __bfloat162float(hx));
    __nv_bfloat16 ly = __float2bfloat16(y - __bfloat162float(hy));
    hi = pack_bf2(hx, hy);
    lo = pack_bf2(lx, ly);
}
#define CP_ASYNC16(dst, src) \
    asm volatile("cp.async.cg.shared.global [%0], [%1], 16;" :: "r"(dst), "l"(src))
#define CP_COMMIT() asm volatile("cp.async.commit_group;" ::: "memory")
#define CP_WAIT1() asm volatile("cp.async.wait_group 1;" ::: "memory")
#define CP_WAIT0() asm volatile("cp.async.wait_group 0;" ::: "memory")

// ======================= scratch =======================
#define XPW 5120
__device__ __nv_bfloat16 g_xp_h [B_*N_*XPW], g_xp_l [B_*N_*XPW];
__device__ __nv_bfloat16 g_qqkv_h[B_*QN_*3*D_], g_qqkv_l[B_*QN_*3*D_];
__device__ __nv_bfloat16 g_x_h  [B_*N_*D_],  g_x_l  [B_*N_*D_];
__device__ __nv_bfloat16 g_q_h  [B_*QN_*D_], g_q_l  [B_*QN_*D_];
__device__ __nv_bfloat16 g_xat_h[B_*N_*D_],  g_xat_l[B_*N_*D_];
__device__ __nv_bfloat16 g_qat_h[B_*QN_*D_], g_qat_l[B_*QN_*D_];
__device__ float g_park[B_*QN_*D_];
#define WT_TOTAL 10485760
__device__ __nv_bfloat16 g_wt_hi[WT_TOTAL];
__device__ __nv_bfloat16 g_wt_lo[WT_TOTAL];
#define WOFF_QKV   0
#define WOFF_XKV   (3072*1024)
#define WOFF_QLIN  (WOFF_XKV + 2048*1024)
#define WOFF_PROJ  (WOFF_QLIN + 3072*1024)
#define WOFF_QPROJ (WOFF_PROJ + 1024*1024)

// ============ fused weight transpose + bf16 split ============
__global__ __launch_bounds__(256) void wsplit_all(
    const float* __restrict__ Wqkv, const float* __restrict__ Wxkv,
    const float* __restrict__ Wqlin, const float* __restrict__ Wproj,
    const float* __restrict__ Wqproj,
    __nv_bfloat16* __restrict__ WH, __nv_bfloat16* __restrict__ WL)
{
    __shared__ float ts[32][33];
    const int nb = blockIdx.x;
    const float* W; int N, n0; size_t woff;
    if (nb < 96)       { W = Wqkv;   N = 3072; n0 = nb * 32;         woff = WOFF_QKV; }
    else if (nb < 160) { W = Wxkv;   N = 2048; n0 = (nb - 96) * 32;  woff = WOFF_XKV; }
    else if (nb < 256) { W = Wqlin;  N = 3072; n0 = (nb - 160) * 32; woff = WOFF_QLIN; }
    else if (nb < 288) { W = Wproj;  N = 1024; n0 = (nb - 256) * 32; woff = WOFF_PROJ; }
    else               { W = Wqproj; N = 1024; n0 = (nb - 288) * 32; woff = WOFF_QPROJ; }
    const int k0 = blockIdx.y * 32;
    const int tx = threadIdx.x & 31, ty = threadIdx.x >> 5;
#pragma unroll
    for (int i = 0; i < 4; i++) {
        int k = k0 + ty + i * 8;
        ts[ty + i * 8][tx] = W[(size_t)k * N + n0 + tx];
    }
    __syncthreads();
#pragma unroll
    for (int i = 0; i < 4; i++) {
        int n = n0 + ty + i * 8;
        float v = ts[tx][ty + i * 8];
        __nv_bfloat16 h = __float2bfloat16(v);
        WH[woff + (size_t)n * 1024 + k0 + tx] = h;
        WL[woff + (size_t)n * 1024 + k0 + tx] = __float2bfloat16(v - __bfloat162float(h));
    }
}

// ============ fused activation split ============
__global__ __launch_bounds__(256) void asplit_all(
    const float* __restrict__ x, const float* __restrict__ query,
    __nv_bfloat16* __restrict__ xh, __nv_bfloat16* __restrict__ xl,
    __nv_bfloat16* __restrict__ qh, __nv_bfloat16* __restrict__ ql)
{
    int cta = blockIdx.x;
    const float* A; __nv_bfloat16 *Ah, *Al; int i;
    if (cta < 4096) { A = x; Ah = xh; Al = xl; i = cta * 256 + threadIdx.x; }
    else { A = query; Ah = qh; Al = ql; i = (cta - 4096) * 256 + threadIdx.x; }
    float4 v = ((const float4*)A)[i];
    uint32_t h0, l0, h1, l1;
    split2(v.x, v.y, h0, l0);
    split2(v.z, v.w, h1, l1);
    ((uint2*)Ah)[i] = make_uint2(h0, h1);
    ((uint2*)Al)[i] = make_uint2(l0, l1);
}

// ============ split-bf16 HMMA GEMM body: 128x128 CTA tile, 4 warps ============
#define PITCH 80
#define STG_BYTES 40960
#define OFS_AH 0
#define OFS_AL 10240
#define OFS_BH 20480
#define OFS_BL 30720
#define GSMEM (2 * STG_BYTES)

__device__ __forceinline__ void gemm_body(
    const __nv_bfloat16* __restrict__ Ah, const __nv_bfloat16* __restrict__ Al,
    const __nv_bfloat16* __restrict__ Bh, const __nv_bfloat16* __restrict__ Bl,
    const float* __restrict__ bias, float* __restrict__ C,
    __nv_bfloat16* __restrict__ Chi, __nv_bfloat16* __restrict__ Clo,
    int bm, int bn, int N, int K, char* dsm)
{
    const uint32_t sb0 = smem_u32(dsm);
    const int t = threadIdx.x;
    const int lane = t & 31;
    const int w = t >> 5;
    const int wm = w & 1, wn = w >> 1;

    float acc[4][8][4];
#pragma unroll
    for (int mf = 0; mf < 4; mf++)
#pragma unroll
        for (int nf = 0; nf < 8; nf++)
#pragma unroll
            for (int q = 0; q < 4; q++) acc[mf][nf][q] = 0.f;

    const int ns = K >> 5;

    auto prefetch = [&](int s, int buf) {
        const uint32_t base = sb0 + buf * STG_BYTES;
        const int k0 = s << 5;
#pragma unroll
        for (int i = 0; i < 4; i++) {
            int f = t + i * 128;
            int row = f >> 2, c8 = (f & 3) << 3;
            size_t goA = (size_t)(bm + row) * K + k0 + c8;
            size_t goB = (size_t)(bn + row) * K + k0 + c8;
            uint32_t so = (uint32_t)(row * PITCH + c8 * 2);
            CP_ASYNC16(base + OFS_AH + so, Ah + goA);
            CP_ASYNC16(base + OFS_AL + so, Al + goA);
            CP_ASYNC16(base + OFS_BH + so, Bh + goB);
            CP_ASYNC16(base + OFS_BL + so, Bl + goB);
        }
        CP_COMMIT();
    };

    prefetch(0, 0);
    int buf = 0;
    for (int s = 0; s < ns; s++) {
        if (s + 1 < ns) {
            prefetch(s + 1, buf ^ 1);
            CP_WAIT1();
        } else {
            CP_WAIT0();
        }
        __syncthreads();

        const uint32_t sb = sb0 + buf * STG_BYTES;
#pragma unroll
        for (int ks = 0; ks < 2; ks++) {
            uint32_t ah[4][4], al[4][4];
#pragma unroll
            for (int mf = 0; mf < 4; mf++) {
                uint32_t addr = sb + OFS_AH +
                    (uint32_t)((wm * 64 + mf * 16 + (lane & 15)) * PITCH +
                               ks * 32 + (lane >> 4) * 16);
                ldsm_x4(ah[mf], addr);
                ldsm_x4(al[mf], addr + (OFS_AL - OFS_AH));
            }
#pragma unroll
            for (int p = 0; p < 4; p++) {
                int g = lane >> 3;
                uint32_t baddr = sb + OFS_BH +
                    (uint32_t)((wn * 64 + (p * 2 + (g >> 1)) * 8 + (lane & 7)) * PITCH +
                               ks * 32 + (g & 1) * 16);
                uint32_t bh[4], bl[4];
                ldsm_x4(bh, baddr);
                ldsm_x4(bl, baddr + (OFS_BL - OFS_BH));
#pragma unroll
                for (int mf = 0; mf < 4; mf++) {
                    mma_bf16(acc[mf][p * 2 + 0], ah[mf], &bh[0]);
                    mma_bf16(acc[mf][p * 2 + 0], ah[mf], &bl[0]);
                    mma_bf16(acc[mf][p * 2 + 0], al[mf], &bh[0]);
                    mma_bf16(acc[mf][p * 2 + 1], ah[mf], &bh[2]);
                    mma_bf16(acc[mf][p * 2 + 1], ah[mf], &bl[2]);
                    mma_bf16(acc[mf][p * 2 + 1], al[mf], &bh[2]);
                }
            }
        }
        __syncthreads();
        buf ^= 1;
    }

#pragma unroll
    for (int mf = 0; mf < 4; mf++) {
        int m = bm + wm * 64 + mf * 16 + (lane >> 2);
#pragma unroll
        for (int nf = 0; nf < 8; nf++) {
            int n = bn + wn * 64 + nf * 8 + (lane & 3) * 2;
            if (Chi) {
                uint32_t h0, l0, h1, l1;
                split2(acc[mf][nf][0], acc[mf][nf][1], h0, l0);
                split2(acc[mf][nf][2], acc[mf][nf][3], h1, l1);
                *(uint32_t*)&Chi[(size_t)m * N + n] = h0;
                *(uint32_t*)&Clo[(size_t)m * N + n] = l0;
                *(uint32_t*)&Chi[(size_t)(m + 8) * N + n] = h1;
                *(uint32_t*)&Clo[(size_t)(m + 8) * N + n] = l1;
            } else {
                float2 v0 = make_float2(acc[mf][nf][0], acc[mf][nf][1]);
                float2 v1 = make_float2(acc[mf][nf][2], acc[mf][nf][3]);
                if (bias) {
                    float2 bv = *(const float2*)&bias[n];
                    v0.x += bv.x; v0.y += bv.y;
                    v1.x += bv.x; v1.y += bv.y;
                }
                *(float2*)&C[(size_t)m * N + n] = v0;
                *(float2*)&C[(size_t)(m + 8) * N + n] = v1;
            }
        }
    }
}

__global__ __launch_bounds__(128, 2) void gemm_in_fused(
    const __nv_bfloat16* __restrict__ xh, const __nv_bfloat16* __restrict__ xl,
    const __nv_bfloat16* __restrict__ qh, const __nv_bfloat16* __restrict__ ql,
    const __nv_bfloat16* __restrict__ wh, const __nv_bfloat16* __restrict__ wl,
    __nv_bfloat16* __restrict__ xph, __nv_bfloat16* __restrict__ xpl,
    __nv_bfloat16* __restrict__ qqh, __nv_bfloat16* __restrict__ qql)
{
    extern __shared__ __align__(16) char dsm[];
    int cta = blockIdx.x;
    if (cta < 1280) {
        int bn = (cta % 40) * 128, bm = (cta / 40) * 128;
        gemm_body(xh, xl, wh + WOFF_QKV, wl + WOFF_QKV, nullptr, nullptr,
                  xph, xpl, bm, bn, XPW, 1024, dsm);
    } else {
        int c2 = cta - 1280;
        int bn = (c2 % 24) * 128, bm = (c2 / 24) * 128;
        gemm_body(qh, ql, wh + WOFF_QLIN, wl + WOFF_QLIN, nullptr, nullptr,
                  qqh, qql, bm, bn, 3072, 1024, dsm);
    }
}

__global__ __launch_bounds__(128, 2) void gemm_out_fused(
    const __nv_bfloat16* __restrict__ xah, const __nv_bfloat16* __restrict__ xal,
    const __nv_bfloat16* __restrict__ qah, const __nv_bfloat16* __restrict__ qal,
    const __nv_bfloat16* __restrict__ wh, const __nv_bfloat16* __restrict__ wl,
    const float* __restrict__ b_proj, const float* __restrict__ b_qproj,
    float* __restrict__ x_out, float* __restrict__ q_out)
{
    extern __shared__ __align__(16) char dsm[];
    int cta = blockIdx.x;
    if (cta < 256) {
        int bn = (cta % 8) * 128, bm = (cta / 8) * 128;
        gemm_body(xah, xal, wh + WOFF_PROJ, wl + WOFF_PROJ, b_proj, x_out,
                  nullptr, nullptr, bm, bn, 1024, 1024, dsm);
    } else {
        int c2 = cta - 256;
        int bn = (c2 % 8) * 128, bm = (c2 / 8) * 128;
        gemm_body(qah, qal, wh + WOFF_QPROJ, wl + WOFF_QPROJ, b_qproj, q_out,
                  nullptr, nullptr, bm, bn, 1024, 1024, dsm);
    }
}

// ======================= HMMA flash attention (4 warps, Q persistent in smem) =======================
#define APITCH 144
#define ABUF 36864           // K/V buffer: KH 0 | KL 9216 | VH 18432 | VL 27648
#define QREG 36864           // Q region: hi at +0, lo at +18432
#define ASMEM (2 * ABUF + QREG)   // 110592 per CTA, 2 CTAs = 221184 <= 228KB

__device__ __forceinline__ void seg_prefetch(
    const __nv_bfloat16* __restrict__ Kh, const __nv_bfloat16* __restrict__ Kl,
    const __nv_bfloat16* __restrict__ Vh, const __nv_bfloat16* __restrict__ Vl,
    int rstride, int k0, uint32_t bufbase, int t)
{
#pragma unroll
    for (int i = 0; i < 4; i++) {
        int f = t + i * 128;
        int row = f >> 3, cb = (f & 7) << 4;
        size_t go = (size_t)(k0 + row) * rstride + (cb >> 1);
        uint32_t so = (uint32_t)(row * APITCH + cb);
        CP_ASYNC16(bufbase + 0     + so, Kh + go);
        CP_ASYNC16(bufbase + 9216  + so, Kl + go);
        CP_ASYNC16(bufbase + 18432 + so, Vh + go);
        CP_ASYNC16(bufbase + 27648 + so, Vl + go);
    }
    CP_COMMIT();
}

__device__ __forceinline__ void attn_segment_pipe(
    const __nv_bfloat16* __restrict__ Kh, const __nv_bfloat16* __restrict__ Kl,
    const __nv_bfloat16* __restrict__ Vh, const __nv_bfloat16* __restrict__ Vl,
    int rstride, int nkeys, uint32_t sb, uint32_t sbQ,
    float (&oacc)[2][8][4], float (&mm)[2][2], float (&ll)[2][2],
    int t, int lane, int w)
{
    const int nch = nkeys >> 6;
    seg_prefetch(Kh, Kl, Vh, Vl, rstride, 0, sb, t);
    int buf = 0;
    for (int s = 0; s < nch; s++) {
        if (s + 1 < nch) {
            seg_prefetch(Kh, Kl, Vh, Vl, rstride, (s + 1) << 6, sb + (buf ^ 1) * ABUF, t);
            CP_WAIT1();
        } else {
            CP_WAIT0();
        }
        __syncthreads();
        const uint32_t cb = sb + buf * ABUF;

        // ---- S = Q K^T (Q frags re-loaded from persistent smem per kc) ----
        float sacc[2][8][4];
#pragma unroll
        for (int mf = 0; mf < 2; mf++)
#pragma unroll
            for (int nt = 0; nt < 8; nt++)
#pragma unroll
                for (int q = 0; q < 4; q++) sacc[mf][nt][q] = 0.f;

#pragma unroll
        for (int kc = 0; kc < 4; kc++) {
            uint32_t qh2[2][4], ql2[2][4];
#pragma unroll
            for (int mf = 0; mf < 2; mf++) {
                uint32_t qaddr = sbQ +
                    (uint32_t)((w * 32 + mf * 16 + (lane & 15)) * APITCH +
                               kc * 32 + (lane >> 4) * 16);
                ldsm_x4(qh2[mf], qaddr);
                ldsm_x4(ql2[mf], qaddr + 18432);
            }
#pragma unroll
            for (int ntp = 0; ntp < 4; ntp++) {
                uint32_t baddr = cb +
                    (uint32_t)((ntp * 16 + (lane & 7) + ((lane >> 4)) * 8) * APITCH +
                               kc * 32 + ((lane >> 3) & 1) * 16);
                uint32_t bh4[4], bl4[4];
                ldsm_x4(bh4, baddr);
                ldsm_x4(bl4, baddr + 9216);
#pragma unroll
                for (int mf = 0; mf < 2; mf++) {
                    mma_bf16(sacc[mf][ntp * 2 + 0], qh2[mf], &bh4[0]);
                    mma_bf16(sacc[mf][ntp * 2 + 0], qh2[mf], &bl4[0]);
                    mma_bf16(sacc[mf][ntp * 2 + 0], ql2[mf], &bh4[0]);
                    mma_bf16(sacc[mf][ntp * 2 + 1], qh2[mf], &bh4[2]);
                    mma_bf16(sacc[mf][ntp * 2 + 1], qh2[mf], &bl4[2]);
                    mma_bf16(sacc[mf][ntp * 2 + 1], ql2[mf], &bh4[2]);
                }
            }
        }

        // ---- online softmax (per mf, rows r and r+8) ----
#pragma unroll
        for (int mf = 0; mf < 2; mf++) {
            float mx0 = -1e30f, mx1 = -1e30f;
#pragma unroll
            for (int nt = 0; nt < 8; nt++) {
                mx0 = fmaxf(mx0, fmaxf(sacc[mf][nt][0], sacc[mf][nt][1]));
                mx1 = fmaxf(mx1, fmaxf(sacc[mf][nt][2], sacc[mf][nt][3]));
            }
            mx0 = fmaxf(mx0, __shfl_xor_sync(0xffffffffu, mx0, 1));
            mx0 = fmaxf(mx0, __shfl_xor_sync(0xffffffffu, mx0, 2));
            mx1 = fmaxf(mx1, __shfl_xor_sync(0xffffffffu, mx1, 1));
            mx1 = fmaxf(mx1, __shfl_xor_sync(0xffffffffu, mx1, 2));
            float mn0 = fmaxf(mm[mf][0], mx0), mn1 = fmaxf(mm[mf][1], mx1);
            float a0 = __expf(mm[mf][0] - mn0), a1 = __expf(mm[mf][1] - mn1);
            mm[mf][0] = mn0; mm[mf][1] = mn1;
            float rs0 = 0.f, rs1 = 0.f;
#pragma unroll
            for (int nt = 0; nt < 8; nt++) {
                sacc[mf][nt][0] = __expf(sacc[mf][nt][0] - mn0);
                sacc[mf][nt][1] = __expf(sacc[mf][nt][1] - mn0);
                sacc[mf][nt][2] = __expf(sacc[mf][nt][2] - mn1);
                sacc[mf][nt][3] = __expf(sacc[mf][nt][3] - mn1);
                rs0 += sacc[mf][nt][0] + sacc[mf][nt][1];
                rs1 += sacc[mf][nt][2] + sacc[mf][nt][3];
            }
            rs0 += __shfl_xor_sync(0xffffffffu, rs0, 1);
            rs0 += __shfl_xor_sync(0xffffffffu, rs0, 2);
            rs1 += __shfl_xor_sync(0xffffffffu, rs1, 1);
            rs1 += __shfl_xor_sync(0xffffffffu, rs1, 2);
            ll[mf][0] = ll[mf][0] * a0 + rs0;
            ll[mf][1] = ll[mf][1] * a1 + rs1;
#pragma unroll
            for (int dt = 0; dt < 8; dt++) {
                oacc[mf][dt][0] *= a0; oacc[mf][dt][1] *= a0;
                oacc[mf][dt][2] *= a1; oacc[mf][dt][3] *= a1;
            }
        }

        // ---- O += P V ----
#pragma unroll
        for (int kc = 0; kc < 4; kc++) {
            uint32_t ph[2][4], pl[2][4];
#pragma unroll
            for (int mf = 0; mf < 2; mf++) {
                split2(sacc[mf][2 * kc][0], sacc[mf][2 * kc][1], ph[mf][0], pl[mf][0]);
                split2(sacc[mf][2 * kc][2], sacc[mf][2 * kc][3], ph[mf][1], pl[mf][1]);
                split2(sacc[mf][2 * kc + 1][0], sacc[mf][2 * kc + 1][1], ph[mf][2], pl[mf][2]);
                split2(sacc[mf][2 * kc + 1][2], sacc[mf][2 * kc + 1][3], ph[mf][3], pl[mf][3]);
            }
#pragma unroll
            for (int dp = 0; dp < 4; dp++) {
                uint32_t vaddr = cb + 18432 +
                    (uint32_t)((kc * 16 + (lane & 7) + ((lane >> 3) & 1) * 8) * APITCH +
                               (dp * 16 + (lane >> 4) * 8) * 2);
                uint32_t vh4[4], vl4[4];
                ldsm_x4_t(vh4, vaddr);
                ldsm_x4_t(vl4, vaddr + 9216);
#pragma unroll
                for (int mf = 0; mf < 2; mf++) {
                    mma_bf16(oacc[mf][dp * 2 + 0], ph[mf], &vh4[0]);
                    mma_bf16(oacc[mf][dp * 2 + 0], ph[mf], &vl4[0]);
                    mma_bf16(oacc[mf][dp * 2 + 0], pl[mf], &vh4[0]);
                    mma_bf16(oacc[mf][dp * 2 + 1], ph[mf], &vh4[2]);
                    mma_bf16(oacc[mf][dp * 2 + 1], ph[mf], &vl4[2]);
                    mma_bf16(oacc[mf][dp * 2 + 1], pl[mf], &vh4[2]);
                }
            }
        }
        __syncthreads();
        buf ^= 1;
    }
}

// stage 128x64 Q tile (scaled by 1/8) into the persistent Q smem region
__device__ __forceinline__ void stage_q(
    const __nv_bfloat16* __restrict__ Qh, const __nv_bfloat16* __restrict__ Ql,
    int rstride, int q0, char* smp, int t)
{
    char* qbase = smp + 2 * ABUF;
    const __nv_bfloat162 sc = __floats2bfloat162_rn(0.125f, 0.125f);
#pragma unroll
    for (int i = 0; i < 16; i++) {
        int f = t + i * 128;
        int row = f >> 4, c8 = f & 15;
        size_t go = (size_t)(q0 + row) * rstride + c8 * 4;
        uint32_t so = (uint32_t)(row * APITCH + c8 * 8);
        uint2 vh = *(const uint2*)&Qh[go];
        uint2 vl = *(const uint2*)&Ql[go];
        __nv_bfloat162* ph = (__nv_bfloat162*)&vh;
        __nv_bfloat162* pL = (__nv_bfloat162*)&vl;
        ph[0] = __hmul2(ph[0], sc); ph[1] = __hmul2(ph[1], sc);
        pL[0] = __hmul2(pL[0], sc); pL[1] = __hmul2(pL[1], sc);
        *(uint2*)(qbase + so) = vh;
        *(uint2*)(qbase + 18432 + so) = vl;
    }
    // visibility: first __syncthreads() inside the segment pipe orders these
    // stores before any warp's Q ldsm; Q region is never overwritten.
}

// fused self + cross attention: blocks [0,512) self, [512,640) cross; 128 threads
__global__ __launch_bounds__(128, 2) void attn_fused(
    const __nv_bfloat16* __restrict__ xp_h, const __nv_bfloat16* __restrict__ xp_l,
    const __nv_bfloat16* __restrict__ qq_h, const __nv_bfloat16* __restrict__ qq_l,
    const float* __restrict__ gate, float* __restrict__ park,
    __nv_bfloat16* __restrict__ xoh, __nv_bfloat16* __restrict__ xol,
    __nv_bfloat16* __restrict__ qoh, __nv_bfloat16* __restrict__ qol)
{
    extern __shared__ __align__(16) char smp[];
    const uint32_t sb = smem_u32(smp);
    const uint32_t sbQ = sb + 2 * ABUF;
    const int t = threadIdx.x, lane = t & 31, w = t >> 5;

    float oacc[2][8][4];
#pragma unroll
    for (int mf = 0; mf < 2; mf++)
#pragma unroll
        for (int dt = 0; dt < 8; dt++)
#pragma unroll
            for (int q = 0; q < 4; q++) oacc[mf][dt][q] = 0.f;
    float mm[2][2] = {{-1e30f, -1e30f}, {-1e30f, -1e30f}};
    float ll[2][2] = {{0.f, 0.f}, {0.f, 0.f}};

    if (blockIdx.x < 512) {
        // self attention; q|k|v at cols 0|1024|2048 of xp (stride 5120)
        const int bh = blockIdx.x & 31, b = bh >> 4, h = bh & 15;
        const int q0 = (blockIdx.x >> 5) * 128;
        const __nv_bfloat16* baseh = xp_h + (size_t)b * N_ * XPW + h * 64;
        const __nv_bfloat16* basel = xp_l + (size_t)b * N_ * XPW + h * 64;

        stage_q(baseh, basel, XPW, q0, smp, t);
        attn_segment_pipe(baseh + 1024, basel + 1024, baseh + 2048, basel + 2048,
                          XPW, N_, sb, sbQ, oacc, mm, ll, t, lane, w);

        int cbc = h * 64 + (lane & 3) * 2;
#pragma unroll
        for (int mf = 0; mf < 2; mf++) {
            float inv0 = 1.f / ll[mf][0], inv1 = 1.f / ll[mf][1];
            int r0 = q0 + w * 32 + mf * 16 + (lane >> 2);
#pragma unroll
            for (int dt = 0; dt < 8; dt++) {
                uint32_t h0, lo0, h1, lo1;
                split2(oacc[mf][dt][0] * inv0, oacc[mf][dt][1] * inv0, h0, lo0);
                split2(oacc[mf][dt][2] * inv1, oacc[mf][dt][3] * inv1, h1, lo1);
                size_t o0 = (size_t)(b * N_ + r0) * D_ + cbc + dt * 8;
                size_t o1 = (size_t)(b * N_ + r0 + 8) * D_ + cbc + dt * 8;
                *(uint32_t*)&xoh[o0] = h0; *(uint32_t*)&xol[o0] = lo0;
                *(uint32_t*)&xoh[o1] = h1; *(uint32_t*)&xol[o1] = lo1;
            }
        }
    } else {
        // cross attention; k2|v2 at cols 3072|4096 of xp (stride 5120)
        const int cid = blockIdx.x - 512;
        const int bh = cid & 31, b = bh >> 4, h = bh & 15;
        const int q0 = (cid >> 5) * 128;
        const __nv_bfloat16* qbh = qq_h + (size_t)b * QN_ * 3072 + h * 64;
        const __nv_bfloat16* qbl = qq_l + (size_t)b * QN_ * 3072 + h * 64;
        const __nv_bfloat16* kbh = xp_h + (size_t)b * N_ * XPW + 3072 + h * 64;
        const __nv_bfloat16* kbl = xp_l + (size_t)b * N_ * XPW + 3072 + h * 64;

        stage_q(qbh, qbl, 3072, q0, smp, t);

        // segment A: keys/values from x (gated)
        attn_segment_pipe(kbh, kbl, kbh + 1024, kbl + 1024,
                          XPW, N_, sb, sbQ, oacc, mm, ll, t, lane, w);

        const float g = tanhf(gate[h]);
        int cbc = h * 64 + (lane & 3) * 2;
#pragma unroll
        for (int mf = 0; mf < 2; mf++) {
            float gi0 = g / ll[mf][0], gi1 = g / ll[mf][1];
            int r0 = q0 + w * 32 + mf * 16 + (lane >> 2);
#pragma unroll
            for (int dt = 0; dt < 8; dt++) {
                *(float2*)&park[(size_t)(b * QN_ + r0) * D_ + cbc + dt * 8] =
                    make_float2(oacc[mf][dt][0] * gi0, oacc[mf][dt][1] * gi0);
                *(float2*)&park[(size_t)(b * QN_ + r0 + 8) * D_ + cbc + dt * 8] =
                    make_float2(oacc[mf][dt][2] * gi1, oacc[mf][dt][3] * gi1);
                oacc[mf][dt][0] = oacc[mf][dt][1] = oacc[mf][dt][2] = oacc[mf][dt][3] = 0.f;
            }
            mm[mf][0] = -1e30f; mm[mf][1] = -1e30f;
            ll[mf][0] = 0.f; ll[mf][1] = 0.f;
        }

        // segment B: keys/values from query stream
        attn_segment_pipe(qbh + 1024, qbl + 1024, qbh + 2048, qbl + 2048,
                          3072, QN_, sb, sbQ, oacc, mm, ll, t, lane, w);

#pragma unroll
        for (int mf = 0; mf < 2; mf++) {
            float inv0 = 1.f / ll[mf][0], inv1 = 1.f / ll[mf][1];
            int r0 = q0 + w * 32 + mf * 16 + (lane >> 2);
#pragma unroll
            for (int dt = 0; dt < 8; dt++) {
                size_t o0 = (size_t)(b * QN_ + r0) * D_ + cbc + dt * 8;
                size_t o1 = (size_t)(b * QN_ + r0 + 8) * D_ + cbc + dt * 8;
                float2 p0 = *(float2*)&park[o0];
                float2 p1 = *(float2*)&park[o1];
                uint32_t h0, lo0, h1, lo1;
                split2(p0.x + oacc[mf][dt][0] * inv0, p0.y + oacc[mf][dt][1] * inv0, h0, lo0);
                split2(p1.x + oacc[mf][dt][2] * inv1, p1.y + oacc[mf][dt][3] * inv1, h1, lo1);
                *(uint32_t*)&qoh[o0] = h0; *(uint32_t*)&qol[o0] = lo0;
                *(uint32_t*)&qoh[o1] = h1; *(uint32_t*)&qol[o1] = lo1;
            }
        }
    }
}

// ======================= low_res scramble + 64x64 proj =======================
__global__ void lr_kernel(const float* __restrict__ low_res,
                          const float* __restrict__ W,
                          const float* __restrict__ bias,
                          float* __restrict__ out)
{
    __shared__ float xin[64];
    const int row = blockIdx.x;
    const int b = row >> 8;
    const int i = row & 255;
    const int t = threadIdx.x;
    {
        int f = i * 64 + t;
        xin[t] = low_res[(size_t)b * (LN_ * LD_) + (f & 255) * 64 + (f >> 8)];
    }
    __syncthreads();
    float s = bias[t];
#pragma unroll 8
    for (int c = 0; c < 64; c++)
        s = fmaf(xin[c], W[c * 64 + t], s);
    out[(size_t)row * 64 + t] = s;
}

// ======================= launch =======================
extern "C" void kernel_launch(void* const* d_in, const int* in_sizes, int n_in,
                              void* d_out, int out_size)
{
    const float* x        = (const float*)d_in[0];
    const float* query    = (const float*)d_in[1];
    const float* low_res  = (const float*)d_in[2];
    const float* W_qkv    = (const float*)d_in[3];
    const float* W_xkv    = (const float*)d_in[4];
    const float* W_qlin   = (const float*)d_in[5];
    const float* gate     = (const float*)d_in[6];
    const float* W_proj   = (const float*)d_in[7];
    const float* b_proj   = (const float*)d_in[8];
    const float* W_qproj  = (const float*)d_in[9];
    const float* b_qproj  = (const float*)d_in[10];
    const float* W_lrproj = (const float*)d_in[11];
    const float* b_lrproj = (const float*)d_in[12];

    __nv_bfloat16 *wh, *wl, *xph, *xpl, *qqh, *qql;
    __nv_bfloat16 *xh, *xl, *qh, *ql, *xah, *xal, *qah, *qal;
    float* park;
    cudaGetSymbolAddress((void**)&wh,  g_wt_hi);
    cudaGetSymbolAddress((void**)&wl,  g_wt_lo);
    cudaGetSymbolAddress((void**)&xph, g_xp_h);
    cudaGetSymbolAddress((void**)&xpl, g_xp_l);
    cudaGetSymbolAddress((void**)&qqh, g_qqkv_h);
    cudaGetSymbolAddress((void**)&qql, g_qqkv_l);
    cudaGetSymbolAddress((void**)&xh,  g_x_h);
    cudaGetSymbolAddress((void**)&xl,  g_x_l);
    cudaGetSymbolAddress((void**)&qh,  g_q_h);
    cudaGetSymbolAddress((void**)&ql,  g_q_l);
    cudaGetSymbolAddress((void**)&xah, g_xat_h);
    cudaGetSymbolAddress((void**)&xal, g_xat_l);
    cudaGetSymbolAddress((void**)&qah, g_qat_h);
    cudaGetSymbolAddress((void**)&qal, g_qat_l);
    cudaGetSymbolAddress((void**)&park, g_park);

    float* out   = (float*)d_out;
    float* x_out = out;
    float* q_out = out + (size_t)B_ * N_ * D_;
    float* l_out = q_out + (size_t)B_ * QN_ * D_;

    cudaFuncSetAttribute(gemm_in_fused,  cudaFuncAttributeMaxDynamicSharedMemorySize, GSMEM);
    cudaFuncSetAttribute(gemm_out_fused, cudaFuncAttributeMaxDynamicSharedMemorySize, GSMEM);
    cudaFuncSetAttribute(attn_fused,     cudaFuncAttributeMaxDynamicSharedMemorySize, ASMEM);

    wsplit_all<<<dim3(320, 32), 256>>>(W_qkv, W_xkv, W_qlin, W_proj, W_qproj, wh, wl);
    asplit_all<<<5120, 256>>>(x, query, xh, xl, qh, ql);

    gemm_in_fused<<<1472, 128, GSMEM>>>(xh, xl, qh, ql, wh, wl, xph, xpl, qqh, qql);

    attn_fused<<<640, 128, ASMEM>>>(xph, xpl, qqh, qql, gate, park, xah, xal, qah, qal);

    gemm_out_fused<<<320, 128, GSMEM>>>(xah, xal, qah, qal, wh, wl,
                                        b_proj, b_qproj, x_out, q_out);

    lr_kernel<<<B_ * LN_, 64>>>(low_res, W_lrproj, b_lrproj, l_out);
}